// round 1
// baseline (speedup 1.0000x reference)
#include <cuda_runtime.h>
#include <math.h>

#define NS   1024
#define NM   128
#define ND   1024
#define NH   16
#define NHD  64
#define NF   2048
#define NL   8
#define NCAT 1280   /* S + 2M */
#define NKV  1152   /* M + S  */
#define NPOS 1280

/* ------------------------------------------------------------------ */
/* scratch (static device arrays; no allocation allowed)              */
/* ------------------------------------------------------------------ */
__device__ float g_cat[NCAT*ND];
__device__ float g_x  [NCAT*ND];
__device__ float g_q  [NS*ND];
__device__ float g_k  [NKV*ND];
__device__ float g_v  [NKV*ND];
__device__ float g_qbf[2*NM*ND];
__device__ float g_kbf[2*NM*ND];
__device__ float g_vbf[2*NM*ND];
__device__ float g_att[NCAT*ND];
__device__ float g_m1 [NCAT*NF];
__device__ float g_m2 [NCAT*NF];
__device__ float g_inj[NL*NM*ND];
__device__ float g_fg [NL*NM*ND];
__device__ float g_cs [NPOS*32];
__device__ float g_sn [NPOS*32];

/* ------------------------------------------------------------------ */
/* RoPE tables (double precision, matches numpy float64 -> float32)   */
/* ------------------------------------------------------------------ */
__global__ void init_tables_kernel() {
    int idx = blockIdx.x*blockDim.x + threadIdx.x;
    if (idx >= NPOS*32) return;
    int pos = idx >> 5, j = idx & 31;
    double inv = exp(-((double)(2*j)/64.0) * log(10000.0));
    double a = (double)pos * inv;
    g_cs[idx] = (float)cos(a);
    g_sn[idx] = (float)sin(a);
}

/* ------------------------------------------------------------------ */
/* embedding gather: out row r = embed[ids[r]]                        */
/* ------------------------------------------------------------------ */
__global__ void gather_kernel(const int* __restrict__ ids,
                              const float* __restrict__ embed,
                              float* __restrict__ out) {
    int row = blockIdx.x;
    int id  = ids[row];
    const float4* src = (const float4*)(embed + (size_t)id*ND);
    float4* dst = (float4*)(out + (size_t)row*ND);
    dst[threadIdx.x] = src[threadIdx.x];   /* 256 threads * float4 = 1024 */
}

/* ------------------------------------------------------------------ */
/* RMSNorm: y = x * w * rsqrt(mean(x^2)+eps), row per block           */
/* ------------------------------------------------------------------ */
__global__ void rmsnorm_kernel(const float* __restrict__ x,
                               const float* __restrict__ w,
                               float* __restrict__ y) {
    int row = blockIdx.x, t = threadIdx.x;
    const float* xr = x + (size_t)row*ND;
    float s = 0.f;
    #pragma unroll
    for (int i = t; i < ND; i += 256) { float v = xr[i]; s += v*v; }
    __shared__ float red[256];
    red[t] = s; __syncthreads();
    for (int st = 128; st > 0; st >>= 1) {
        if (t < st) red[t] += red[t+st];
        __syncthreads();
    }
    float r = rsqrtf(red[0]*(1.f/ND) + 1e-5f);
    float* yr = y + (size_t)row*ND;
    #pragma unroll
    for (int i = t; i < ND; i += 256) yr[i] = xr[i]*w[i]*r;
}

/* ------------------------------------------------------------------ */
/* in-place RoPE on [rows, 1024], pos = pos0 + row                    */
/* ------------------------------------------------------------------ */
__global__ void rope_kernel(float* __restrict__ X, int rows, int pos0) {
    int idx = blockIdx.x*blockDim.x + threadIdx.x;
    if (idx >= rows*512) return;
    int j = idx & 31;
    int h = (idx >> 5) & 15;
    int r = idx >> 9;
    int pos = pos0 + r;
    float c = g_cs[pos*32 + j], s = g_sn[pos*32 + j];
    float* p = X + (size_t)r*ND + h*64;
    float x1 = p[j], x2 = p[j+32];
    p[j]    = x1*c - x2*s;
    p[j+32] = x2*c + x1*s;
}

/* ------------------------------------------------------------------ */
/* SGEMM 128x128x8, 256 threads, 8x8 per thread. All dims mult. of    */
/* 128 (M,N) and 8 (K) in this model -> no bounds checks.             */
/* ------------------------------------------------------------------ */
struct GemmDesc  { const float* A; const float* B; float* C; };
struct GemmBatch { GemmDesc d[8]; };

__device__ __forceinline__ void gemm_core(const float* __restrict__ A,
                                          const float* __restrict__ B,
                                          float* __restrict__ C,
                                          int N, int K, int beta) {
    __shared__ float As[8][128];
    __shared__ float Bs[8][128];
    int tid = threadIdx.x;
    int ty = tid >> 4, tx = tid & 15;
    size_t brow = (size_t)blockIdx.y * 128;
    size_t bcol = (size_t)blockIdx.x * 128;
    int arow = tid >> 1;
    int acol = (tid & 1) << 2;
    int brl  = tid >> 5;
    int bcl  = (tid & 31) << 2;
    const float* Ap = A + (brow + arow)*K + acol;
    const float* Bp = B + (size_t)brl*N + bcol + bcl;
    float acc[8][8];
    #pragma unroll
    for (int i = 0; i < 8; i++)
        #pragma unroll
        for (int j = 0; j < 8; j++) acc[i][j] = 0.f;

    for (int k0 = 0; k0 < K; k0 += 8) {
        float4 av = *(const float4*)(Ap + k0);
        As[acol+0][arow] = av.x; As[acol+1][arow] = av.y;
        As[acol+2][arow] = av.z; As[acol+3][arow] = av.w;
        *(float4*)&Bs[brl][bcl] = *(const float4*)(Bp + (size_t)k0*N);
        __syncthreads();
        #pragma unroll
        for (int kk = 0; kk < 8; kk++) {
            float a[8], b[8];
            *(float4*)&a[0] = *(float4*)&As[kk][ty*8];
            *(float4*)&a[4] = *(float4*)&As[kk][ty*8+4];
            *(float4*)&b[0] = *(float4*)&Bs[kk][tx*8];
            *(float4*)&b[4] = *(float4*)&Bs[kk][tx*8+4];
            #pragma unroll
            for (int i = 0; i < 8; i++)
                #pragma unroll
                for (int j = 0; j < 8; j++)
                    acc[i][j] += a[i]*b[j];
        }
        __syncthreads();
    }
    #pragma unroll
    for (int i = 0; i < 8; i++) {
        size_t r = brow + ty*8 + i;
        float* cp = C + r*N + bcol + tx*8;
        #pragma unroll
        for (int j = 0; j < 8; j += 4) {
            float4 cv;
            if (beta) {
                cv = *(float4*)(cp + j);
                cv.x += acc[i][j];   cv.y += acc[i][j+1];
                cv.z += acc[i][j+2]; cv.w += acc[i][j+3];
            } else {
                cv.x = acc[i][j];   cv.y = acc[i][j+1];
                cv.z = acc[i][j+2]; cv.w = acc[i][j+3];
            }
            *(float4*)(cp + j) = cv;
        }
    }
}

__global__ __launch_bounds__(256)
void sgemm_kernel(const float* A, const float* B, float* C, int N, int K, int beta) {
    gemm_core(A, B, C, N, K, beta);
}
__global__ __launch_bounds__(256)
void sgemm_batch_kernel(GemmBatch bat, int N, int K, int beta) {
    GemmDesc dsc = bat.d[blockIdx.z];
    gemm_core(dsc.A, dsc.B, dsc.C, N, K, beta);
}

/* ------------------------------------------------------------------ */
/* Flash-style fp32 attention.                                        */
/* Mask: key kk visible iff kk <= q + coff (coff=128 hidden, 1152 BF) */
/* Keys = [K1 (n1 rows); K2 (n2 rows)]; blockIdx.z strides Q/K2/O.    */
/* ------------------------------------------------------------------ */
__global__ __launch_bounds__(64)
void attn_kernel(const float* Q, size_t qz,
                 const float* K1, const float* V1, int n1,
                 const float* K2, const float* V2, size_t kz, int n2,
                 float* O, size_t oz, int coff) {
    int z = blockIdx.z;
    Q  += (size_t)z*qz;  K2 += (size_t)z*kz;
    V2 += (size_t)z*kz;  O  += (size_t)z*oz;
    int h  = blockIdx.y;
    int q0 = blockIdx.x*64;
    int tq = threadIdx.x;
    int q  = q0 + tq;

    __shared__ float Ks[64][64];
    __shared__ float Vs[64][64];

    float qv[64];
    {
        const float4* qp = (const float4*)(Q + (size_t)q*ND + h*64);
        #pragma unroll
        for (int i = 0; i < 16; i++) {
            float4 t = qp[i];
            qv[4*i] = t.x; qv[4*i+1] = t.y; qv[4*i+2] = t.z; qv[4*i+3] = t.w;
        }
    }
    float m = -1e30f, l = 0.f;
    float acc[64];
    #pragma unroll
    for (int i = 0; i < 64; i++) acc[i] = 0.f;

    int ntot = n1 + n2;
    int kmax = ntot;
    int vis  = q0 + 63 + coff + 1;
    if (vis < kmax) kmax = vis;

    for (int t0 = 0; t0 < kmax; t0 += 64) {
        int cnt = ntot - t0; if (cnt > 64) cnt = 64;
        if (tq < cnt) {
            int kk = t0 + tq;
            const float *kp, *vp;
            if (kk < n1) { kp = K1 + (size_t)kk*ND;      vp = V1 + (size_t)kk*ND; }
            else         { kp = K2 + (size_t)(kk-n1)*ND; vp = V2 + (size_t)(kk-n1)*ND; }
            kp += h*64; vp += h*64;
            #pragma unroll
            for (int i = 0; i < 16; i++) {
                ((float4*)Ks[tq])[i] = ((const float4*)kp)[i];
                ((float4*)Vs[tq])[i] = ((const float4*)vp)[i];
            }
        }
        __syncthreads();
        int jend = q + coff - t0 + 1;
        if (jend > cnt) jend = cnt;
        for (int j = 0; j < jend; j++) {
            float s = 0.f;
            #pragma unroll
            for (int d = 0; d < 64; d++) s += qv[d]*Ks[j][d];
            s *= 0.125f;                       /* 1/sqrt(64) */
            float mn   = fmaxf(m, s);
            float corr = expf(m - mn);
            float p    = expf(s - mn);
            l = l*corr + p;
            #pragma unroll
            for (int d = 0; d < 64; d++) acc[d] = acc[d]*corr + p*Vs[j][d];
            m = mn;
        }
        __syncthreads();
    }
    float invl = 1.f/l;
    float* op = O + (size_t)q*ND + h*64;
    #pragma unroll
    for (int d = 0; d < 64; d++) op[d] = acc[d]*invl;
}

/* ------------------------------------------------------------------ */
/* elementwise: m1 = silu(m1) * m2                                    */
/* ------------------------------------------------------------------ */
__global__ void silumul_kernel(float* __restrict__ a, const float* __restrict__ b, int n) {
    int i = blockIdx.x*blockDim.x + threadIdx.x;
    if (i >= n) return;
    float g = a[i];
    a[i] = (g / (1.f + expf(-g))) * b[i];
}

/* ------------------------------------------------------------------ */
/* final gate: out = mem*sig(fg) + inj*(1-sig(fg))                    */
/* ------------------------------------------------------------------ */
__global__ void gate_out_kernel(const float* __restrict__ mem,
                                const float* __restrict__ inj,
                                const float* __restrict__ fg,
                                float* __restrict__ out, int n) {
    int i = blockIdx.x*blockDim.x + threadIdx.x;
    if (i >= n) return;
    float g = 1.f / (1.f + expf(-fg[i]));
    out[i] = mem[i]*g + inj[i]*(1.f - g);
}

/* ================================================================== */
extern "C" void kernel_launch(void* const* d_in, const int* in_sizes, int n_in,
                              void* d_out, int out_size) {
    const int*   ids    = (const int*)d_in[0];
    const float* memory = (const float*)d_in[1];
    const float* beacon = (const float*)d_in[2];
    const float* forget = (const float*)d_in[3];
    const float* embed  = (const float*)d_in[4];
    const float* ln1    = (const float*)d_in[5];
    const float* ln2    = (const float*)d_in[6];
    const float* Wq  = (const float*)d_in[7];
    const float* Wk  = (const float*)d_in[8];
    const float* Wv  = (const float*)d_in[9];
    const float* Wo  = (const float*)d_in[10];
    const float* mWk = (const float*)d_in[11];
    const float* mWv = (const float*)d_in[12];
    const float* bWq = (const float*)d_in[13];
    const float* bWk = (const float*)d_in[14];
    const float* bWv = (const float*)d_in[15];
    const float* fWq = (const float*)d_in[16];
    const float* fWk = (const float*)d_in[17];
    const float* fWv = (const float*)d_in[18];
    const float* Wg  = (const float*)d_in[19];
    const float* Wu  = (const float*)d_in[20];
    const float* Wd  = (const float*)d_in[21];

    float *cat,*x,*q,*k,*v,*qbf,*kbf,*vbf,*att,*m1,*m2,*inj,*fg;
    cudaGetSymbolAddress((void**)&cat, g_cat);
    cudaGetSymbolAddress((void**)&x,   g_x);
    cudaGetSymbolAddress((void**)&q,   g_q);
    cudaGetSymbolAddress((void**)&k,   g_k);
    cudaGetSymbolAddress((void**)&v,   g_v);
    cudaGetSymbolAddress((void**)&qbf, g_qbf);
    cudaGetSymbolAddress((void**)&kbf, g_kbf);
    cudaGetSymbolAddress((void**)&vbf, g_vbf);
    cudaGetSymbolAddress((void**)&att, g_att);
    cudaGetSymbolAddress((void**)&m1,  g_m1);
    cudaGetSymbolAddress((void**)&m2,  g_m2);
    cudaGetSymbolAddress((void**)&inj, g_inj);
    cudaGetSymbolAddress((void**)&fg,  g_fg);

    const size_t RECB = (size_t)NM*ND*sizeof(float);

    init_tables_kernel<<<(NPOS*32+255)/256, 256>>>();
    gather_kernel<<<NS, 256>>>(ids, embed, cat);
    cudaMemcpyAsync(cat + (size_t)NS*ND,      beacon, RECB, cudaMemcpyDeviceToDevice, 0);
    cudaMemcpyAsync(cat + (size_t)(NS+NM)*ND, forget, RECB, cudaMemcpyDeviceToDevice, 0);

    /* layers 0..6 (layer 7's outputs are never consumed: rec is taken at
       layer entry and the final scan carry is discarded).              */
    for (int l = 0; l < 7; l++) {
        const size_t wdd = (size_t)ND*ND;
        const float* Wq_l  = Wq  + l*wdd;  const float* Wk_l  = Wk  + l*wdd;
        const float* Wv_l  = Wv  + l*wdd;  const float* Wo_l  = Wo  + l*wdd;
        const float* mWk_l = mWk + l*wdd;  const float* mWv_l = mWv + l*wdd;
        const float* bWq_l = bWq + l*wdd;  const float* bWk_l = bWk + l*wdd;
        const float* bWv_l = bWv + l*wdd;  const float* fWq_l = fWq + l*wdd;
        const float* fWk_l = fWk + l*wdd;  const float* fWv_l = fWv + l*wdd;
        const float* Wg_l  = Wg + (size_t)l*ND*NF;
        const float* Wu_l  = Wu + (size_t)l*ND*NF;
        const float* Wd_l  = Wd + (size_t)l*NF*ND;
        const float* mem_l = memory + (size_t)l*NM*ND;
        const bool last = (l == 6);

        /* record beacon/forget at layer entry */
        cudaMemcpyAsync(inj + (size_t)l*NM*ND, cat + (size_t)NS*ND,      RECB, cudaMemcpyDeviceToDevice, 0);
        cudaMemcpyAsync(fg  + (size_t)l*NM*ND, cat + (size_t)(NS+NM)*ND, RECB, cudaMemcpyDeviceToDevice, 0);

        rmsnorm_kernel<<<NCAT, 256>>>(cat, ln1 + (size_t)l*ND, x);

        /* big projections on hidden rows (skip Wq in last layer: oh unused) */
        {
            GemmBatch ba; int nb = 0;
            if (!last) { ba.d[nb].A = x; ba.d[nb].B = Wq_l; ba.d[nb].C = q; nb++; }
            ba.d[nb].A = x; ba.d[nb].B = Wk_l; ba.d[nb].C = k + (size_t)NM*ND; nb++;
            ba.d[nb].A = x; ba.d[nb].B = Wv_l; ba.d[nb].C = v + (size_t)NM*ND; nb++;
            sgemm_batch_kernel<<<dim3(8, 8, nb), 256>>>(ba, ND, ND, 0);
        }
        /* 8 small 128-row projections in one batched launch */
        {
            GemmBatch sa;
            const float* bx = x + (size_t)NS*ND;
            const float* fx = x + (size_t)(NS+NM)*ND;
            sa.d[0].A = mem_l; sa.d[0].B = mWk_l; sa.d[0].C = k;
            sa.d[1].A = mem_l; sa.d[1].B = mWv_l; sa.d[1].C = v;
            sa.d[2].A = bx;    sa.d[2].B = bWq_l; sa.d[2].C = qbf;
            sa.d[3].A = bx;    sa.d[3].B = bWk_l; sa.d[3].C = kbf;
            sa.d[4].A = bx;    sa.d[4].B = bWv_l; sa.d[4].C = vbf;
            sa.d[5].A = fx;    sa.d[5].B = fWq_l; sa.d[5].C = qbf + (size_t)NM*ND;
            sa.d[6].A = fx;    sa.d[6].B = fWk_l; sa.d[6].C = kbf + (size_t)NM*ND;
            sa.d[7].A = fx;    sa.d[7].B = fWv_l; sa.d[7].C = vbf + (size_t)NM*ND;
            sgemm_batch_kernel<<<dim3(8, 1, 8), 256>>>(sa, ND, ND, 0);
        }

        /* RoPE: mem keys pos 0..127, hidden pos 128..1151, gates pos 1152..1279 */
        if (!last) rope_kernel<<<NS*2, 256>>>(q, NS, NM);
        rope_kernel<<<NKV*2, 256>>>(k, NKV, 0);
        rope_kernel<<<NM*2, 256>>>(qbf,                 NM, NKV);
        rope_kernel<<<NM*2, 256>>>(qbf + (size_t)NM*ND, NM, NKV);
        rope_kernel<<<NM*2, 256>>>(kbf,                 NM, NKV);
        rope_kernel<<<NM*2, 256>>>(kbf + (size_t)NM*ND, NM, NKV);

        /* attention */
        if (!last)
            attn_kernel<<<dim3(NS/64, NH, 1), 64>>>(q, 0, k, v, NKV,
                                                    k, v, 0, 0,
                                                    att, 0, NM);
        attn_kernel<<<dim3(NM/64, NH, 2), 64>>>(qbf, (size_t)NM*ND, k, v, NKV,
                                                kbf, vbf, (size_t)NM*ND, NM,
                                                att + (size_t)NS*ND, (size_t)NM*ND, NKV);

        /* Wo with residual accumulate */
        if (!last)
            sgemm_kernel<<<dim3(8, 10), 256>>>(att, Wo_l, cat, ND, ND, 1);
        else
            sgemm_kernel<<<dim3(8, 2), 256>>>(att + (size_t)NS*ND, Wo_l,
                                              cat + (size_t)NS*ND, ND, ND, 1);

        /* ln2 + MLP (last layer: only the 256 beacon/forget rows matter) */
        int rows = last ? 2*NM : NCAT;
        size_t off = last ? (size_t)NS*ND : 0;
        rmsnorm_kernel<<<rows, 256>>>(cat + off, ln2 + (size_t)l*ND, x + off);
        {
            GemmBatch ga;
            ga.d[0].A = x + off; ga.d[0].B = Wg_l; ga.d[0].C = m1;
            ga.d[1].A = x + off; ga.d[1].B = Wu_l; ga.d[1].C = m2;
            sgemm_batch_kernel<<<dim3(NF/128, rows/128, 2), 256>>>(ga, NF, ND, 0);
        }
        silumul_kernel<<<(rows*NF)/256, 256>>>(m1, m2, rows*NF);
        sgemm_kernel<<<dim3(8, rows/128), 256>>>(m1, Wd_l, cat + off, ND, NF, 1);
    }

    /* layer-7 entry record = layer-6 output */
    cudaMemcpyAsync(inj + (size_t)7*NM*ND, cat + (size_t)NS*ND,      RECB, cudaMemcpyDeviceToDevice, 0);
    cudaMemcpyAsync(fg  + (size_t)7*NM*ND, cat + (size_t)(NS+NM)*ND, RECB, cudaMemcpyDeviceToDevice, 0);

    gate_out_kernel<<<(NL*NM*ND)/256, 256>>>(memory, inj, fg, (float*)d_out, NL*NM*ND);
}

// round 2
// speedup vs baseline: 1.2553x; 1.2553x over previous
#include <cuda_runtime.h>
#include <math.h>
#include <mma.h>

using namespace nvcuda;

#define NS   1024
#define NM   128
#define ND   1024
#define NH   16
#define NHD  64
#define NF   2048
#define NL   8
#define NCAT 1280   /* S + 2M */
#define NKV  1152   /* M + S  */
#define NPOS 1280

/* ------------------------------------------------------------------ */
/* scratch (static device arrays; no allocation allowed)              */
/* ------------------------------------------------------------------ */
__device__ float g_cat[NCAT*ND];
__device__ float g_x  [NCAT*ND];
__device__ float g_q  [NS*ND];
__device__ float g_k  [NKV*ND];
__device__ float g_v  [NKV*ND];
__device__ float g_qbf[2*NM*ND];
__device__ float g_kbf[2*NM*ND];
__device__ float g_vbf[2*NM*ND];
__device__ float g_att[NCAT*ND];
__device__ float g_m1 [NCAT*NF];
__device__ float g_m2 [NCAT*NF];
__device__ float g_inj[NL*NM*ND];
__device__ float g_fg [NL*NM*ND];
__device__ float g_cs [NPOS*32];
__device__ float g_sn [NPOS*32];

/* ------------------------------------------------------------------ */
/* RoPE tables (double precision, matches numpy float64 -> float32)   */
/* ------------------------------------------------------------------ */
__global__ void init_tables_kernel() {
    int idx = blockIdx.x*blockDim.x + threadIdx.x;
    if (idx >= NPOS*32) return;
    int pos = idx >> 5, j = idx & 31;
    double inv = exp(-((double)(2*j)/64.0) * log(10000.0));
    double a = (double)pos * inv;
    g_cs[idx] = (float)cos(a);
    g_sn[idx] = (float)sin(a);
}

/* ------------------------------------------------------------------ */
/* embedding gather                                                   */
/* ------------------------------------------------------------------ */
__global__ void gather_kernel(const int* __restrict__ ids,
                              const float* __restrict__ embed,
                              float* __restrict__ out) {
    int row = blockIdx.x;
    int id  = ids[row];
    const float4* src = (const float4*)(embed + (size_t)id*ND);
    float4* dst = (float4*)(out + (size_t)row*ND);
    dst[threadIdx.x] = src[threadIdx.x];
}

/* ------------------------------------------------------------------ */
/* RMSNorm                                                            */
/* ------------------------------------------------------------------ */
__global__ void rmsnorm_kernel(const float* __restrict__ x,
                               const float* __restrict__ w,
                               float* __restrict__ y) {
    int row = blockIdx.x, t = threadIdx.x;
    const float* xr = x + (size_t)row*ND;
    float s = 0.f;
    #pragma unroll
    for (int i = t; i < ND; i += 256) { float v = xr[i]; s += v*v; }
    __shared__ float red[256];
    red[t] = s; __syncthreads();
    for (int st = 128; st > 0; st >>= 1) {
        if (t < st) red[t] += red[t+st];
        __syncthreads();
    }
    float r = rsqrtf(red[0]*(1.f/ND) + 1e-5f);
    float* yr = y + (size_t)row*ND;
    #pragma unroll
    for (int i = t; i < ND; i += 256) yr[i] = xr[i]*w[i]*r;
}

/* ------------------------------------------------------------------ */
/* in-place RoPE on [rows, 1024], pos = pos0 + row                    */
/* ------------------------------------------------------------------ */
__global__ void rope_kernel(float* __restrict__ X, int rows, int pos0) {
    int idx = blockIdx.x*blockDim.x + threadIdx.x;
    if (idx >= rows*512) return;
    int j = idx & 31;
    int h = (idx >> 5) & 15;
    int r = idx >> 9;
    int pos = pos0 + r;
    float c = g_cs[pos*32 + j], s = g_sn[pos*32 + j];
    float* p = X + (size_t)r*ND + h*64;
    float x1 = p[j], x2 = p[j+32];
    p[j]    = x1*c - x2*s;
    p[j+32] = x2*c + x1*s;
}

/* ------------------------------------------------------------------ */
/* tf32 WMMA GEMM: 128x128 block tile, 8 warps (32x64 each),          */
/* K-tile 16, double buffered. M,N mult of 128; K mult of 16.         */
/* ------------------------------------------------------------------ */
struct GemmDesc  { const float* A; const float* B; float* C; };
struct GemmBatch { GemmDesc d[8]; };

typedef wmma::fragment<wmma::matrix_a, 16,16,8, wmma::precision::tf32, wmma::row_major> FragA;
typedef wmma::fragment<wmma::matrix_b, 16,16,8, wmma::precision::tf32, wmma::row_major> FragB;
typedef wmma::fragment<wmma::accumulator, 16,16,8, float> FragC;

__device__ __forceinline__ void gemm_core(const float* __restrict__ A,
                                          const float* __restrict__ B,
                                          float* __restrict__ C,
                                          int N, int K, int beta) {
    __shared__ float As[2][128][17];   /* odd stride: conflict-free frag loads */
    __shared__ float Bs[2][16][132];

    int tid = threadIdx.x;
    int wid = tid >> 5;
    int wm  = wid & 3;          /* warp M 0..3  -> 32-row strip  */
    int wn  = wid >> 2;         /* warp N 0..1  -> 64-col strip  */
    size_t brow = (size_t)blockIdx.y * 128;
    size_t bcol = (size_t)blockIdx.x * 128;

    const float* Abase = A + brow * K;
    const float* Bbase = B + bcol;

    /* A tile load map: idx -> (m = idx/4, kq = (idx%4)*4)   128x16  */
    /* B tile load map: idx -> (kr = idx/32, nq = (idx%32)*4) 16x128 */
    int am[2], ak[2], bk[2], bn[2];
    #pragma unroll
    for (int i = 0; i < 2; i++) {
        int idx = tid + 256*i;
        am[i] = idx >> 2;  ak[i] = (idx & 3) << 2;
        bk[i] = idx >> 5;  bn[i] = (idx & 31) << 2;
    }

    FragC acc[2][4];
    #pragma unroll
    for (int mi = 0; mi < 2; mi++)
        #pragma unroll
        for (int ni = 0; ni < 4; ni++)
            wmma::fill_fragment(acc[mi][ni], 0.f);

    int nt = K >> 4;
    float4 av[2], bv[2];

    /* prologue: tile 0 */
    #pragma unroll
    for (int i = 0; i < 2; i++) {
        av[i] = *(const float4*)(Abase + (size_t)am[i]*K + ak[i]);
        bv[i] = *(const float4*)(Bbase + (size_t)bk[i]*N);
        bv[i] = *(const float4*)(Bbase + (size_t)bk[i]*N + bn[i]);
    }
    #pragma unroll
    for (int i = 0; i < 2; i++) {
        As[0][am[i]][ak[i]+0] = av[i].x; As[0][am[i]][ak[i]+1] = av[i].y;
        As[0][am[i]][ak[i]+2] = av[i].z; As[0][am[i]][ak[i]+3] = av[i].w;
        *(float4*)&Bs[0][bk[i]][bn[i]] = bv[i];
    }
    __syncthreads();

    for (int kt = 0; kt < nt; kt++) {
        int cur = kt & 1;
        if (kt + 1 < nt) {
            int k0 = (kt + 1) << 4;
            #pragma unroll
            for (int i = 0; i < 2; i++) {
                av[i] = *(const float4*)(Abase + (size_t)am[i]*K + k0 + ak[i]);
                bv[i] = *(const float4*)(Bbase + (size_t)(k0 + bk[i])*N + bn[i]);
            }
        }
        #pragma unroll
        for (int kk = 0; kk < 16; kk += 8) {
            FragA af[2];
            FragB bf[4];
            #pragma unroll
            for (int mi = 0; mi < 2; mi++) {
                wmma::load_matrix_sync(af[mi], &As[cur][wm*32 + mi*16][kk], 17);
                #pragma unroll
                for (int t = 0; t < af[mi].num_elements; t++)
                    af[mi].x[t] = wmma::__float_to_tf32(af[mi].x[t]);
            }
            #pragma unroll
            for (int ni = 0; ni < 4; ni++) {
                wmma::load_matrix_sync(bf[ni], &Bs[cur][kk][wn*64 + ni*16], 132);
                #pragma unroll
                for (int t = 0; t < bf[ni].num_elements; t++)
                    bf[ni].x[t] = wmma::__float_to_tf32(bf[ni].x[t]);
            }
            #pragma unroll
            for (int mi = 0; mi < 2; mi++)
                #pragma unroll
                for (int ni = 0; ni < 4; ni++)
                    wmma::mma_sync(acc[mi][ni], af[mi], bf[ni], acc[mi][ni]);
        }
        if (kt + 1 < nt) {
            int nxt = (kt + 1) & 1;
            #pragma unroll
            for (int i = 0; i < 2; i++) {
                As[nxt][am[i]][ak[i]+0] = av[i].x; As[nxt][am[i]][ak[i]+1] = av[i].y;
                As[nxt][am[i]][ak[i]+2] = av[i].z; As[nxt][am[i]][ak[i]+3] = av[i].w;
                *(float4*)&Bs[nxt][bk[i]][bn[i]] = bv[i];
            }
        }
        __syncthreads();
    }

    #pragma unroll
    for (int mi = 0; mi < 2; mi++)
        #pragma unroll
        for (int ni = 0; ni < 4; ni++) {
            float* cp = C + (brow + wm*32 + mi*16)*N + bcol + wn*64 + ni*16;
            if (beta) {
                FragC cf;
                wmma::load_matrix_sync(cf, cp, N, wmma::mem_row_major);
                #pragma unroll
                for (int t = 0; t < cf.num_elements; t++)
                    acc[mi][ni].x[t] += cf.x[t];
            }
            wmma::store_matrix_sync(cp, acc[mi][ni], N, wmma::mem_row_major);
        }
}

__global__ __launch_bounds__(256)
void sgemm_kernel(const float* A, const float* B, float* C, int N, int K, int beta) {
    gemm_core(A, B, C, N, K, beta);
}
__global__ __launch_bounds__(256)
void sgemm_batch_kernel(GemmBatch bat, int N, int K, int beta) {
    GemmDesc dsc = bat.d[blockIdx.z];
    gemm_core(dsc.A, dsc.B, dsc.C, N, K, beta);
}

/* ------------------------------------------------------------------ */
/* Flash-style fp32 attention (unchanged this round)                  */
/* ------------------------------------------------------------------ */
__global__ __launch_bounds__(64)
void attn_kernel(const float* Q, size_t qz,
                 const float* K1, const float* V1, int n1,
                 const float* K2, const float* V2, size_t kz, int n2,
                 float* O, size_t oz, int coff) {
    int z = blockIdx.z;
    Q  += (size_t)z*qz;  K2 += (size_t)z*kz;
    V2 += (size_t)z*kz;  O  += (size_t)z*oz;
    int h  = blockIdx.y;
    int q0 = blockIdx.x*64;
    int tq = threadIdx.x;
    int q  = q0 + tq;

    __shared__ float Ks[64][64];
    __shared__ float Vs[64][64];

    float qv[64];
    {
        const float4* qp = (const float4*)(Q + (size_t)q*ND + h*64);
        #pragma unroll
        for (int i = 0; i < 16; i++) {
            float4 t = qp[i];
            qv[4*i] = t.x; qv[4*i+1] = t.y; qv[4*i+2] = t.z; qv[4*i+3] = t.w;
        }
    }
    float m = -1e30f, l = 0.f;
    float acc[64];
    #pragma unroll
    for (int i = 0; i < 64; i++) acc[i] = 0.f;

    int ntot = n1 + n2;
    int kmax = ntot;
    int vis  = q0 + 63 + coff + 1;
    if (vis < kmax) kmax = vis;

    for (int t0 = 0; t0 < kmax; t0 += 64) {
        int cnt = ntot - t0; if (cnt > 64) cnt = 64;
        if (tq < cnt) {
            int kk = t0 + tq;
            const float *kp, *vp;
            if (kk < n1) { kp = K1 + (size_t)kk*ND;      vp = V1 + (size_t)kk*ND; }
            else         { kp = K2 + (size_t)(kk-n1)*ND; vp = V2 + (size_t)(kk-n1)*ND; }
            kp += h*64; vp += h*64;
            #pragma unroll
            for (int i = 0; i < 16; i++) {
                ((float4*)Ks[tq])[i] = ((const float4*)kp)[i];
                ((float4*)Vs[tq])[i] = ((const float4*)vp)[i];
            }
        }
        __syncthreads();
        int jend = q + coff - t0 + 1;
        if (jend > cnt) jend = cnt;
        for (int j = 0; j < jend; j++) {
            float s = 0.f;
            #pragma unroll
            for (int d = 0; d < 64; d++) s += qv[d]*Ks[j][d];
            s *= 0.125f;
            float mn   = fmaxf(m, s);
            float corr = expf(m - mn);
            float p    = expf(s - mn);
            l = l*corr + p;
            #pragma unroll
            for (int d = 0; d < 64; d++) acc[d] = acc[d]*corr + p*Vs[j][d];
            m = mn;
        }
        __syncthreads();
    }
    float invl = 1.f/l;
    float* op = O + (size_t)q*ND + h*64;
    #pragma unroll
    for (int d = 0; d < 64; d++) op[d] = acc[d]*invl;
}

/* ------------------------------------------------------------------ */
__global__ void silumul_kernel(float* __restrict__ a, const float* __restrict__ b, int n) {
    int i = blockIdx.x*blockDim.x + threadIdx.x;
    if (i >= n) return;
    float g = a[i];
    a[i] = (g / (1.f + expf(-g))) * b[i];
}

__global__ void gate_out_kernel(const float* __restrict__ mem,
                                const float* __restrict__ inj,
                                const float* __restrict__ fg,
                                float* __restrict__ out, int n) {
    int i = blockIdx.x*blockDim.x + threadIdx.x;
    if (i >= n) return;
    float g = 1.f / (1.f + expf(-fg[i]));
    out[i] = mem[i]*g + inj[i]*(1.f - g);
}

/* ================================================================== */
extern "C" void kernel_launch(void* const* d_in, const int* in_sizes, int n_in,
                              void* d_out, int out_size) {
    const int*   ids    = (const int*)d_in[0];
    const float* memory = (const float*)d_in[1];
    const float* beacon = (const float*)d_in[2];
    const float* forget = (const float*)d_in[3];
    const float* embed  = (const float*)d_in[4];
    const float* ln1    = (const float*)d_in[5];
    const float* ln2    = (const float*)d_in[6];
    const float* Wq  = (const float*)d_in[7];
    const float* Wk  = (const float*)d_in[8];
    const float* Wv  = (const float*)d_in[9];
    const float* Wo  = (const float*)d_in[10];
    const float* mWk = (const float*)d_in[11];
    const float* mWv = (const float*)d_in[12];
    const float* bWq = (const float*)d_in[13];
    const float* bWk = (const float*)d_in[14];
    const float* bWv = (const float*)d_in[15];
    const float* fWq = (const float*)d_in[16];
    const float* fWk = (const float*)d_in[17];
    const float* fWv = (const float*)d_in[18];
    const float* Wg  = (const float*)d_in[19];
    const float* Wu  = (const float*)d_in[20];
    const float* Wd  = (const float*)d_in[21];

    float *cat,*x,*q,*k,*v,*qbf,*kbf,*vbf,*att,*m1,*m2,*inj,*fg;
    cudaGetSymbolAddress((void**)&cat, g_cat);
    cudaGetSymbolAddress((void**)&x,   g_x);
    cudaGetSymbolAddress((void**)&q,   g_q);
    cudaGetSymbolAddress((void**)&k,   g_k);
    cudaGetSymbolAddress((void**)&v,   g_v);
    cudaGetSymbolAddress((void**)&qbf, g_qbf);
    cudaGetSymbolAddress((void**)&kbf, g_kbf);
    cudaGetSymbolAddress((void**)&vbf, g_vbf);
    cudaGetSymbolAddress((void**)&att, g_att);
    cudaGetSymbolAddress((void**)&m1,  g_m1);
    cudaGetSymbolAddress((void**)&m2,  g_m2);
    cudaGetSymbolAddress((void**)&inj, g_inj);
    cudaGetSymbolAddress((void**)&fg,  g_fg);

    const size_t RECB = (size_t)NM*ND*sizeof(float);

    init_tables_kernel<<<(NPOS*32+255)/256, 256>>>();
    gather_kernel<<<NS, 256>>>(ids, embed, cat);
    cudaMemcpyAsync(cat + (size_t)NS*ND,      beacon, RECB, cudaMemcpyDeviceToDevice, 0);
    cudaMemcpyAsync(cat + (size_t)(NS+NM)*ND, forget, RECB, cudaMemcpyDeviceToDevice, 0);

    for (int l = 0; l < 7; l++) {
        const size_t wdd = (size_t)ND*ND;
        const float* Wq_l  = Wq  + l*wdd;  const float* Wk_l  = Wk  + l*wdd;
        const float* Wv_l  = Wv  + l*wdd;  const float* Wo_l  = Wo  + l*wdd;
        const float* mWk_l = mWk + l*wdd;  const float* mWv_l = mWv + l*wdd;
        const float* bWq_l = bWq + l*wdd;  const float* bWk_l = bWk + l*wdd;
        const float* bWv_l = bWv + l*wdd;  const float* fWq_l = fWq + l*wdd;
        const float* fWk_l = fWk + l*wdd;  const float* fWv_l = fWv + l*wdd;
        const float* Wg_l  = Wg + (size_t)l*ND*NF;
        const float* Wu_l  = Wu + (size_t)l*ND*NF;
        const float* Wd_l  = Wd + (size_t)l*NF*ND;
        const float* mem_l = memory + (size_t)l*NM*ND;
        const bool last = (l == 6);

        cudaMemcpyAsync(inj + (size_t)l*NM*ND, cat + (size_t)NS*ND,      RECB, cudaMemcpyDeviceToDevice, 0);
        cudaMemcpyAsync(fg  + (size_t)l*NM*ND, cat + (size_t)(NS+NM)*ND, RECB, cudaMemcpyDeviceToDevice, 0);

        rmsnorm_kernel<<<NCAT, 256>>>(cat, ln1 + (size_t)l*ND, x);

        {
            GemmBatch ba; int nb = 0;
            if (!last) { ba.d[nb].A = x; ba.d[nb].B = Wq_l; ba.d[nb].C = q; nb++; }
            ba.d[nb].A = x; ba.d[nb].B = Wk_l; ba.d[nb].C = k + (size_t)NM*ND; nb++;
            ba.d[nb].A = x; ba.d[nb].B = Wv_l; ba.d[nb].C = v + (size_t)NM*ND; nb++;
            sgemm_batch_kernel<<<dim3(8, 8, nb), 256>>>(ba, ND, ND, 0);
        }
        {
            GemmBatch sa;
            const float* bx = x + (size_t)NS*ND;
            const float* fx = x + (size_t)(NS+NM)*ND;
            sa.d[0].A = mem_l; sa.d[0].B = mWk_l; sa.d[0].C = k;
            sa.d[1].A = mem_l; sa.d[1].B = mWv_l; sa.d[1].C = v;
            sa.d[2].A = bx;    sa.d[2].B = bWq_l; sa.d[2].C = qbf;
            sa.d[3].A = bx;    sa.d[3].B = bWk_l; sa.d[3].C = kbf;
            sa.d[4].A = bx;    sa.d[4].B = bWv_l; sa.d[4].C = vbf;
            sa.d[5].A = fx;    sa.d[5].B = fWq_l; sa.d[5].C = qbf + (size_t)NM*ND;
            sa.d[6].A = fx;    sa.d[6].B = fWk_l; sa.d[6].C = kbf + (size_t)NM*ND;
            sa.d[7].A = fx;    sa.d[7].B = fWv_l; sa.d[7].C = vbf + (size_t)NM*ND;
            sgemm_batch_kernel<<<dim3(8, 1, 8), 256>>>(sa, ND, ND, 0);
        }

        if (!last) rope_kernel<<<NS*2, 256>>>(q, NS, NM);
        rope_kernel<<<NKV*2, 256>>>(k, NKV, 0);
        rope_kernel<<<NM*2, 256>>>(qbf,                 NM, NKV);
        rope_kernel<<<NM*2, 256>>>(qbf + (size_t)NM*ND, NM, NKV);
        rope_kernel<<<NM*2, 256>>>(kbf,                 NM, NKV);
        rope_kernel<<<NM*2, 256>>>(kbf + (size_t)NM*ND, NM, NKV);

        if (!last)
            attn_kernel<<<dim3(NS/64, NH, 1), 64>>>(q, 0, k, v, NKV,
                                                    k, v, 0, 0,
                                                    att, 0, NM);
        attn_kernel<<<dim3(NM/64, NH, 2), 64>>>(qbf, (size_t)NM*ND, k, v, NKV,
                                                kbf, vbf, (size_t)NM*ND, NM,
                                                att + (size_t)NS*ND, (size_t)NM*ND, NKV);

        if (!last)
            sgemm_kernel<<<dim3(8, 10), 256>>>(att, Wo_l, cat, ND, ND, 1);
        else
            sgemm_kernel<<<dim3(8, 2), 256>>>(att + (size_t)NS*ND, Wo_l,
                                              cat + (size_t)NS*ND, ND, ND, 1);

        int rows = last ? 2*NM : NCAT;
        size_t off = last ? (size_t)NS*ND : 0;
        rmsnorm_kernel<<<rows, 256>>>(cat + off, ln2 + (size_t)l*ND, x + off);
        {
            GemmBatch ga;
            ga.d[0].A = x + off; ga.d[0].B = Wg_l; ga.d[0].C = m1;
            ga.d[1].A = x + off; ga.d[1].B = Wu_l; ga.d[1].C = m2;
            sgemm_batch_kernel<<<dim3(NF/128, rows/128, 2), 256>>>(ga, NF, ND, 0);
        }
        silumul_kernel<<<(rows*NF)/256, 256>>>(m1, m2, rows*NF);
        sgemm_kernel<<<dim3(8, rows/128), 256>>>(m1, Wd_l, cat + off, ND, NF, 1);
    }

    cudaMemcpyAsync(inj + (size_t)7*NM*ND, cat + (size_t)NS*ND,      RECB, cudaMemcpyDeviceToDevice, 0);
    cudaMemcpyAsync(fg  + (size_t)7*NM*ND, cat + (size_t)(NS+NM)*ND, RECB, cudaMemcpyDeviceToDevice, 0);

    gate_out_kernel<<<(NL*NM*ND)/256, 256>>>(memory, inj, fg, (float*)d_out, NL*NM*ND);
}

// round 7
// speedup vs baseline: 1.4542x; 1.1585x over previous
#include <cuda_runtime.h>
#include <math.h>
#include <mma.h>
#include <stdint.h>

using namespace nvcuda;

#define NS   1024
#define NM   128
#define ND   1024
#define NH   16
#define NHD  64
#define NF   2048
#define NL   8
#define NCAT 1280   /* S + 2M */
#define NKV  1152   /* M + S  */
#define NPOS 1280

/* ------------------------------------------------------------------ */
/* scratch (static device arrays; no allocation allowed)              */
/* ------------------------------------------------------------------ */
__device__ float g_cat[NCAT*ND];
__device__ float g_x  [NCAT*ND];
__device__ float g_q  [NS*ND];
__device__ float g_k  [NKV*ND];
__device__ float g_v  [NKV*ND];
__device__ float g_qbf[2*NM*ND];
__device__ float g_kbf[2*NM*ND];
__device__ float g_vbf[2*NM*ND];
__device__ float g_att[NCAT*ND];
__device__ float g_m1 [NCAT*NF];
__device__ float g_m2 [NCAT*NF];
__device__ float g_inj[NL*NM*ND];
__device__ float g_fg [NL*NM*ND];
__device__ float g_cs [NPOS*32];
__device__ float g_sn [NPOS*32];

/* ------------------------------------------------------------------ */
__global__ void init_tables_kernel() {
    int idx = blockIdx.x*blockDim.x + threadIdx.x;
    if (idx >= NPOS*32) return;
    int pos = idx >> 5, j = idx & 31;
    double inv = exp(-((double)(2*j)/64.0) * log(10000.0));
    double a = (double)pos * inv;
    g_cs[idx] = (float)cos(a);
    g_sn[idx] = (float)sin(a);
}

__global__ void gather_kernel(const int* __restrict__ ids,
                              const float* __restrict__ embed,
                              float* __restrict__ out) {
    int row = blockIdx.x;
    int id  = ids[row];
    const float4* src = (const float4*)(embed + (size_t)id*ND);
    float4* dst = (float4*)(out + (size_t)row*ND);
    dst[threadIdx.x] = src[threadIdx.x];
}

__global__ void rmsnorm_kernel(const float* __restrict__ x,
                               const float* __restrict__ w,
                               float* __restrict__ y) {
    int row = blockIdx.x, t = threadIdx.x;
    const float* xr = x + (size_t)row*ND;
    float s = 0.f;
    #pragma unroll
    for (int i = t; i < ND; i += 256) { float v = xr[i]; s += v*v; }
    __shared__ float red[256];
    red[t] = s; __syncthreads();
    for (int st = 128; st > 0; st >>= 1) {
        if (t < st) red[t] += red[t+st];
        __syncthreads();
    }
    float r = rsqrtf(red[0]*(1.f/ND) + 1e-5f);
    float* yr = y + (size_t)row*ND;
    #pragma unroll
    for (int i = t; i < ND; i += 256) yr[i] = xr[i]*w[i]*r;
}

__global__ void rope_kernel(float* __restrict__ X, int rows, int pos0) {
    int idx = blockIdx.x*blockDim.x + threadIdx.x;
    if (idx >= rows*512) return;
    int j = idx & 31;
    int h = (idx >> 5) & 15;
    int r = idx >> 9;
    int pos = pos0 + r;
    float c = g_cs[pos*32 + j], s = g_sn[pos*32 + j];
    float* p = X + (size_t)r*ND + h*64;
    float x1 = p[j], x2 = p[j+32];
    p[j]    = x1*c - x2*s;
    p[j+32] = x2*c + x1*s;
}

/* ------------------------------------------------------------------ */
/* tf32 WMMA GEMM: 128x128 tile, 8 warps (32x64), BK=16, cp.async     */
/* 3-stage pipeline, no explicit tf32 cvt (HW truncation).            */
/* ------------------------------------------------------------------ */
struct GemmDesc  { const float* A; const float* B; float* C; };
struct GemmBatch { GemmDesc d[8]; };

typedef wmma::fragment<wmma::matrix_a, 16,16,8, wmma::precision::tf32, wmma::row_major> FragA;
typedef wmma::fragment<wmma::matrix_b, 16,16,8, wmma::precision::tf32, wmma::row_major> FragB;
typedef wmma::fragment<wmma::accumulator, 16,16,8, float> FragC;

#define GSTAGES 3
#define A_STRIDE 20
#define B_STRIDE 132
#define A_TILE_F (128*A_STRIDE)           /* 2560 floats */
#define B_TILE_F (16*B_STRIDE)            /* 2112 floats */
#define GSMEM_BYTES (GSTAGES*(A_TILE_F + B_TILE_F)*4)   /* 56064 */

__device__ __forceinline__ void cp16(uint32_t dst, const void* src) {
    asm volatile("cp.async.cg.shared.global [%0], [%1], 16;" :: "r"(dst), "l"(src));
}
__device__ __forceinline__ void cp_commit() {
    asm volatile("cp.async.commit_group;");
}
__device__ __forceinline__ void cp_wait1() {
    asm volatile("cp.async.wait_group 1;");
}

__device__ __forceinline__ void gemm_core(const float* __restrict__ A,
                                          const float* __restrict__ B,
                                          float* __restrict__ C,
                                          int N, int K, int beta) {
    extern __shared__ float sm[];
    float* Asm = sm;                               /* [GSTAGES][128][20]  */
    float* Bsm = sm + GSTAGES*A_TILE_F;            /* [GSTAGES][16][132]  */

    int tid = threadIdx.x;
    int wid = tid >> 5;
    int wm  = wid & 3;
    int wn  = wid >> 2;
    size_t brow = (size_t)blockIdx.y * 128;
    size_t bcol = (size_t)blockIdx.x * 128;

    /* A load map: thread -> rows r0, r0+64, col quad q0 (16 cols/tile)  */
    int r0 = tid >> 2;
    int q0 = (tid & 3) << 2;
    /* B load map: rows bkr, bkr+8, col quad bc4 (128 cols/tile)         */
    int bkr = tid >> 5;
    int bc4 = (tid & 31) << 2;

    const float* Abase = A + (brow + r0)*K + q0;
    const float* Bbase = B + (size_t)bkr*N + bcol + bc4;

    uint32_t sa0 = (uint32_t)__cvta_generic_to_shared(Asm + r0*A_STRIDE + q0);
    uint32_t sa1 = sa0 + 64*A_STRIDE*4;
    uint32_t sb0 = (uint32_t)__cvta_generic_to_shared(Bsm + bkr*B_STRIDE + bc4);
    uint32_t sb1 = sb0 + 8*B_STRIDE*4;
    const uint32_t aStageB = A_TILE_F*4;
    const uint32_t bStageB = B_TILE_F*4;

    int nt = K >> 4;

    /* prologue: stages 0,1 */
    #pragma unroll
    for (int s = 0; s < 2; s++) {
        int k0 = s << 4;
        cp16(sa0 + s*aStageB, Abase + k0);
        cp16(sa1 + s*aStageB, Abase + k0 + (size_t)64*K);
        cp16(sb0 + s*bStageB, Bbase + (size_t)k0*N);
        cp16(sb1 + s*bStageB, Bbase + (size_t)(k0+8)*N);
        cp_commit();
    }

    FragC acc[2][4];
    #pragma unroll
    for (int mi = 0; mi < 2; mi++)
        #pragma unroll
        for (int ni = 0; ni < 4; ni++)
            wmma::fill_fragment(acc[mi][ni], 0.f);

    int st = 0;           /* compute stage  */
    int ld = 2;           /* next load stage */
    for (int kt = 0; kt < nt; kt++) {
        cp_wait1();
        __syncthreads();
        if (kt + 2 < nt) {
            int k0 = (kt + 2) << 4;
            cp16(sa0 + ld*aStageB, Abase + k0);
            cp16(sa1 + ld*aStageB, Abase + k0 + (size_t)64*K);
            cp16(sb0 + ld*bStageB, Bbase + (size_t)k0*N);
            cp16(sb1 + ld*bStageB, Bbase + (size_t)(k0+8)*N);
        }
        cp_commit();

        const float* Ast = Asm + st*A_TILE_F;
        const float* Bst = Bsm + st*B_TILE_F;
        #pragma unroll
        for (int kk = 0; kk < 16; kk += 8) {
            FragA af[2];
            FragB bf[4];
            #pragma unroll
            for (int mi = 0; mi < 2; mi++)
                wmma::load_matrix_sync(af[mi], Ast + (wm*32 + mi*16)*A_STRIDE + kk, A_STRIDE);
            #pragma unroll
            for (int ni = 0; ni < 4; ni++)
                wmma::load_matrix_sync(bf[ni], Bst + kk*B_STRIDE + wn*64 + ni*16, B_STRIDE);
            #pragma unroll
            for (int mi = 0; mi < 2; mi++)
                #pragma unroll
                for (int ni = 0; ni < 4; ni++)
                    wmma::mma_sync(acc[mi][ni], af[mi], bf[ni], acc[mi][ni]);
        }
        st++; if (st == GSTAGES) st = 0;
        ld++; if (ld == GSTAGES) ld = 0;
    }

    #pragma unroll
    for (int mi = 0; mi < 2; mi++)
        #pragma unroll
        for (int ni = 0; ni < 4; ni++) {
            float* cp = C + (brow + wm*32 + mi*16)*N + bcol + wn*64 + ni*16;
            if (beta) {
                FragC cf;
                wmma::load_matrix_sync(cf, cp, N, wmma::mem_row_major);
                #pragma unroll
                for (int t = 0; t < cf.num_elements; t++)
                    acc[mi][ni].x[t] += cf.x[t];
            }
            wmma::store_matrix_sync(cp, acc[mi][ni], N, wmma::mem_row_major);
        }
}

__global__ __launch_bounds__(256, 2)
void sgemm_kernel(const float* A, const float* B, float* C, int N, int K, int beta) {
    gemm_core(A, B, C, N, K, beta);
}
__global__ __launch_bounds__(256, 2)
void sgemm_batch_kernel(GemmBatch bat, int N, int K, int beta) {
    GemmDesc dsc = bat.d[blockIdx.z];
    gemm_core(dsc.A, dsc.B, dsc.C, N, K, beta);
}

/* ------------------------------------------------------------------ */
/* Flash-style fp32 attention (unchanged this round)                  */
/* ------------------------------------------------------------------ */
__global__ __launch_bounds__(64)
void attn_kernel(const float* Q, size_t qz,
                 const float* K1, const float* V1, int n1,
                 const float* K2, const float* V2, size_t kz, int n2,
                 float* O, size_t oz, int coff) {
    int z = blockIdx.z;
    Q  += (size_t)z*qz;  K2 += (size_t)z*kz;
    V2 += (size_t)z*kz;  O  += (size_t)z*oz;
    int h  = blockIdx.y;
    int q0 = blockIdx.x*64;
    int tq = threadIdx.x;
    int q  = q0 + tq;

    __shared__ float Ks[64][64];
    __shared__ float Vs[64][64];

    float qv[64];
    {
        const float4* qp = (const float4*)(Q + (size_t)q*ND + h*64);
        #pragma unroll
        for (int i = 0; i < 16; i++) {
            float4 t = qp[i];
            qv[4*i] = t.x; qv[4*i+1] = t.y; qv[4*i+2] = t.z; qv[4*i+3] = t.w;
        }
    }
    float m = -1e30f, l = 0.f;
    float acc[64];
    #pragma unroll
    for (int i = 0; i < 64; i++) acc[i] = 0.f;

    int ntot = n1 + n2;
    int kmax = ntot;
    int vis  = q0 + 63 + coff + 1;
    if (vis < kmax) kmax = vis;

    for (int t0 = 0; t0 < kmax; t0 += 64) {
        int cnt = ntot - t0; if (cnt > 64) cnt = 64;
        if (tq < cnt) {
            int kk = t0 + tq;
            const float *kp, *vp;
            if (kk < n1) { kp = K1 + (size_t)kk*ND;      vp = V1 + (size_t)kk*ND; }
            else         { kp = K2 + (size_t)(kk-n1)*ND; vp = V2 + (size_t)(kk-n1)*ND; }
            kp += h*64; vp += h*64;
            #pragma unroll
            for (int i = 0; i < 16; i++) {
                ((float4*)Ks[tq])[i] = ((const float4*)kp)[i];
                ((float4*)Vs[tq])[i] = ((const float4*)vp)[i];
            }
        }
        __syncthreads();
        int jend = q + coff - t0 + 1;
        if (jend > cnt) jend = cnt;
        for (int j = 0; j < jend; j++) {
            float s = 0.f;
            #pragma unroll
            for (int d = 0; d < 64; d++) s += qv[d]*Ks[j][d];
            s *= 0.125f;
            float mn   = fmaxf(m, s);
            float corr = expf(m - mn);
            float p    = expf(s - mn);
            l = l*corr + p;
            #pragma unroll
            for (int d = 0; d < 64; d++) acc[d] = acc[d]*corr + p*Vs[j][d];
            m = mn;
        }
        __syncthreads();
    }
    float invl = 1.f/l;
    float* op = O + (size_t)q*ND + h*64;
    #pragma unroll
    for (int d = 0; d < 64; d++) op[d] = acc[d]*invl;
}

/* ------------------------------------------------------------------ */
__global__ void silumul_kernel(float* __restrict__ a, const float* __restrict__ b, int n) {
    int i = blockIdx.x*blockDim.x + threadIdx.x;
    if (i >= n) return;
    float g = a[i];
    a[i] = (g / (1.f + expf(-g))) * b[i];
}

__global__ void gate_out_kernel(const float* __restrict__ mem,
                                const float* __restrict__ inj,
                                const float* __restrict__ fg,
                                float* __restrict__ out, int n) {
    int i = blockIdx.x*blockDim.x + threadIdx.x;
    if (i >= n) return;
    float g = 1.f / (1.f + expf(-fg[i]));
    out[i] = mem[i]*g + inj[i]*(1.f - g);
}

/* ================================================================== */
extern "C" void kernel_launch(void* const* d_in, const int* in_sizes, int n_in,
                              void* d_out, int out_size) {
    const int*   ids    = (const int*)d_in[0];
    const float* memory = (const float*)d_in[1];
    const float* beacon = (const float*)d_in[2];
    const float* forget = (const float*)d_in[3];
    const float* embed  = (const float*)d_in[4];
    const float* ln1    = (const float*)d_in[5];
    const float* ln2    = (const float*)d_in[6];
    const float* Wq  = (const float*)d_in[7];
    const float* Wk  = (const float*)d_in[8];
    const float* Wv  = (const float*)d_in[9];
    const float* Wo  = (const float*)d_in[10];
    const float* mWk = (const float*)d_in[11];
    const float* mWv = (const float*)d_in[12];
    const float* bWq = (const float*)d_in[13];
    const float* bWk = (const float*)d_in[14];
    const float* bWv = (const float*)d_in[15];
    const float* fWq = (const float*)d_in[16];
    const float* fWk = (const float*)d_in[17];
    const float* fWv = (const float*)d_in[18];
    const float* Wg  = (const float*)d_in[19];
    const float* Wu  = (const float*)d_in[20];
    const float* Wd  = (const float*)d_in[21];

    static int smem_set = 0;
    if (!smem_set) {
        cudaFuncSetAttribute(sgemm_kernel, cudaFuncAttributeMaxDynamicSharedMemorySize, GSMEM_BYTES);
        cudaFuncSetAttribute(sgemm_batch_kernel, cudaFuncAttributeMaxDynamicSharedMemorySize, GSMEM_BYTES);
        smem_set = 1;
    }

    float *cat,*x,*q,*k,*v,*qbf,*kbf,*vbf,*att,*m1,*m2,*inj,*fg;
    cudaGetSymbolAddress((void**)&cat, g_cat);
    cudaGetSymbolAddress((void**)&x,   g_x);
    cudaGetSymbolAddress((void**)&q,   g_q);
    cudaGetSymbolAddress((void**)&k,   g_k);
    cudaGetSymbolAddress((void**)&v,   g_v);
    cudaGetSymbolAddress((void**)&qbf, g_qbf);
    cudaGetSymbolAddress((void**)&kbf, g_kbf);
    cudaGetSymbolAddress((void**)&vbf, g_vbf);
    cudaGetSymbolAddress((void**)&att, g_att);
    cudaGetSymbolAddress((void**)&m1,  g_m1);
    cudaGetSymbolAddress((void**)&m2,  g_m2);
    cudaGetSymbolAddress((void**)&inj, g_inj);
    cudaGetSymbolAddress((void**)&fg,  g_fg);

    const size_t RECB = (size_t)NM*ND*sizeof(float);

    init_tables_kernel<<<(NPOS*32+255)/256, 256>>>();
    gather_kernel<<<NS, 256>>>(ids, embed, cat);
    cudaMemcpyAsync(cat + (size_t)NS*ND,      beacon, RECB, cudaMemcpyDeviceToDevice, 0);
    cudaMemcpyAsync(cat + (size_t)(NS+NM)*ND, forget, RECB, cudaMemcpyDeviceToDevice, 0);

    for (int l = 0; l < 7; l++) {
        const size_t wdd = (size_t)ND*ND;
        const float* Wq_l  = Wq  + l*wdd;  const float* Wk_l  = Wk  + l*wdd;
        const float* Wv_l  = Wv  + l*wdd;  const float* Wo_l  = Wo  + l*wdd;
        const float* mWk_l = mWk + l*wdd;  const float* mWv_l = mWv + l*wdd;
        const float* bWq_l = bWq + l*wdd;  const float* bWk_l = bWk + l*wdd;
        const float* bWv_l = bWv + l*wdd;  const float* fWq_l = fWq + l*wdd;
        const float* fWk_l = fWk + l*wdd;  const float* fWv_l = fWv + l*wdd;
        const float* Wg_l  = Wg + (size_t)l*ND*NF;
        const float* Wu_l  = Wu + (size_t)l*ND*NF;
        const float* Wd_l  = Wd + (size_t)l*NF*ND;
        const float* mem_l = memory + (size_t)l*NM*ND;
        const bool last = (l == 6);

        cudaMemcpyAsync(inj + (size_t)l*NM*ND, cat + (size_t)NS*ND,      RECB, cudaMemcpyDeviceToDevice, 0);
        cudaMemcpyAsync(fg  + (size_t)l*NM*ND, cat + (size_t)(NS+NM)*ND, RECB, cudaMemcpyDeviceToDevice, 0);

        rmsnorm_kernel<<<NCAT, 256>>>(cat, ln1 + (size_t)l*ND, x);

        {
            GemmBatch ba; int nb = 0;
            if (!last) { ba.d[nb].A = x; ba.d[nb].B = Wq_l; ba.d[nb].C = q; nb++; }
            ba.d[nb].A = x; ba.d[nb].B = Wk_l; ba.d[nb].C = k + (size_t)NM*ND; nb++;
            ba.d[nb].A = x; ba.d[nb].B = Wv_l; ba.d[nb].C = v + (size_t)NM*ND; nb++;
            sgemm_batch_kernel<<<dim3(8, 8, nb), 256, GSMEM_BYTES>>>(ba, ND, ND, 0);
        }
        {
            GemmBatch sa;
            const float* bx = x + (size_t)NS*ND;
            const float* fx = x + (size_t)(NS+NM)*ND;
            sa.d[0].A = mem_l; sa.d[0].B = mWk_l; sa.d[0].C = k;
            sa.d[1].A = mem_l; sa.d[1].B = mWv_l; sa.d[1].C = v;
            sa.d[2].A = bx;    sa.d[2].B = bWq_l; sa.d[2].C = qbf;
            sa.d[3].A = bx;    sa.d[3].B = bWk_l; sa.d[3].C = kbf;
            sa.d[4].A = bx;    sa.d[4].B = bWv_l; sa.d[4].C = vbf;
            sa.d[5].A = fx;    sa.d[5].B = fWq_l; sa.d[5].C = qbf + (size_t)NM*ND;
            sa.d[6].A = fx;    sa.d[6].B = fWk_l; sa.d[6].C = kbf + (size_t)NM*ND;
            sa.d[7].A = fx;    sa.d[7].B = fWv_l; sa.d[7].C = vbf + (size_t)NM*ND;
            sgemm_batch_kernel<<<dim3(8, 1, 8), 256, GSMEM_BYTES>>>(sa, ND, ND, 0);
        }

        if (!last) rope_kernel<<<NS*2, 256>>>(q, NS, NM);
        rope_kernel<<<NKV*2, 256>>>(k, NKV, 0);
        rope_kernel<<<NM*2, 256>>>(qbf,                 NM, NKV);
        rope_kernel<<<NM*2, 256>>>(qbf + (size_t)NM*ND, NM, NKV);
        rope_kernel<<<NM*2, 256>>>(kbf,                 NM, NKV);
        rope_kernel<<<NM*2, 256>>>(kbf + (size_t)NM*ND, NM, NKV);

        if (!last)
            attn_kernel<<<dim3(NS/64, NH, 1), 64>>>(q, 0, k, v, NKV,
                                                    k, v, 0, 0,
                                                    att, 0, NM);
        attn_kernel<<<dim3(NM/64, NH, 2), 64>>>(qbf, (size_t)NM*ND, k, v, NKV,
                                                kbf, vbf, (size_t)NM*ND, NM,
                                                att + (size_t)NS*ND, (size_t)NM*ND, NKV);

        if (!last)
            sgemm_kernel<<<dim3(8, 10), 256, GSMEM_BYTES>>>(att, Wo_l, cat, ND, ND, 1);
        else
            sgemm_kernel<<<dim3(8, 2), 256, GSMEM_BYTES>>>(att + (size_t)NS*ND, Wo_l,
                                              cat + (size_t)NS*ND, ND, ND, 1);

        int rows = last ? 2*NM : NCAT;
        size_t off = last ? (size_t)NS*ND : 0;
        rmsnorm_kernel<<<rows, 256>>>(cat + off, ln2 + (size_t)l*ND, x + off);
        {
            GemmBatch ga;
            ga.d[0].A = x + off; ga.d[0].B = Wg_l; ga.d[0].C = m1;
            ga.d[1].A = x + off; ga.d[1].B = Wu_l; ga.d[1].C = m2;
            sgemm_batch_kernel<<<dim3(NF/128, rows/128, 2), 256, GSMEM_BYTES>>>(ga, NF, ND, 0);
        }
        silumul_kernel<<<(rows*NF)/256, 256>>>(m1, m2, rows*NF);
        sgemm_kernel<<<dim3(8, rows/128), 256, GSMEM_BYTES>>>(m1, Wd_l, cat + off, ND, NF, 1);
    }

    cudaMemcpyAsync(inj + (size_t)7*NM*ND, cat + (size_t)NS*ND,      RECB, cudaMemcpyDeviceToDevice, 0);
    cudaMemcpyAsync(fg  + (size_t)7*NM*ND, cat + (size_t)(NS+NM)*ND, RECB, cudaMemcpyDeviceToDevice, 0);

    gate_out_kernel<<<(NL*NM*ND)/256, 256>>>(memory, inj, fg, (float*)d_out, NL*NM*ND);
}

// round 8
// speedup vs baseline: 1.9468x; 1.3387x over previous
#include <cuda_runtime.h>
#include <math.h>
#include <mma.h>
#include <stdint.h>

using namespace nvcuda;

#define NS   1024
#define NM   128
#define ND   1024
#define NH   16
#define NHD  64
#define NF   2048
#define NL   8
#define NCAT 1280   /* S + 2M */
#define NKV  1152   /* M + S  */
#define NPOS 1280

/* ------------------------------------------------------------------ */
/* scratch (static device arrays; no allocation allowed)              */
/* ------------------------------------------------------------------ */
__device__ float g_cat[NCAT*ND];
__device__ float g_x  [NCAT*ND];
__device__ float g_q  [NS*ND];
__device__ float g_k  [NKV*ND];
__device__ float g_v  [NKV*ND];
__device__ float g_qbf[2*NM*ND];
__device__ float g_kbf[2*NM*ND];
__device__ float g_vbf[2*NM*ND];
__device__ float g_att[NCAT*ND];
__device__ float g_m1 [NCAT*NF];
__device__ float g_m2 [NCAT*NF];
__device__ float g_inj[NL*NM*ND];
__device__ float g_fg [NL*NM*ND];
__device__ float g_memr[7*NM*ND];
__device__ float g_cs [NPOS*32];
__device__ float g_sn [NPOS*32];

/* round-to-nearest onto the tf32 grid (so HW truncation is exact)    */
__device__ __forceinline__ float tf32r(float x) {
    unsigned u = __float_as_uint(x), r;
    asm("cvt.rna.tf32.f32 %0, %1;" : "=r"(r) : "r"(u));
    return __uint_as_float(r);
}

/* ------------------------------------------------------------------ */
__global__ void init_tables_kernel() {
    int idx = blockIdx.x*blockDim.x + threadIdx.x;
    if (idx >= NPOS*32) return;
    int pos = idx >> 5, j = idx & 31;
    double inv = exp(-((double)(2*j)/64.0) * log(10000.0));
    double a = (double)pos * inv;
    g_cs[idx] = (float)cos(a);
    g_sn[idx] = (float)sin(a);
}

__global__ void gather_kernel(const int* __restrict__ ids,
                              const float* __restrict__ embed,
                              float* __restrict__ out) {
    int row = blockIdx.x;
    int id  = ids[row];
    const float4* src = (const float4*)(embed + (size_t)id*ND);
    float4* dst = (float4*)(out + (size_t)row*ND);
    dst[threadIdx.x] = src[threadIdx.x];
}

__global__ void round_kernel(const float* __restrict__ in,
                             float* __restrict__ out, int n) {
    int i = blockIdx.x*blockDim.x + threadIdx.x;
    if (i < n) out[i] = tf32r(in[i]);
}

/* RMSNorm; output rounded to tf32 grid (feeds GEMM A)                */
__global__ void rmsnorm_kernel(const float* __restrict__ x,
                               const float* __restrict__ w,
                               float* __restrict__ y) {
    int row = blockIdx.x, t = threadIdx.x;
    const float* xr = x + (size_t)row*ND;
    float s = 0.f;
    #pragma unroll
    for (int i = t; i < ND; i += 256) { float v = xr[i]; s += v*v; }
    __shared__ float red[256];
    red[t] = s; __syncthreads();
    for (int st = 128; st > 0; st >>= 1) {
        if (t < st) red[t] += red[t+st];
        __syncthreads();
    }
    float r = rsqrtf(red[0]*(1.f/ND) + 1e-5f);
    float* yr = y + (size_t)row*ND;
    #pragma unroll
    for (int i = t; i < ND; i += 256) yr[i] = tf32r(xr[i]*w[i]*r);
}

__global__ void rope_kernel(float* __restrict__ X, int rows, int pos0) {
    int idx = blockIdx.x*blockDim.x + threadIdx.x;
    if (idx >= rows*512) return;
    int j = idx & 31;
    int h = (idx >> 5) & 15;
    int r = idx >> 9;
    int pos = pos0 + r;
    float c = g_cs[pos*32 + j], s = g_sn[pos*32 + j];
    float* p = X + (size_t)r*ND + h*64;
    float x1 = p[j], x2 = p[j+32];
    p[j]    = x1*c - x2*s;
    p[j+32] = x2*c + x1*s;
}

/* ------------------------------------------------------------------ */
/* tf32 WMMA GEMM v2: 128x128 CTA tile, 4 warps (64x64 each), BK=32,  */
/* 3-stage cp.async. A pre-rounded to tf32 (exact truncation); B      */
/* RN-converted in the fragment.                                      */
/* ------------------------------------------------------------------ */
struct GemmDesc  { const float* A; const float* B; float* C; };
struct GemmBatch { GemmDesc d[8]; };

typedef wmma::fragment<wmma::matrix_a, 16,16,8, wmma::precision::tf32, wmma::row_major> FragA;
typedef wmma::fragment<wmma::matrix_b, 16,16,8, wmma::precision::tf32, wmma::row_major> FragB;
typedef wmma::fragment<wmma::accumulator, 16,16,8, float> FragC;

#define GSTAGES 3
#define A_STRIDE 36
#define B_STRIDE 132
#define A_TILE_F (128*A_STRIDE)           /* 4608 floats */
#define B_TILE_F (32*B_STRIDE)            /* 4224 floats */
#define GSMEM_BYTES (GSTAGES*(A_TILE_F + B_TILE_F)*4)   /* 105984 */

__device__ __forceinline__ void cp16(uint32_t dst, const void* src) {
    asm volatile("cp.async.cg.shared.global [%0], [%1], 16;" :: "r"(dst), "l"(src));
}
__device__ __forceinline__ void cp_commit() {
    asm volatile("cp.async.commit_group;");
}
__device__ __forceinline__ void cp_wait1() {
    asm volatile("cp.async.wait_group 1;");
}

__device__ __forceinline__ void gemm_core(const float* __restrict__ A,
                                          const float* __restrict__ B,
                                          float* __restrict__ C,
                                          int N, int K, int beta) {
    extern __shared__ float sm[];
    float* Asm = sm;                               /* [3][128][36] */
    float* Bsm = sm + GSTAGES*A_TILE_F;            /* [3][32][132] */

    int tid = threadIdx.x;
    int wid = tid >> 5;
    int wy  = wid >> 1;          /* 0..1 -> 64-row strip */
    int wx  = wid & 1;           /* 0..1 -> 64-col strip */
    size_t brow = (size_t)blockIdx.y * 128;
    size_t bcol = (size_t)blockIdx.x * 128;

    /* A: thread covers rows ar+16i (i<8), 4 cols at ac. warp = 4 rows x 32 cols */
    int ar = tid >> 3, ac = (tid & 7) << 2;
    /* B: thread covers rows br+4i (i<8), 4 cols at bc. warp = 1 row x 128 cols  */
    int br = tid >> 5, bc = (tid & 31) << 2;

    const float* Ag = A + (brow + ar)*K + ac;
    const float* Bg = B + (size_t)br*N + bcol + bc;

    uint32_t sA = (uint32_t)__cvta_generic_to_shared(Asm + ar*A_STRIDE + ac);
    uint32_t sB = (uint32_t)__cvta_generic_to_shared(Bsm + br*B_STRIDE + bc);
    const uint32_t aStageB = A_TILE_F*4;
    const uint32_t bStageB = B_TILE_F*4;

    int nt = K >> 5;

    /* prologue: stages 0,1 */
    #pragma unroll
    for (int s = 0; s < 2; s++) {
        int k0 = s << 5;
        #pragma unroll
        for (int i = 0; i < 8; i++)
            cp16(sA + s*aStageB + i*16*A_STRIDE*4, Ag + k0 + (size_t)(16*i)*K);
        #pragma unroll
        for (int i = 0; i < 8; i++)
            cp16(sB + s*bStageB + i*4*B_STRIDE*4, Bg + (size_t)(k0 + 4*i)*N);
        cp_commit();
    }

    FragC acc[4][4];
    #pragma unroll
    for (int mi = 0; mi < 4; mi++)
        #pragma unroll
        for (int ni = 0; ni < 4; ni++)
            wmma::fill_fragment(acc[mi][ni], 0.f);

    int st = 0, ld = 2;
    for (int kt = 0; kt < nt; kt++) {
        cp_wait1();
        __syncthreads();
        if (kt + 2 < nt) {
            int k0 = (kt + 2) << 5;
            #pragma unroll
            for (int i = 0; i < 8; i++)
                cp16(sA + ld*aStageB + i*16*A_STRIDE*4, Ag + k0 + (size_t)(16*i)*K);
            #pragma unroll
            for (int i = 0; i < 8; i++)
                cp16(sB + ld*bStageB + i*4*B_STRIDE*4, Bg + (size_t)(k0 + 4*i)*N);
        }
        cp_commit();

        const float* Ast = Asm + st*A_TILE_F;
        const float* Bst = Bsm + st*B_TILE_F;
        #pragma unroll
        for (int kk = 0; kk < 32; kk += 8) {
            FragA af[4];
            FragB bf[4];
            #pragma unroll
            for (int mi = 0; mi < 4; mi++)
                wmma::load_matrix_sync(af[mi], Ast + (wy*64 + mi*16)*A_STRIDE + kk, A_STRIDE);
            #pragma unroll
            for (int ni = 0; ni < 4; ni++) {
                wmma::load_matrix_sync(bf[ni], Bst + kk*B_STRIDE + wx*64 + ni*16, B_STRIDE);
                #pragma unroll
                for (int t = 0; t < bf[ni].num_elements; t++)
                    bf[ni].x[t] = wmma::__float_to_tf32(bf[ni].x[t]);
            }
            #pragma unroll
            for (int mi = 0; mi < 4; mi++)
                #pragma unroll
                for (int ni = 0; ni < 4; ni++)
                    wmma::mma_sync(acc[mi][ni], af[mi], bf[ni], acc[mi][ni]);
        }
        st++; if (st == GSTAGES) st = 0;
        ld++; if (ld == GSTAGES) ld = 0;
    }

    #pragma unroll
    for (int mi = 0; mi < 4; mi++)
        #pragma unroll
        for (int ni = 0; ni < 4; ni++) {
            float* cp = C + (brow + wy*64 + mi*16)*N + bcol + wx*64 + ni*16;
            if (beta) {
                FragC cf;
                wmma::load_matrix_sync(cf, cp, N, wmma::mem_row_major);
                #pragma unroll
                for (int t = 0; t < cf.num_elements; t++)
                    acc[mi][ni].x[t] += cf.x[t];
            }
            wmma::store_matrix_sync(cp, acc[mi][ni], N, wmma::mem_row_major);
        }
}

__global__ __launch_bounds__(128, 2)
void sgemm_kernel(const float* A, const float* B, float* C, int N, int K, int beta) {
    gemm_core(A, B, C, N, K, beta);
}
__global__ __launch_bounds__(128, 2)
void sgemm_batch_kernel(GemmBatch bat, int N, int K, int beta) {
    GemmDesc dsc = bat.d[blockIdx.z];
    gemm_core(dsc.A, dsc.B, dsc.C, N, K, beta);
}

/* ------------------------------------------------------------------ */
/* Flash-style fp32 attention v2: 128 threads = 2 key-split halves of */
/* 64 query-threads. Halves process interleaved 64-key tiles with     */
/* private (m,l,acc); merged via smem. Scores chunked by 8 so the acc */
/* rescale runs once per 8 keys. Output rounded to tf32 (feeds Wo A). */
/* smem: Ks[2][64][64] | Vs[2][64][64] = 64KB (dynamic)               */
/* ------------------------------------------------------------------ */
#define ATTN_SMEM 65536

__global__ __launch_bounds__(128)
void attn_kernel(const float* Q, size_t qz,
                 const float* K1, const float* V1, int n1,
                 const float* K2, const float* V2, size_t kz, int n2,
                 float* O, size_t oz, int coff) {
    extern __shared__ float sm[];
    int z = blockIdx.z;
    Q  += (size_t)z*qz;  K2 += (size_t)z*kz;
    V2 += (size_t)z*kz;  O  += (size_t)z*oz;
    int h    = blockIdx.y;
    int q0   = blockIdx.x*64;
    int tq   = threadIdx.x & 63;
    int half = threadIdx.x >> 6;
    int q    = q0 + tq;

    float* Ks = sm + half*4096;
    float* Vs = sm + 8192 + half*4096;

    float qv[64];
    {
        const float4* qp = (const float4*)(Q + (size_t)q*ND + h*64);
        #pragma unroll
        for (int i = 0; i < 16; i++) {
            float4 t = qp[i];
            qv[4*i] = t.x; qv[4*i+1] = t.y; qv[4*i+2] = t.z; qv[4*i+3] = t.w;
        }
    }
    float m = -1e30f, l = 0.f;
    float acc[64];
    #pragma unroll
    for (int i = 0; i < 64; i++) acc[i] = 0.f;

    int ntot = n1 + n2;
    int kmax = ntot;
    int vis  = q0 + 63 + coff + 1;
    if (vis < kmax) kmax = vis;
    int ntiles = (kmax + 63) >> 6;
    int npairs = (ntiles + 1) >> 1;

    for (int p = 0; p < npairs; p++) {
        int ti = 2*p + half;
        int t0 = ti << 6;
        bool active = (t0 < kmax);
        int cnt = ntot - t0; if (cnt > 64) cnt = 64;
        __syncthreads();
        if (active) {
            if (tq < cnt) {
                int kk = t0 + tq;
                const float *kp, *vp;
                if (kk < n1) { kp = K1 + (size_t)kk*ND;      vp = V1 + (size_t)kk*ND; }
                else         { kp = K2 + (size_t)(kk-n1)*ND; vp = V2 + (size_t)(kk-n1)*ND; }
                kp += h*64; vp += h*64;
                #pragma unroll
                for (int i = 0; i < 16; i++) {
                    ((float4*)(Ks + tq*64))[i] = ((const float4*)kp)[i];
                    ((float4*)(Vs + tq*64))[i] = ((const float4*)vp)[i];
                }
            } else {
                float4 z4 = make_float4(0.f,0.f,0.f,0.f);
                #pragma unroll
                for (int i = 0; i < 16; i++)
                    ((float4*)(Vs + tq*64))[i] = z4;
            }
        }
        __syncthreads();
        if (!active) continue;
        int jend = q + coff - t0 + 1;
        if (jend > cnt) jend = cnt;
        for (int j0 = 0; j0 < jend; j0 += 8) {
            float sc[8];
            float smax = -1e30f;
            #pragma unroll
            for (int jj = 0; jj < 8; jj++) {
                int j = j0 + jj;
                float s = -1e30f;
                if (j < jend) {
                    const float* kr = Ks + j*64;
                    s = 0.f;
                    #pragma unroll
                    for (int d = 0; d < 64; d++) s += qv[d]*kr[d];
                    s *= 0.125f;
                }
                sc[jj] = s;
                smax = fmaxf(smax, s);
            }
            float mn   = fmaxf(m, smax);
            float corr = expf(m - mn);
            l *= corr;
            #pragma unroll
            for (int d = 0; d < 64; d++) acc[d] *= corr;
            #pragma unroll
            for (int jj = 0; jj < 8; jj++) {
                float pj = expf(sc[jj] - mn);
                l += pj;
                const float* vr = Vs + (j0 + jj)*64;
                #pragma unroll
                for (int d = 0; d < 64; d++) acc[d] += pj*vr[d];
            }
            m = mn;
        }
    }

    /* merge the two halves */
    __syncthreads();
    float* buf = sm;                      /* 64 x 66 floats, reuses Ks */
    if (half == 1) {
        buf[tq*66 + 0] = m;
        buf[tq*66 + 1] = l;
        #pragma unroll
        for (int d = 0; d < 64; d++) buf[tq*66 + 2 + d] = acc[d];
    }
    __syncthreads();
    if (half == 0) {
        float m1v = buf[tq*66 + 0], l1v = buf[tq*66 + 1];
        float mn = fmaxf(m, m1v);
        float c0 = expf(m - mn), c1 = expf(m1v - mn);
        float invl = 1.f/(l*c0 + l1v*c1);
        float* op = O + (size_t)q*ND + h*64;
        #pragma unroll
        for (int d = 0; d < 64; d++)
            op[d] = tf32r((acc[d]*c0 + buf[tq*66 + 2 + d]*c1)*invl);
    }
}

/* ------------------------------------------------------------------ */
__global__ void silumul_kernel(float* __restrict__ a, const float* __restrict__ b, int n) {
    int i = blockIdx.x*blockDim.x + threadIdx.x;
    if (i >= n) return;
    float g = a[i];
    a[i] = tf32r((g / (1.f + expf(-g))) * b[i]);
}

__global__ void gate_out_kernel(const float* __restrict__ mem,
                                const float* __restrict__ inj,
                                const float* __restrict__ fg,
                                float* __restrict__ out, int n) {
    int i = blockIdx.x*blockDim.x + threadIdx.x;
    if (i >= n) return;
    float g = 1.f / (1.f + expf(-fg[i]));
    out[i] = mem[i]*g + inj[i]*(1.f - g);
}

/* ================================================================== */
extern "C" void kernel_launch(void* const* d_in, const int* in_sizes, int n_in,
                              void* d_out, int out_size) {
    const int*   ids    = (const int*)d_in[0];
    const float* memory = (const float*)d_in[1];
    const float* beacon = (const float*)d_in[2];
    const float* forget = (const float*)d_in[3];
    const float* embed  = (const float*)d_in[4];
    const float* ln1    = (const float*)d_in[5];
    const float* ln2    = (const float*)d_in[6];
    const float* Wq  = (const float*)d_in[7];
    const float* Wk  = (const float*)d_in[8];
    const float* Wv  = (const float*)d_in[9];
    const float* Wo  = (const float*)d_in[10];
    const float* mWk = (const float*)d_in[11];
    const float* mWv = (const float*)d_in[12];
    const float* bWq = (const float*)d_in[13];
    const float* bWk = (const float*)d_in[14];
    const float* bWv = (const float*)d_in[15];
    const float* fWq = (const float*)d_in[16];
    const float* fWk = (const float*)d_in[17];
    const float* fWv = (const float*)d_in[18];
    const float* Wg  = (const float*)d_in[19];
    const float* Wu  = (const float*)d_in[20];
    const float* Wd  = (const float*)d_in[21];

    static int attr_set = 0;
    if (!attr_set) {
        cudaFuncSetAttribute(sgemm_kernel, cudaFuncAttributeMaxDynamicSharedMemorySize, GSMEM_BYTES);
        cudaFuncSetAttribute(sgemm_batch_kernel, cudaFuncAttributeMaxDynamicSharedMemorySize, GSMEM_BYTES);
        cudaFuncSetAttribute(attn_kernel, cudaFuncAttributeMaxDynamicSharedMemorySize, ATTN_SMEM);
        attr_set = 1;
    }

    float *cat,*x,*q,*k,*v,*qbf,*kbf,*vbf,*att,*m1,*m2,*inj,*fg,*memr;
    cudaGetSymbolAddress((void**)&cat, g_cat);
    cudaGetSymbolAddress((void**)&x,   g_x);
    cudaGetSymbolAddress((void**)&q,   g_q);
    cudaGetSymbolAddress((void**)&k,   g_k);
    cudaGetSymbolAddress((void**)&v,   g_v);
    cudaGetSymbolAddress((void**)&qbf, g_qbf);
    cudaGetSymbolAddress((void**)&kbf, g_kbf);
    cudaGetSymbolAddress((void**)&vbf, g_vbf);
    cudaGetSymbolAddress((void**)&att, g_att);
    cudaGetSymbolAddress((void**)&m1,  g_m1);
    cudaGetSymbolAddress((void**)&m2,  g_m2);
    cudaGetSymbolAddress((void**)&inj, g_inj);
    cudaGetSymbolAddress((void**)&fg,  g_fg);
    cudaGetSymbolAddress((void**)&memr,g_memr);

    const size_t RECB = (size_t)NM*ND*sizeof(float);

    init_tables_kernel<<<(NPOS*32+255)/256, 256>>>();
    gather_kernel<<<NS, 256>>>(ids, embed, cat);
    round_kernel<<<(7*NM*ND)/256, 256>>>(memory, memr, 7*NM*ND);
    cudaMemcpyAsync(cat + (size_t)NS*ND,      beacon, RECB, cudaMemcpyDeviceToDevice, 0);
    cudaMemcpyAsync(cat + (size_t)(NS+NM)*ND, forget, RECB, cudaMemcpyDeviceToDevice, 0);

    for (int l = 0; l < 7; l++) {
        const size_t wdd = (size_t)ND*ND;
        const float* Wq_l  = Wq  + l*wdd;  const float* Wk_l  = Wk  + l*wdd;
        const float* Wv_l  = Wv  + l*wdd;  const float* Wo_l  = Wo  + l*wdd;
        const float* mWk_l = mWk + l*wdd;  const float* mWv_l = mWv + l*wdd;
        const float* bWq_l = bWq + l*wdd;  const float* bWk_l = bWk + l*wdd;
        const float* bWv_l = bWv + l*wdd;  const float* fWq_l = fWq + l*wdd;
        const float* fWk_l = fWk + l*wdd;  const float* fWv_l = fWv + l*wdd;
        const float* Wg_l  = Wg + (size_t)l*ND*NF;
        const float* Wu_l  = Wu + (size_t)l*ND*NF;
        const float* Wd_l  = Wd + (size_t)l*NF*ND;
        const float* mem_l = memr + (size_t)l*NM*ND;
        const bool last = (l == 6);

        cudaMemcpyAsync(inj + (size_t)l*NM*ND, cat + (size_t)NS*ND,      RECB, cudaMemcpyDeviceToDevice, 0);
        cudaMemcpyAsync(fg  + (size_t)l*NM*ND, cat + (size_t)(NS+NM)*ND, RECB, cudaMemcpyDeviceToDevice, 0);

        rmsnorm_kernel<<<NCAT, 256>>>(cat, ln1 + (size_t)l*ND, x);

        {
            GemmBatch ba; int nb = 0;
            if (!last) { ba.d[nb].A = x; ba.d[nb].B = Wq_l; ba.d[nb].C = q; nb++; }
            ba.d[nb].A = x; ba.d[nb].B = Wk_l; ba.d[nb].C = k + (size_t)NM*ND; nb++;
            ba.d[nb].A = x; ba.d[nb].B = Wv_l; ba.d[nb].C = v + (size_t)NM*ND; nb++;
            sgemm_batch_kernel<<<dim3(8, 8, nb), 128, GSMEM_BYTES>>>(ba, ND, ND, 0);
        }
        {
            GemmBatch sa;
            const float* bx = x + (size_t)NS*ND;
            const float* fx = x + (size_t)(NS+NM)*ND;
            sa.d[0].A = mem_l; sa.d[0].B = mWk_l; sa.d[0].C = k;
            sa.d[1].A = mem_l; sa.d[1].B = mWv_l; sa.d[1].C = v;
            sa.d[2].A = bx;    sa.d[2].B = bWq_l; sa.d[2].C = qbf;
            sa.d[3].A = bx;    sa.d[3].B = bWk_l; sa.d[3].C = kbf;
            sa.d[4].A = bx;    sa.d[4].B = bWv_l; sa.d[4].C = vbf;
            sa.d[5].A = fx;    sa.d[5].B = fWq_l; sa.d[5].C = qbf + (size_t)NM*ND;
            sa.d[6].A = fx;    sa.d[6].B = fWk_l; sa.d[6].C = kbf + (size_t)NM*ND;
            sa.d[7].A = fx;    sa.d[7].B = fWv_l; sa.d[7].C = vbf + (size_t)NM*ND;
            sgemm_batch_kernel<<<dim3(8, 1, 8), 128, GSMEM_BYTES>>>(sa, ND, ND, 0);
        }

        if (!last) rope_kernel<<<NS*2, 256>>>(q, NS, NM);
        rope_kernel<<<NKV*2, 256>>>(k, NKV, 0);
        rope_kernel<<<NM*2, 256>>>(qbf,                 NM, NKV);
        rope_kernel<<<NM*2, 256>>>(qbf + (size_t)NM*ND, NM, NKV);
        rope_kernel<<<NM*2, 256>>>(kbf,                 NM, NKV);
        rope_kernel<<<NM*2, 256>>>(kbf + (size_t)NM*ND, NM, NKV);

        if (!last)
            attn_kernel<<<dim3(NS/64, NH, 1), 128, ATTN_SMEM>>>(q, 0, k, v, NKV,
                                                    k, v, 0, 0,
                                                    att, 0, NM);
        attn_kernel<<<dim3(NM/64, NH, 2), 128, ATTN_SMEM>>>(qbf, (size_t)NM*ND, k, v, NKV,
                                                kbf, vbf, (size_t)NM*ND, NM,
                                                att + (size_t)NS*ND, (size_t)NM*ND, NKV);

        if (!last)
            sgemm_kernel<<<dim3(8, 10), 128, GSMEM_BYTES>>>(att, Wo_l, cat, ND, ND, 1);
        else
            sgemm_kernel<<<dim3(8, 2), 128, GSMEM_BYTES>>>(att + (size_t)NS*ND, Wo_l,
                                              cat + (size_t)NS*ND, ND, ND, 1);

        int rows = last ? 2*NM : NCAT;
        size_t off = last ? (size_t)NS*ND : 0;
        rmsnorm_kernel<<<rows, 256>>>(cat + off, ln2 + (size_t)l*ND, x + off);
        {
            GemmBatch ga;
            ga.d[0].A = x + off; ga.d[0].B = Wg_l; ga.d[0].C = m1;
            ga.d[1].A = x + off; ga.d[1].B = Wu_l; ga.d[1].C = m2;
            sgemm_batch_kernel<<<dim3(NF/128, rows/128, 2), 128, GSMEM_BYTES>>>(ga, NF, ND, 0);
        }
        silumul_kernel<<<(rows*NF)/256, 256>>>(m1, m2, rows*NF);
        sgemm_kernel<<<dim3(8, rows/128), 128, GSMEM_BYTES>>>(m1, Wd_l, cat + off, ND, NF, 1);
    }

    cudaMemcpyAsync(inj + (size_t)7*NM*ND, cat + (size_t)NS*ND,      RECB, cudaMemcpyDeviceToDevice, 0);
    cudaMemcpyAsync(fg  + (size_t)7*NM*ND, cat + (size_t)(NS+NM)*ND, RECB, cudaMemcpyDeviceToDevice, 0);

    gate_out_kernel<<<(NL*NM*ND)/256, 256>>>(memory, inj, fg, (float*)d_out, NL*NM*ND);
}

// round 10
// speedup vs baseline: 1.9929x; 1.0237x over previous
#include <cuda_runtime.h>
#include <math.h>
#include <mma.h>
#include <stdint.h>

using namespace nvcuda;

#define NS   1024
#define NM   128
#define ND   1024
#define NH   16
#define NHD  64
#define NF   2048
#define NL   8
#define NCAT 1280   /* S + 2M */
#define NKV  1152   /* M + S  */
#define NPOS 1280

/* ------------------------------------------------------------------ */
/* scratch (static device arrays; no allocation allowed)              */
/* ------------------------------------------------------------------ */
__device__ float g_cat[NCAT*ND];
__device__ float g_x  [NCAT*ND];
__device__ float g_q  [NS*ND];
__device__ float g_k  [NKV*ND];
__device__ float g_v  [NKV*ND];
__device__ float g_qbf[2*NM*ND];
__device__ float g_kbf[2*NM*ND];
__device__ float g_vbf[2*NM*ND];
__device__ float g_att[NCAT*ND];
__device__ float g_m1 [NCAT*NF];
__device__ float g_m2 [NCAT*NF];
__device__ float g_inj[NL*NM*ND];
__device__ float g_fg [NL*NM*ND];
__device__ float g_memr[7*NM*ND];
__device__ float g_cs [NPOS*32];
__device__ float g_sn [NPOS*32];

/* round-to-nearest onto the tf32 grid (so HW truncation is exact)    */
__device__ __forceinline__ float tf32r(float x) {
    unsigned u = __float_as_uint(x), r;
    asm("cvt.rna.tf32.f32 %0, %1;" : "=r"(r) : "r"(u));
    return __uint_as_float(r);
}

/* ------------------------------------------------------------------ */
__global__ void init_tables_kernel() {
    int idx = blockIdx.x*blockDim.x + threadIdx.x;
    if (idx >= NPOS*32) return;
    int pos = idx >> 5, j = idx & 31;
    double inv = exp(-((double)(2*j)/64.0) * log(10000.0));
    double a = (double)pos * inv;
    g_cs[idx] = (float)cos(a);
    g_sn[idx] = (float)sin(a);
}

__global__ void gather_kernel(const int* __restrict__ ids,
                              const float* __restrict__ embed,
                              float* __restrict__ out) {
    int row = blockIdx.x;
    int id  = ids[row];
    const float4* src = (const float4*)(embed + (size_t)id*ND);
    float4* dst = (float4*)(out + (size_t)row*ND);
    dst[threadIdx.x] = src[threadIdx.x];
}

__global__ void round_kernel(const float* __restrict__ in,
                             float* __restrict__ out, int n) {
    int i = blockIdx.x*blockDim.x + threadIdx.x;
    if (i < n) out[i] = tf32r(in[i]);
}

/* RMSNorm; output rounded to tf32 grid (feeds GEMM A)                */
__global__ void rmsnorm_kernel(const float* __restrict__ x,
                               const float* __restrict__ w,
                               float* __restrict__ y) {
    int row = blockIdx.x, t = threadIdx.x;
    const float* xr = x + (size_t)row*ND;
    float s = 0.f;
    #pragma unroll
    for (int i = t; i < ND; i += 256) { float v = xr[i]; s += v*v; }
    __shared__ float red[256];
    red[t] = s; __syncthreads();
    for (int st = 128; st > 0; st >>= 1) {
        if (t < st) red[t] += red[t+st];
        __syncthreads();
    }
    float r = rsqrtf(red[0]*(1.f/ND) + 1e-5f);
    float* yr = y + (size_t)row*ND;
    #pragma unroll
    for (int i = t; i < ND; i += 256) yr[i] = tf32r(xr[i]*w[i]*r);
}

/* fused RoPE over all segments of one layer:
   q   (NS rows,  pos = NM + r)           [optional]
   k   (NKV rows, pos = r)
   qbf (2*NM rows, pos = NKV + (r&127))
   kbf (2*NM rows, pos = NKV + (r&127))                               */
__global__ void rope_all_kernel(float* __restrict__ q,
                                float* __restrict__ k,
                                float* __restrict__ qbf,
                                float* __restrict__ kbf,
                                int inc_q) {
    int idx = blockIdx.x*blockDim.x + threadIdx.x;
    int qrows = inc_q ? NS : 0;
    int total = qrows + NKV + 512;
    if (idx >= total*512) return;
    int r = idx >> 9;
    int t = idx & 511;
    int j = t & 31, h = t >> 5;
    float* base; int pos;
    if (r < qrows) { base = q; pos = NM + r; }
    else {
        int rr = r - qrows;
        if (rr < NKV) { base = k; pos = rr; r = rr; }
        else {
            rr -= NKV;
            if (rr < 256) { base = qbf; pos = NKV + (rr & 127); r = rr; }
            else          { rr -= 256; base = kbf; pos = NKV + (rr & 127); r = rr; }
        }
    }
    float c = g_cs[pos*32 + j], s = g_sn[pos*32 + j];
    float* p = base + (size_t)r*ND + h*64;
    float x1 = p[j], x2 = p[j+32];
    p[j]    = x1*c - x2*s;
    p[j+32] = x2*c + x1*s;
}

/* ------------------------------------------------------------------ */
/* tf32 WMMA GEMM v2: 128x128 CTA tile, 4 warps (64x64 each), BK=32,  */
/* 3-stage cp.async. A pre-rounded to tf32 (exact truncation); B      */
/* RN-converted in the fragment.                                      */
/* ------------------------------------------------------------------ */
struct GemmDesc  { const float* A; const float* B; float* C; };
struct GemmBatch { GemmDesc d[8]; };

typedef wmma::fragment<wmma::matrix_a, 16,16,8, wmma::precision::tf32, wmma::row_major> FragA;
typedef wmma::fragment<wmma::matrix_b, 16,16,8, wmma::precision::tf32, wmma::row_major> FragB;
typedef wmma::fragment<wmma::matrix_b, 16,16,8, wmma::precision::tf32, wmma::col_major> FragBc;
typedef wmma::fragment<wmma::accumulator, 16,16,8, float> FragC;

#define GSTAGES 3
#define A_STRIDE 36
#define B_STRIDE 132
#define A_TILE_F (128*A_STRIDE)           /* 4608 floats */
#define B_TILE_F (32*B_STRIDE)            /* 4224 floats */
#define GSMEM_BYTES (GSTAGES*(A_TILE_F + B_TILE_F)*4)   /* 105984 */

__device__ __forceinline__ void cp16(uint32_t dst, const void* src) {
    asm volatile("cp.async.cg.shared.global [%0], [%1], 16;" :: "r"(dst), "l"(src));
}
__device__ __forceinline__ void cp_commit() {
    asm volatile("cp.async.commit_group;");
}
__device__ __forceinline__ void cp_wait1() {
    asm volatile("cp.async.wait_group 1;");
}

__device__ __forceinline__ void gemm_core(const float* __restrict__ A,
                                          const float* __restrict__ B,
                                          float* __restrict__ C,
                                          int N, int K, int beta) {
    extern __shared__ float sm[];
    float* Asm = sm;                               /* [3][128][36] */
    float* Bsm = sm + GSTAGES*A_TILE_F;            /* [3][32][132] */

    int tid = threadIdx.x;
    int wid = tid >> 5;
    int wy  = wid >> 1;
    int wx  = wid & 1;
    size_t brow = (size_t)blockIdx.y * 128;
    size_t bcol = (size_t)blockIdx.x * 128;

    int ar = tid >> 3, ac = (tid & 7) << 2;
    int br = tid >> 5, bc = (tid & 31) << 2;

    const float* Ag = A + (brow + ar)*K + ac;
    const float* Bg = B + (size_t)br*N + bcol + bc;

    uint32_t sA = (uint32_t)__cvta_generic_to_shared(Asm + ar*A_STRIDE + ac);
    uint32_t sB = (uint32_t)__cvta_generic_to_shared(Bsm + br*B_STRIDE + bc);
    const uint32_t aStageB = A_TILE_F*4;
    const uint32_t bStageB = B_TILE_F*4;

    int nt = K >> 5;

    #pragma unroll
    for (int s = 0; s < 2; s++) {
        int k0 = s << 5;
        #pragma unroll
        for (int i = 0; i < 8; i++)
            cp16(sA + s*aStageB + i*16*A_STRIDE*4, Ag + k0 + (size_t)(16*i)*K);
        #pragma unroll
        for (int i = 0; i < 8; i++)
            cp16(sB + s*bStageB + i*4*B_STRIDE*4, Bg + (size_t)(k0 + 4*i)*N);
        cp_commit();
    }

    FragC acc[4][4];
    #pragma unroll
    for (int mi = 0; mi < 4; mi++)
        #pragma unroll
        for (int ni = 0; ni < 4; ni++)
            wmma::fill_fragment(acc[mi][ni], 0.f);

    int st = 0, ld = 2;
    for (int kt = 0; kt < nt; kt++) {
        cp_wait1();
        __syncthreads();
        if (kt + 2 < nt) {
            int k0 = (kt + 2) << 5;
            #pragma unroll
            for (int i = 0; i < 8; i++)
                cp16(sA + ld*aStageB + i*16*A_STRIDE*4, Ag + k0 + (size_t)(16*i)*K);
            #pragma unroll
            for (int i = 0; i < 8; i++)
                cp16(sB + ld*bStageB + i*4*B_STRIDE*4, Bg + (size_t)(k0 + 4*i)*N);
        }
        cp_commit();

        const float* Ast = Asm + st*A_TILE_F;
        const float* Bst = Bsm + st*B_TILE_F;
        #pragma unroll
        for (int kk = 0; kk < 32; kk += 8) {
            FragA af[4];
            FragB bf[4];
            #pragma unroll
            for (int mi = 0; mi < 4; mi++)
                wmma::load_matrix_sync(af[mi], Ast + (wy*64 + mi*16)*A_STRIDE + kk, A_STRIDE);
            #pragma unroll
            for (int ni = 0; ni < 4; ni++) {
                wmma::load_matrix_sync(bf[ni], Bst + kk*B_STRIDE + wx*64 + ni*16, B_STRIDE);
                #pragma unroll
                for (int t = 0; t < bf[ni].num_elements; t++)
                    bf[ni].x[t] = wmma::__float_to_tf32(bf[ni].x[t]);
            }
            #pragma unroll
            for (int mi = 0; mi < 4; mi++)
                #pragma unroll
                for (int ni = 0; ni < 4; ni++)
                    wmma::mma_sync(acc[mi][ni], af[mi], bf[ni], acc[mi][ni]);
        }
        st++; if (st == GSTAGES) st = 0;
        ld++; if (ld == GSTAGES) ld = 0;
    }

    #pragma unroll
    for (int mi = 0; mi < 4; mi++)
        #pragma unroll
        for (int ni = 0; ni < 4; ni++) {
            float* cp = C + (brow + wy*64 + mi*16)*N + bcol + wx*64 + ni*16;
            if (beta) {
                FragC cf;
                wmma::load_matrix_sync(cf, cp, N, wmma::mem_row_major);
                #pragma unroll
                for (int t = 0; t < cf.num_elements; t++)
                    acc[mi][ni].x[t] += cf.x[t];
            }
            wmma::store_matrix_sync(cp, acc[mi][ni], N, wmma::mem_row_major);
        }
}

__global__ __launch_bounds__(128, 2)
void sgemm_kernel(const float* A, const float* B, float* C, int N, int K, int beta) {
    gemm_core(A, B, C, N, K, beta);
}
__global__ __launch_bounds__(128, 2)
void sgemm_batch_kernel(GemmBatch bat, int N, int K, int beta) {
    GemmDesc dsc = bat.d[blockIdx.z];
    gemm_core(dsc.A, dsc.B, dsc.C, N, K, beta);
}

/* ------------------------------------------------------------------ */
/* WMMA flash attention: 64 queries x one head per CTA, 4 warps.      */
/* QK^T and PV via m16n16k8 tf32 MMA with 3-term hi/lo split          */
/* (fp32-grade accuracy). All k-tiles are exactly 64 rows; only the   */
/* last tile is mask-triangular. O tile in smem, rescaled per row.    */
/* smem: Q,K,V,S,O (64x68 each) + m,l  = 87.5KB -> 2 CTAs/SM          */
/* ------------------------------------------------------------------ */
#define AT_STRIDE 68
#define AT_TILE   (64*AT_STRIDE)
#define ATTN_SMEM ((5*AT_TILE + 128)*4)

template<class F>
__device__ __forceinline__ void split_frag(const F& raw, F& hi, F& lo) {
    #pragma unroll
    for (int t = 0; t < raw.num_elements; t++) {
        float x = raw.x[t];
        float h = wmma::__float_to_tf32(x);
        hi.x[t] = h;
        lo.x[t] = wmma::__float_to_tf32(x - h);
    }
}

__global__ __launch_bounds__(128)
void attn_kernel(const float* Q, size_t qz,
                 const float* K1, const float* V1, int n1,
                 const float* K2, const float* V2, size_t kz, int n2,
                 float* O, size_t oz, int coff) {
    extern __shared__ float sm[];
    float* Qs = sm;
    float* Ks = sm +   AT_TILE;
    float* Vs = sm + 2*AT_TILE;
    float* Ss = sm + 3*AT_TILE;
    float* Os = sm + 4*AT_TILE;
    float* mrow = sm + 5*AT_TILE;
    float* lrow = mrow + 64;

    int z = blockIdx.z;
    Q  += (size_t)z*qz;  K2 += (size_t)z*kz;
    V2 += (size_t)z*kz;  O  += (size_t)z*oz;
    int h  = blockIdx.y;
    int q0 = blockIdx.x*64;
    int tid = threadIdx.x;
    int wid = tid >> 5;
    int r2  = tid >> 1;        /* row 0..63   */
    int hf  = tid & 1;         /* half of row */

    /* load Q tile, zero O, init m/l */
    {
        const float4* qp = (const float4*)(Q + (size_t)(q0+r2)*ND + h*64 + hf*32);
        float4* qd = (float4*)(Qs + r2*AT_STRIDE + hf*32);
        float4* od = (float4*)(Os + r2*AT_STRIDE + hf*32);
        float4 z4 = make_float4(0.f,0.f,0.f,0.f);
        #pragma unroll
        for (int i = 0; i < 8; i++) { qd[i] = qp[i]; od[i] = z4; }
        if (tid < 64) { mrow[tid] = -1e30f; lrow[tid] = 0.f; }
    }
    __syncthreads();

    int ntot = n1 + n2;
    int kmax = ntot;
    int vis  = q0 + 64 + coff;
    if (vis < kmax) kmax = vis;

    for (int t0 = 0; t0 < kmax; t0 += 64) {
        /* load K,V tile (always full 64 rows) */
        {
            int kk = t0 + r2;
            const float *kp, *vp;
            if (kk < n1) { kp = K1 + (size_t)kk*ND;      vp = V1 + (size_t)kk*ND; }
            else         { kp = K2 + (size_t)(kk-n1)*ND; vp = V2 + (size_t)(kk-n1)*ND; }
            kp += h*64 + hf*32; vp += h*64 + hf*32;
            float4* kd = (float4*)(Ks + r2*AT_STRIDE + hf*32);
            float4* vd = (float4*)(Vs + r2*AT_STRIDE + hf*32);
            #pragma unroll
            for (int i = 0; i < 8; i++) {
                kd[i] = ((const float4*)kp)[i];
                vd[i] = ((const float4*)vp)[i];
            }
        }
        __syncthreads();

        /* S = Q @ K^T (3x tf32), warp -> 16-row strip */
        {
            FragC sacc[4];
            #pragma unroll
            for (int ni = 0; ni < 4; ni++) wmma::fill_fragment(sacc[ni], 0.f);
            #pragma unroll
            for (int ks = 0; ks < 8; ks++) {
                FragA araw, ah, al;
                wmma::load_matrix_sync(araw, Qs + (wid*16)*AT_STRIDE + ks*8, AT_STRIDE);
                split_frag(araw, ah, al);
                #pragma unroll
                for (int ni = 0; ni < 4; ni++) {
                    FragBc braw, bh, bl;
                    wmma::load_matrix_sync(braw, Ks + (ni*16)*AT_STRIDE + ks*8, AT_STRIDE);
                    split_frag(braw, bh, bl);
                    wmma::mma_sync(sacc[ni], ah, bh, sacc[ni]);
                    wmma::mma_sync(sacc[ni], ah, bl, sacc[ni]);
                    wmma::mma_sync(sacc[ni], al, bh, sacc[ni]);
                }
            }
            #pragma unroll
            for (int ni = 0; ni < 4; ni++)
                wmma::store_matrix_sync(Ss + (wid*16)*AT_STRIDE + ni*16, sacc[ni],
                                        AT_STRIDE, wmma::mem_row_major);
        }
        __syncthreads();

        /* online softmax: 2 threads per row */
        {
            int moff = q0 + coff - t0;
            int jmax = r2 + moff; if (jmax > 63) jmax = 63;
            float mold = mrow[r2];
            float* srow = Ss + r2*AT_STRIDE + hf*32;
            float sv[32];
            float tmax = -1e30f;
            #pragma unroll
            for (int c = 0; c < 32; c++) {
                int cc = hf*32 + c;
                float s = srow[c]*0.125f;
                sv[c] = s;
                if (cc <= jmax) tmax = fmaxf(tmax, s);
            }
            tmax = fmaxf(tmax, __shfl_xor_sync(0xffffffffu, tmax, 1));
            float mnew = fmaxf(mold, tmax);
            float corr = expf(mold - mnew);
            float psum = 0.f;
            #pragma unroll
            for (int c = 0; c < 32; c++) {
                int cc = hf*32 + c;
                float p = (cc <= jmax) ? expf(sv[c] - mnew) : 0.f;
                srow[c] = p;
                psum += p;
            }
            psum += __shfl_xor_sync(0xffffffffu, psum, 1);
            if (hf == 0) { mrow[r2] = mnew; lrow[r2] = lrow[r2]*corr + psum; }
            float* orow = Os + r2*AT_STRIDE + hf*32;
            #pragma unroll
            for (int c = 0; c < 32; c++) orow[c] *= corr;
        }
        __syncthreads();

        /* O += P @ V (3x tf32) */
        {
            FragC oacc[4];
            #pragma unroll
            for (int ni = 0; ni < 4; ni++)
                wmma::load_matrix_sync(oacc[ni], Os + (wid*16)*AT_STRIDE + ni*16,
                                       AT_STRIDE, wmma::mem_row_major);
            #pragma unroll
            for (int ks = 0; ks < 8; ks++) {
                FragA praw, ph, pl;
                wmma::load_matrix_sync(praw, Ss + (wid*16)*AT_STRIDE + ks*8, AT_STRIDE);
                split_frag(praw, ph, pl);
                #pragma unroll
                for (int ni = 0; ni < 4; ni++) {
                    FragB vraw, vh, vl;
                    wmma::load_matrix_sync(vraw, Vs + (ks*8)*AT_STRIDE + ni*16, AT_STRIDE);
                    split_frag(vraw, vh, vl);
                    wmma::mma_sync(oacc[ni], ph, vh, oacc[ni]);
                    wmma::mma_sync(oacc[ni], ph, vl, oacc[ni]);
                    wmma::mma_sync(oacc[ni], pl, vh, oacc[ni]);
                }
            }
            #pragma unroll
            for (int ni = 0; ni < 4; ni++)
                wmma::store_matrix_sync(Os + (wid*16)*AT_STRIDE + ni*16, oacc[ni],
                                        AT_STRIDE, wmma::mem_row_major);
        }
        __syncthreads();
    }

    /* epilogue */
    {
        float invl = 1.f/lrow[r2];
        const float* orow = Os + r2*AT_STRIDE + hf*32;
        float* op = O + (size_t)(q0+r2)*ND + h*64 + hf*32;
        #pragma unroll
        for (int c = 0; c < 32; c++) op[c] = tf32r(orow[c]*invl);
    }
}

/* ------------------------------------------------------------------ */
__global__ void silumul_kernel(float* __restrict__ a, const float* __restrict__ b, int n) {
    int i = blockIdx.x*blockDim.x + threadIdx.x;
    if (i >= n) return;
    float g = a[i];
    a[i] = tf32r((g / (1.f + expf(-g))) * b[i]);
}

__global__ void gate_out_kernel(const float* __restrict__ mem,
                                const float* __restrict__ inj,
                                const float* __restrict__ fg,
                                float* __restrict__ out, int n) {
    int i = blockIdx.x*blockDim.x + threadIdx.x;
    if (i >= n) return;
    float g = 1.f / (1.f + expf(-fg[i]));
    out[i] = mem[i]*g + inj[i]*(1.f - g);
}

/* ================================================================== */
extern "C" void kernel_launch(void* const* d_in, const int* in_sizes, int n_in,
                              void* d_out, int out_size) {
    const int*   ids    = (const int*)d_in[0];
    const float* memory = (const float*)d_in[1];
    const float* beacon = (const float*)d_in[2];
    const float* forget = (const float*)d_in[3];
    const float* embed  = (const float*)d_in[4];
    const float* ln1    = (const float*)d_in[5];
    const float* ln2    = (const float*)d_in[6];
    const float* Wq  = (const float*)d_in[7];
    const float* Wk  = (const float*)d_in[8];
    const float* Wv  = (const float*)d_in[9];
    const float* Wo  = (const float*)d_in[10];
    const float* mWk = (const float*)d_in[11];
    const float* mWv = (const float*)d_in[12];
    const float* bWq = (const float*)d_in[13];
    const float* bWk = (const float*)d_in[14];
    const float* bWv = (const float*)d_in[15];
    const float* fWq = (const float*)d_in[16];
    const float* fWk = (const float*)d_in[17];
    const float* fWv = (const float*)d_in[18];
    const float* Wg  = (const float*)d_in[19];
    const float* Wu  = (const float*)d_in[20];
    const float* Wd  = (const float*)d_in[21];

    static int attr_set = 0;
    if (!attr_set) {
        cudaFuncSetAttribute(sgemm_kernel, cudaFuncAttributeMaxDynamicSharedMemorySize, GSMEM_BYTES);
        cudaFuncSetAttribute(sgemm_batch_kernel, cudaFuncAttributeMaxDynamicSharedMemorySize, GSMEM_BYTES);
        cudaFuncSetAttribute(attn_kernel, cudaFuncAttributeMaxDynamicSharedMemorySize, ATTN_SMEM);
        attr_set = 1;
    }

    float *cat,*x,*q,*k,*v,*qbf,*kbf,*vbf,*att,*m1,*m2,*inj,*fg,*memr;
    cudaGetSymbolAddress((void**)&cat, g_cat);
    cudaGetSymbolAddress((void**)&x,   g_x);
    cudaGetSymbolAddress((void**)&q,   g_q);
    cudaGetSymbolAddress((void**)&k,   g_k);
    cudaGetSymbolAddress((void**)&v,   g_v);
    cudaGetSymbolAddress((void**)&qbf, g_qbf);
    cudaGetSymbolAddress((void**)&kbf, g_kbf);
    cudaGetSymbolAddress((void**)&vbf, g_vbf);
    cudaGetSymbolAddress((void**)&att, g_att);
    cudaGetSymbolAddress((void**)&m1,  g_m1);
    cudaGetSymbolAddress((void**)&m2,  g_m2);
    cudaGetSymbolAddress((void**)&inj, g_inj);
    cudaGetSymbolAddress((void**)&fg,  g_fg);
    cudaGetSymbolAddress((void**)&memr,g_memr);

    const size_t RECB = (size_t)NM*ND*sizeof(float);

    init_tables_kernel<<<(NPOS*32+255)/256, 256>>>();
    gather_kernel<<<NS, 256>>>(ids, embed, cat);
    round_kernel<<<(7*NM*ND)/256, 256>>>(memory, memr, 7*NM*ND);
    cudaMemcpyAsync(cat + (size_t)NS*ND,      beacon, RECB, cudaMemcpyDeviceToDevice, 0);
    cudaMemcpyAsync(cat + (size_t)(NS+NM)*ND, forget, RECB, cudaMemcpyDeviceToDevice, 0);

    for (int l = 0; l < 7; l++) {
        const size_t wdd = (size_t)ND*ND;
        const float* Wq_l  = Wq  + l*wdd;  const float* Wk_l  = Wk  + l*wdd;
        const float* Wv_l  = Wv  + l*wdd;  const float* Wo_l  = Wo  + l*wdd;
        const float* mWk_l = mWk + l*wdd;  const float* mWv_l = mWv + l*wdd;
        const float* bWq_l = bWq + l*wdd;  const float* bWk_l = bWk + l*wdd;
        const float* bWv_l = bWv + l*wdd;  const float* fWq_l = fWq + l*wdd;
        const float* fWk_l = fWk + l*wdd;  const float* fWv_l = fWv + l*wdd;
        const float* Wg_l  = Wg + (size_t)l*ND*NF;
        const float* Wu_l  = Wu + (size_t)l*ND*NF;
        const float* Wd_l  = Wd + (size_t)l*NF*ND;
        const float* mem_l = memr + (size_t)l*NM*ND;
        const bool last = (l == 6);

        cudaMemcpyAsync(inj + (size_t)l*NM*ND, cat + (size_t)NS*ND,      RECB, cudaMemcpyDeviceToDevice, 0);
        cudaMemcpyAsync(fg  + (size_t)l*NM*ND, cat + (size_t)(NS+NM)*ND, RECB, cudaMemcpyDeviceToDevice, 0);

        rmsnorm_kernel<<<NCAT, 256>>>(cat, ln1 + (size_t)l*ND, x);

        {
            GemmBatch ba; int nb = 0;
            if (!last) { ba.d[nb].A = x; ba.d[nb].B = Wq_l; ba.d[nb].C = q; nb++; }
            ba.d[nb].A = x; ba.d[nb].B = Wk_l; ba.d[nb].C = k + (size_t)NM*ND; nb++;
            ba.d[nb].A = x; ba.d[nb].B = Wv_l; ba.d[nb].C = v + (size_t)NM*ND; nb++;
            sgemm_batch_kernel<<<dim3(8, 8, nb), 128, GSMEM_BYTES>>>(ba, ND, ND, 0);
        }
        {
            GemmBatch sa;
            const float* bx = x + (size_t)NS*ND;
            const float* fx = x + (size_t)(NS+NM)*ND;
            sa.d[0].A = mem_l; sa.d[0].B = mWk_l; sa.d[0].C = k;
            sa.d[1].A = mem_l; sa.d[1].B = mWv_l; sa.d[1].C = v;
            sa.d[2].A = bx;    sa.d[2].B = bWq_l; sa.d[2].C = qbf;
            sa.d[3].A = bx;    sa.d[3].B = bWk_l; sa.d[3].C = kbf;
            sa.d[4].A = bx;    sa.d[4].B = bWv_l; sa.d[4].C = vbf;
            sa.d[5].A = fx;    sa.d[5].B = fWq_l; sa.d[5].C = qbf + (size_t)NM*ND;
            sa.d[6].A = fx;    sa.d[6].B = fWk_l; sa.d[6].C = kbf + (size_t)NM*ND;
            sa.d[7].A = fx;    sa.d[7].B = fWv_l; sa.d[7].C = vbf + (size_t)NM*ND;
            sgemm_batch_kernel<<<dim3(8, 1, 8), 128, GSMEM_BYTES>>>(sa, ND, ND, 0);
        }

        {
            int inc_q = last ? 0 : 1;
            int rows = (inc_q ? NS : 0) + NKV + 512;
            rope_all_kernel<<<(rows*512 + 255)/256, 256>>>(q, k, qbf, kbf, inc_q);
        }

        if (!last)
            attn_kernel<<<dim3(NS/64, NH, 1), 128, ATTN_SMEM>>>(q, 0, k, v, NKV,
                                                    k, v, 0, 0,
                                                    att, 0, NM);
        attn_kernel<<<dim3(NM/64, NH, 2), 128, ATTN_SMEM>>>(qbf, (size_t)NM*ND, k, v, NKV,
                                                kbf, vbf, (size_t)NM*ND, NM,
                                                att + (size_t)NS*ND, (size_t)NM*ND, NKV);

        if (!last)
            sgemm_kernel<<<dim3(8, 10), 128, GSMEM_BYTES>>>(att, Wo_l, cat, ND, ND, 1);
        else
            sgemm_kernel<<<dim3(8, 2), 128, GSMEM_BYTES>>>(att + (size_t)NS*ND, Wo_l,
                                              cat + (size_t)NS*ND, ND, ND, 1);

        int rows = last ? 2*NM : NCAT;
        size_t off = last ? (size_t)NS*ND : 0;
        rmsnorm_kernel<<<rows, 256>>>(cat + off, ln2 + (size_t)l*ND, x + off);
        {
            GemmBatch ga;
            ga.d[0].A = x + off; ga.d[0].B = Wg_l; ga.d[0].C = m1;
            ga.d[1].A = x + off; ga.d[1].B = Wu_l; ga.d[1].C = m2;
            sgemm_batch_kernel<<<dim3(NF/128, rows/128, 2), 128, GSMEM_BYTES>>>(ga, NF, ND, 0);
        }
        silumul_kernel<<<(rows*NF)/256, 256>>>(m1, m2, rows*NF);
        sgemm_kernel<<<dim3(8, rows/128), 128, GSMEM_BYTES>>>(m1, Wd_l, cat + off, ND, NF, 1);
    }

    cudaMemcpyAsync(inj + (size_t)7*NM*ND, cat + (size_t)NS*ND,      RECB, cudaMemcpyDeviceToDevice, 0);
    cudaMemcpyAsync(fg  + (size_t)7*NM*ND, cat + (size_t)(NS+NM)*ND, RECB, cudaMemcpyDeviceToDevice, 0);

    gate_out_kernel<<<(NL*NM*ND)/256, 256>>>(memory, inj, fg, (float*)d_out, NL*NM*ND);
}

// round 11
// speedup vs baseline: 2.1195x; 1.0635x over previous
#include <cuda_runtime.h>
#include <math.h>
#include <mma.h>
#include <stdint.h>

using namespace nvcuda;

#define NS   1024
#define NM   128
#define ND   1024
#define NH   16
#define NHD  64
#define NF   2048
#define NL   8
#define NCAT 1280   /* S + 2M */
#define NKV  1152   /* M + S  */
#define NPOS 1280

/* ------------------------------------------------------------------ */
/* scratch (static device arrays; no allocation allowed)              */
/* ------------------------------------------------------------------ */
__device__ float g_cat[NCAT*ND];
__device__ float g_x  [NCAT*ND];
__device__ float g_q  [NS*ND];
__device__ float g_k  [NKV*ND];
__device__ float g_v  [NKV*ND];
__device__ float g_qbf[2*NM*ND];
__device__ float g_kbf[2*NM*ND];
__device__ float g_vbf[2*NM*ND];
__device__ float g_att[NCAT*ND];
__device__ float g_m1 [NCAT*NF];
__device__ float g_m2 [NCAT*NF];
__device__ float g_inj[NL*NM*ND];
__device__ float g_fg [NL*NM*ND];
__device__ float g_memr[7*NM*ND];
__device__ float g_cs [NPOS*32];
__device__ float g_sn [NPOS*32];

/* pre-rounded (tf32-grid) weights, 7 layers each */
#define WDD (7*ND*ND)
#define WDF (7*ND*NF)
#define WFD (7*NF*ND)
__device__ float g_wq [WDD]; __device__ float g_wk [WDD];
__device__ float g_wv [WDD]; __device__ float g_wo [WDD];
__device__ float g_mwk[WDD]; __device__ float g_mwv[WDD];
__device__ float g_bwq[WDD]; __device__ float g_bwk[WDD];
__device__ float g_bwv[WDD]; __device__ float g_fwq[WDD];
__device__ float g_fwk[WDD]; __device__ float g_fwv[WDD];
__device__ float g_wg [WDF]; __device__ float g_wu [WDF];
__device__ float g_wd [WFD];

/* round-to-nearest onto the tf32 grid (so HW truncation is exact)    */
__device__ __forceinline__ float tf32r(float x) {
    unsigned u = __float_as_uint(x), r;
    asm("cvt.rna.tf32.f32 %0, %1;" : "=r"(r) : "r"(u));
    return __uint_as_float(r);
}

/* ------------------------------------------------------------------ */
__global__ void init_tables_kernel() {
    int idx = blockIdx.x*blockDim.x + threadIdx.x;
    if (idx >= NPOS*32) return;
    int pos = idx >> 5, j = idx & 31;
    double inv = exp(-((double)(2*j)/64.0) * log(10000.0));
    double a = (double)pos * inv;
    g_cs[idx] = (float)cos(a);
    g_sn[idx] = (float)sin(a);
}

__global__ void gather_kernel(const int* __restrict__ ids,
                              const float* __restrict__ embed,
                              float* __restrict__ out) {
    int row = blockIdx.x;
    int id  = ids[row];
    const float4* src = (const float4*)(embed + (size_t)id*ND);
    float4* dst = (float4*)(out + (size_t)row*ND);
    dst[threadIdx.x] = src[threadIdx.x];
}

/* batched tf32-grid rounding of all weight tensors                   */
struct RoundJob  { const float* s; float* d; int n4; };
struct RoundJobs { RoundJob j[16]; };

__global__ void round_w_kernel(RoundJobs js) {
    RoundJob jb = js.j[blockIdx.y];
    const float4* s = (const float4*)jb.s;
    float4* d = (float4*)jb.d;
    int stride = gridDim.x*blockDim.x;
    for (int i = blockIdx.x*blockDim.x + threadIdx.x; i < jb.n4; i += stride) {
        float4 v = s[i];
        v.x = tf32r(v.x); v.y = tf32r(v.y);
        v.z = tf32r(v.z); v.w = tf32r(v.w);
        d[i] = v;
    }
}

/* RMSNorm; output rounded to tf32 grid. Optionally records the raw   */
/* beacon/forget rows (layer-entry snapshot) into inj/fg.             */
__global__ void rmsnorm_kernel(const float* __restrict__ x,
                               const float* __restrict__ w,
                               float* __restrict__ y,
                               float* __restrict__ rec_inj,
                               float* __restrict__ rec_fg) {
    int row = blockIdx.x, t = threadIdx.x;
    const float* xr = x + (size_t)row*ND;
    float s = 0.f;
    #pragma unroll
    for (int i = t; i < ND; i += 256) { float v = xr[i]; s += v*v; }
    __shared__ float red[256];
    red[t] = s; __syncthreads();
    for (int st = 128; st > 0; st >>= 1) {
        if (t < st) red[t] += red[t+st];
        __syncthreads();
    }
    float r = rsqrtf(red[0]*(1.f/ND) + 1e-5f);
    float* yr = y + (size_t)row*ND;
    float* dst = 0;
    if (rec_inj && row >= NS)
        dst = (row < NS+NM) ? rec_inj + (size_t)(row-NS)*ND
                            : rec_fg  + (size_t)(row-NS-NM)*ND;
    #pragma unroll
    for (int i = t; i < ND; i += 256) {
        float v = xr[i];
        if (dst) dst[i] = v;
        yr[i] = tf32r(v*w[i]*r);
    }
}

/* fused RoPE over all segments of one layer                          */
__global__ void rope_all_kernel(float* __restrict__ q,
                                float* __restrict__ k,
                                float* __restrict__ qbf,
                                float* __restrict__ kbf,
                                int inc_q) {
    int idx = blockIdx.x*blockDim.x + threadIdx.x;
    int qrows = inc_q ? NS : 0;
    int total = qrows + NKV + 512;
    if (idx >= total*512) return;
    int r = idx >> 9;
    int t = idx & 511;
    int j = t & 31, h = t >> 5;
    float* base; int pos;
    if (r < qrows) { base = q; pos = NM + r; }
    else {
        int rr = r - qrows;
        if (rr < NKV) { base = k; pos = rr; r = rr; }
        else {
            rr -= NKV;
            if (rr < 256) { base = qbf; pos = NKV + (rr & 127); r = rr; }
            else          { rr -= 256; base = kbf; pos = NKV + (rr & 127); r = rr; }
        }
    }
    float c = g_cs[pos*32 + j], s = g_sn[pos*32 + j];
    float* p = base + (size_t)r*ND + h*64;
    float x1 = p[j], x2 = p[j+32];
    p[j]    = x1*c - x2*s;
    p[j+32] = x2*c + x1*s;
}

/* ------------------------------------------------------------------ */
/* tf32 WMMA GEMM: 128x128 CTA tile, 4 warps (64x64), BK=32, 3-stage  */
/* cp.async. A and B both pre-rounded to the tf32 grid -> zero cvt.   */
/* ------------------------------------------------------------------ */
struct GemmDesc  { const float* A; const float* B; float* C; int nrb; };
struct GemmBatch { GemmDesc d[12]; };

typedef wmma::fragment<wmma::matrix_a, 16,16,8, wmma::precision::tf32, wmma::row_major> FragA;
typedef wmma::fragment<wmma::matrix_b, 16,16,8, wmma::precision::tf32, wmma::row_major> FragB;
typedef wmma::fragment<wmma::matrix_b, 16,16,8, wmma::precision::tf32, wmma::col_major> FragBc;
typedef wmma::fragment<wmma::accumulator, 16,16,8, float> FragC;

#define GSTAGES 3
#define A_STRIDE 36
#define B_STRIDE 132
#define A_TILE_F (128*A_STRIDE)
#define B_TILE_F (32*B_STRIDE)
#define GSMEM_BYTES (GSTAGES*(A_TILE_F + B_TILE_F)*4)

__device__ __forceinline__ void cp16(uint32_t dst, const void* src) {
    asm volatile("cp.async.cg.shared.global [%0], [%1], 16;" :: "r"(dst), "l"(src));
}
__device__ __forceinline__ void cp_commit() {
    asm volatile("cp.async.commit_group;");
}
__device__ __forceinline__ void cp_wait1() {
    asm volatile("cp.async.wait_group 1;");
}

__device__ __forceinline__ void gemm_core(const float* __restrict__ A,
                                          const float* __restrict__ B,
                                          float* __restrict__ C,
                                          int N, int K, int beta) {
    extern __shared__ float sm[];
    float* Asm = sm;
    float* Bsm = sm + GSTAGES*A_TILE_F;

    int tid = threadIdx.x;
    int wid = tid >> 5;
    int wy  = wid >> 1;
    int wx  = wid & 1;
    size_t brow = (size_t)blockIdx.y * 128;
    size_t bcol = (size_t)blockIdx.x * 128;

    int ar = tid >> 3, ac = (tid & 7) << 2;
    int br = tid >> 5, bc = (tid & 31) << 2;

    const float* Ag = A + (brow + ar)*K + ac;
    const float* Bg = B + (size_t)br*N + bcol + bc;

    uint32_t sA = (uint32_t)__cvta_generic_to_shared(Asm + ar*A_STRIDE + ac);
    uint32_t sB = (uint32_t)__cvta_generic_to_shared(Bsm + br*B_STRIDE + bc);
    const uint32_t aStageB = A_TILE_F*4;
    const uint32_t bStageB = B_TILE_F*4;

    int nt = K >> 5;

    #pragma unroll
    for (int s = 0; s < 2; s++) {
        int k0 = s << 5;
        #pragma unroll
        for (int i = 0; i < 8; i++)
            cp16(sA + s*aStageB + i*16*A_STRIDE*4, Ag + k0 + (size_t)(16*i)*K);
        #pragma unroll
        for (int i = 0; i < 8; i++)
            cp16(sB + s*bStageB + i*4*B_STRIDE*4, Bg + (size_t)(k0 + 4*i)*N);
        cp_commit();
    }

    FragC acc[4][4];
    #pragma unroll
    for (int mi = 0; mi < 4; mi++)
        #pragma unroll
        for (int ni = 0; ni < 4; ni++)
            wmma::fill_fragment(acc[mi][ni], 0.f);

    int st = 0, ld = 2;
    for (int kt = 0; kt < nt; kt++) {
        cp_wait1();
        __syncthreads();
        if (kt + 2 < nt) {
            int k0 = (kt + 2) << 5;
            #pragma unroll
            for (int i = 0; i < 8; i++)
                cp16(sA + ld*aStageB + i*16*A_STRIDE*4, Ag + k0 + (size_t)(16*i)*K);
            #pragma unroll
            for (int i = 0; i < 8; i++)
                cp16(sB + ld*bStageB + i*4*B_STRIDE*4, Bg + (size_t)(k0 + 4*i)*N);
        }
        cp_commit();

        const float* Ast = Asm + st*A_TILE_F;
        const float* Bst = Bsm + st*B_TILE_F;
        #pragma unroll
        for (int kk = 0; kk < 32; kk += 8) {
            FragA af[4];
            FragB bf[4];
            #pragma unroll
            for (int mi = 0; mi < 4; mi++)
                wmma::load_matrix_sync(af[mi], Ast + (wy*64 + mi*16)*A_STRIDE + kk, A_STRIDE);
            #pragma unroll
            for (int ni = 0; ni < 4; ni++)
                wmma::load_matrix_sync(bf[ni], Bst + kk*B_STRIDE + wx*64 + ni*16, B_STRIDE);
            #pragma unroll
            for (int mi = 0; mi < 4; mi++)
                #pragma unroll
                for (int ni = 0; ni < 4; ni++)
                    wmma::mma_sync(acc[mi][ni], af[mi], bf[ni], acc[mi][ni]);
        }
        st++; if (st == GSTAGES) st = 0;
        ld++; if (ld == GSTAGES) ld = 0;
    }

    #pragma unroll
    for (int mi = 0; mi < 4; mi++)
        #pragma unroll
        for (int ni = 0; ni < 4; ni++) {
            float* cp = C + (brow + wy*64 + mi*16)*N + bcol + wx*64 + ni*16;
            if (beta) {
                FragC cf;
                wmma::load_matrix_sync(cf, cp, N, wmma::mem_row_major);
                #pragma unroll
                for (int t = 0; t < cf.num_elements; t++)
                    acc[mi][ni].x[t] += cf.x[t];
            }
            wmma::store_matrix_sync(cp, acc[mi][ni], N, wmma::mem_row_major);
        }
}

__global__ __launch_bounds__(128, 2)
void sgemm_kernel(const float* A, const float* B, float* C, int N, int K, int beta) {
    gemm_core(A, B, C, N, K, beta);
}
__global__ __launch_bounds__(128, 2)
void sgemm_batch_kernel(GemmBatch bat, int N, int K, int beta) {
    GemmDesc dsc = bat.d[blockIdx.z];
    if ((int)blockIdx.y >= dsc.nrb) return;
    gemm_core(dsc.A, dsc.B, dsc.C, N, K, beta);
}

/* ------------------------------------------------------------------ */
/* WMMA flash attention (3x tf32 hi/lo split, fp32-grade accuracy).   */
/* ------------------------------------------------------------------ */
#define AT_STRIDE 68
#define AT_TILE   (64*AT_STRIDE)
#define ATTN_SMEM ((5*AT_TILE + 128)*4)

template<class F>
__device__ __forceinline__ void split_frag(const F& raw, F& hi, F& lo) {
    #pragma unroll
    for (int t = 0; t < raw.num_elements; t++) {
        float x = raw.x[t];
        float h = wmma::__float_to_tf32(x);
        hi.x[t] = h;
        lo.x[t] = wmma::__float_to_tf32(x - h);
    }
}

__global__ __launch_bounds__(128)
void attn_kernel(const float* Q, size_t qz,
                 const float* K1, const float* V1, int n1,
                 const float* K2, const float* V2, size_t kz, int n2,
                 float* O, size_t oz, int coff) {
    extern __shared__ float sm[];
    float* Qs = sm;
    float* Ks = sm +   AT_TILE;
    float* Vs = sm + 2*AT_TILE;
    float* Ss = sm + 3*AT_TILE;
    float* Os = sm + 4*AT_TILE;
    float* mrow = sm + 5*AT_TILE;
    float* lrow = mrow + 64;

    int z = blockIdx.z;
    Q  += (size_t)z*qz;  K2 += (size_t)z*kz;
    V2 += (size_t)z*kz;  O  += (size_t)z*oz;
    int h  = blockIdx.y;
    int q0 = blockIdx.x*64;
    int tid = threadIdx.x;
    int wid = tid >> 5;
    int r2  = tid >> 1;
    int hf  = tid & 1;

    {
        const float4* qp = (const float4*)(Q + (size_t)(q0+r2)*ND + h*64 + hf*32);
        float4* qd = (float4*)(Qs + r2*AT_STRIDE + hf*32);
        float4* od = (float4*)(Os + r2*AT_STRIDE + hf*32);
        float4 z4 = make_float4(0.f,0.f,0.f,0.f);
        #pragma unroll
        for (int i = 0; i < 8; i++) { qd[i] = qp[i]; od[i] = z4; }
        if (tid < 64) { mrow[tid] = -1e30f; lrow[tid] = 0.f; }
    }
    __syncthreads();

    int ntot = n1 + n2;
    int kmax = ntot;
    int vis  = q0 + 64 + coff;
    if (vis < kmax) kmax = vis;

    for (int t0 = 0; t0 < kmax; t0 += 64) {
        {
            int kk = t0 + r2;
            const float *kp, *vp;
            if (kk < n1) { kp = K1 + (size_t)kk*ND;      vp = V1 + (size_t)kk*ND; }
            else         { kp = K2 + (size_t)(kk-n1)*ND; vp = V2 + (size_t)(kk-n1)*ND; }
            kp += h*64 + hf*32; vp += h*64 + hf*32;
            float4* kd = (float4*)(Ks + r2*AT_STRIDE + hf*32);
            float4* vd = (float4*)(Vs + r2*AT_STRIDE + hf*32);
            #pragma unroll
            for (int i = 0; i < 8; i++) {
                kd[i] = ((const float4*)kp)[i];
                vd[i] = ((const float4*)vp)[i];
            }
        }
        __syncthreads();

        {
            FragC sacc[4];
            #pragma unroll
            for (int ni = 0; ni < 4; ni++) wmma::fill_fragment(sacc[ni], 0.f);
            #pragma unroll
            for (int ks = 0; ks < 8; ks++) {
                FragA araw, ah, al;
                wmma::load_matrix_sync(araw, Qs + (wid*16)*AT_STRIDE + ks*8, AT_STRIDE);
                split_frag(araw, ah, al);
                #pragma unroll
                for (int ni = 0; ni < 4; ni++) {
                    FragBc braw, bh, bl;
                    wmma::load_matrix_sync(braw, Ks + (ni*16)*AT_STRIDE + ks*8, AT_STRIDE);
                    split_frag(braw, bh, bl);
                    wmma::mma_sync(sacc[ni], ah, bh, sacc[ni]);
                    wmma::mma_sync(sacc[ni], ah, bl, sacc[ni]);
                    wmma::mma_sync(sacc[ni], al, bh, sacc[ni]);
                }
            }
            #pragma unroll
            for (int ni = 0; ni < 4; ni++)
                wmma::store_matrix_sync(Ss + (wid*16)*AT_STRIDE + ni*16, sacc[ni],
                                        AT_STRIDE, wmma::mem_row_major);
        }
        __syncthreads();

        {
            int moff = q0 + coff - t0;
            int jmax = r2 + moff; if (jmax > 63) jmax = 63;
            float mold = mrow[r2];
            float* srow = Ss + r2*AT_STRIDE + hf*32;
            float sv[32];
            float tmax = -1e30f;
            #pragma unroll
            for (int c = 0; c < 32; c++) {
                int cc = hf*32 + c;
                float s = srow[c]*0.125f;
                sv[c] = s;
                if (cc <= jmax) tmax = fmaxf(tmax, s);
            }
            tmax = fmaxf(tmax, __shfl_xor_sync(0xffffffffu, tmax, 1));
            float mnew = fmaxf(mold, tmax);
            float corr = expf(mold - mnew);
            float psum = 0.f;
            #pragma unroll
            for (int c = 0; c < 32; c++) {
                int cc = hf*32 + c;
                float p = (cc <= jmax) ? expf(sv[c] - mnew) : 0.f;
                srow[c] = p;
                psum += p;
            }
            psum += __shfl_xor_sync(0xffffffffu, psum, 1);
            if (hf == 0) { mrow[r2] = mnew; lrow[r2] = lrow[r2]*corr + psum; }
            float* orow = Os + r2*AT_STRIDE + hf*32;
            #pragma unroll
            for (int c = 0; c < 32; c++) orow[c] *= corr;
        }
        __syncthreads();

        {
            FragC oacc[4];
            #pragma unroll
            for (int ni = 0; ni < 4; ni++)
                wmma::load_matrix_sync(oacc[ni], Os + (wid*16)*AT_STRIDE + ni*16,
                                       AT_STRIDE, wmma::mem_row_major);
            #pragma unroll
            for (int ks = 0; ks < 8; ks++) {
                FragA praw, ph, pl;
                wmma::load_matrix_sync(praw, Ss + (wid*16)*AT_STRIDE + ks*8, AT_STRIDE);
                split_frag(praw, ph, pl);
                #pragma unroll
                for (int ni = 0; ni < 4; ni++) {
                    FragB vraw, vh, vl;
                    wmma::load_matrix_sync(vraw, Vs + (ks*8)*AT_STRIDE + ni*16, AT_STRIDE);
                    split_frag(vraw, vh, vl);
                    wmma::mma_sync(oacc[ni], ph, vh, oacc[ni]);
                    wmma::mma_sync(oacc[ni], ph, vl, oacc[ni]);
                    wmma::mma_sync(oacc[ni], pl, vh, oacc[ni]);
                }
            }
            #pragma unroll
            for (int ni = 0; ni < 4; ni++)
                wmma::store_matrix_sync(Os + (wid*16)*AT_STRIDE + ni*16, oacc[ni],
                                        AT_STRIDE, wmma::mem_row_major);
        }
        __syncthreads();
    }

    {
        float invl = 1.f/lrow[r2];
        const float* orow = Os + r2*AT_STRIDE + hf*32;
        float* op = O + (size_t)(q0+r2)*ND + h*64 + hf*32;
        #pragma unroll
        for (int c = 0; c < 32; c++) op[c] = tf32r(orow[c]*invl);
    }
}

/* ------------------------------------------------------------------ */
__global__ void silumul_kernel(float* __restrict__ a, const float* __restrict__ b, int n) {
    int i = blockIdx.x*blockDim.x + threadIdx.x;
    if (i >= n) return;
    float g = a[i];
    a[i] = tf32r((g / (1.f + expf(-g))) * b[i]);
}

__global__ void gate_out_kernel(const float* __restrict__ mem,
                                const float* __restrict__ inj,
                                const float* __restrict__ fg,
                                float* __restrict__ out, int n) {
    int i = blockIdx.x*blockDim.x + threadIdx.x;
    if (i >= n) return;
    float g = 1.f / (1.f + expf(-fg[i]));
    out[i] = mem[i]*g + inj[i]*(1.f - g);
}

/* ================================================================== */
extern "C" void kernel_launch(void* const* d_in, const int* in_sizes, int n_in,
                              void* d_out, int out_size) {
    const int*   ids    = (const int*)d_in[0];
    const float* memory = (const float*)d_in[1];
    const float* beacon = (const float*)d_in[2];
    const float* forget = (const float*)d_in[3];
    const float* embed  = (const float*)d_in[4];
    const float* ln1    = (const float*)d_in[5];
    const float* ln2    = (const float*)d_in[6];
    const float* Wq  = (const float*)d_in[7];
    const float* Wk  = (const float*)d_in[8];
    const float* Wv  = (const float*)d_in[9];
    const float* Wo  = (const float*)d_in[10];
    const float* mWk = (const float*)d_in[11];
    const float* mWv = (const float*)d_in[12];
    const float* bWq = (const float*)d_in[13];
    const float* bWk = (const float*)d_in[14];
    const float* bWv = (const float*)d_in[15];
    const float* fWq = (const float*)d_in[16];
    const float* fWk = (const float*)d_in[17];
    const float* fWv = (const float*)d_in[18];
    const float* Wg  = (const float*)d_in[19];
    const float* Wu  = (const float*)d_in[20];
    const float* Wd  = (const float*)d_in[21];

    static int attr_set = 0;
    if (!attr_set) {
        cudaFuncSetAttribute(sgemm_kernel, cudaFuncAttributeMaxDynamicSharedMemorySize, GSMEM_BYTES);
        cudaFuncSetAttribute(sgemm_batch_kernel, cudaFuncAttributeMaxDynamicSharedMemorySize, GSMEM_BYTES);
        cudaFuncSetAttribute(attn_kernel, cudaFuncAttributeMaxDynamicSharedMemorySize, ATTN_SMEM);
        attr_set = 1;
    }

    float *cat,*x,*q,*k,*v,*qbf,*kbf,*vbf,*att,*m1,*m2,*inj,*fg,*memr;
    float *wq,*wk,*wv,*wo,*mwk,*mwv,*bwq,*bwk,*bwv,*fwq,*fwk,*fwv,*wg,*wu,*wd;
    cudaGetSymbolAddress((void**)&cat, g_cat);
    cudaGetSymbolAddress((void**)&x,   g_x);
    cudaGetSymbolAddress((void**)&q,   g_q);
    cudaGetSymbolAddress((void**)&k,   g_k);
    cudaGetSymbolAddress((void**)&v,   g_v);
    cudaGetSymbolAddress((void**)&qbf, g_qbf);
    cudaGetSymbolAddress((void**)&kbf, g_kbf);
    cudaGetSymbolAddress((void**)&vbf, g_vbf);
    cudaGetSymbolAddress((void**)&att, g_att);
    cudaGetSymbolAddress((void**)&m1,  g_m1);
    cudaGetSymbolAddress((void**)&m2,  g_m2);
    cudaGetSymbolAddress((void**)&inj, g_inj);
    cudaGetSymbolAddress((void**)&fg,  g_fg);
    cudaGetSymbolAddress((void**)&memr,g_memr);
    cudaGetSymbolAddress((void**)&wq,  g_wq);
    cudaGetSymbolAddress((void**)&wk,  g_wk);
    cudaGetSymbolAddress((void**)&wv,  g_wv);
    cudaGetSymbolAddress((void**)&wo,  g_wo);
    cudaGetSymbolAddress((void**)&mwk, g_mwk);
    cudaGetSymbolAddress((void**)&mwv, g_mwv);
    cudaGetSymbolAddress((void**)&bwq, g_bwq);
    cudaGetSymbolAddress((void**)&bwk, g_bwk);
    cudaGetSymbolAddress((void**)&bwv, g_bwv);
    cudaGetSymbolAddress((void**)&fwq, g_fwq);
    cudaGetSymbolAddress((void**)&fwk, g_fwk);
    cudaGetSymbolAddress((void**)&fwv, g_fwv);
    cudaGetSymbolAddress((void**)&wg,  g_wg);
    cudaGetSymbolAddress((void**)&wu,  g_wu);
    cudaGetSymbolAddress((void**)&wd,  g_wd);

    const size_t RECB = (size_t)NM*ND*sizeof(float);

    init_tables_kernel<<<(NPOS*32+255)/256, 256>>>();
    gather_kernel<<<NS, 256>>>(ids, embed, cat);

    /* pre-round all weights (7 layers) + memory onto the tf32 grid */
    {
        RoundJobs js;
        js.j[0]  = { Wq,  wq,  WDD/4 };  js.j[1]  = { Wk,  wk,  WDD/4 };
        js.j[2]  = { Wv,  wv,  WDD/4 };  js.j[3]  = { Wo,  wo,  WDD/4 };
        js.j[4]  = { mWk, mwk, WDD/4 };  js.j[5]  = { mWv, mwv, WDD/4 };
        js.j[6]  = { bWq, bwq, WDD/4 };  js.j[7]  = { bWk, bwk, WDD/4 };
        js.j[8]  = { bWv, bwv, WDD/4 };  js.j[9]  = { fWq, fwq, WDD/4 };
        js.j[10] = { fWk, fwk, WDD/4 };  js.j[11] = { fWv, fwv, WDD/4 };
        js.j[12] = { Wg,  wg,  WDF/4 };  js.j[13] = { Wu,  wu,  WDF/4 };
        js.j[14] = { Wd,  wd,  WFD/4 };  js.j[15] = { memory, memr, (7*NM*ND)/4 };
        round_w_kernel<<<dim3(1024, 16), 256>>>(js);
    }

    cudaMemcpyAsync(cat + (size_t)NS*ND,      beacon, RECB, cudaMemcpyDeviceToDevice, 0);
    cudaMemcpyAsync(cat + (size_t)(NS+NM)*ND, forget, RECB, cudaMemcpyDeviceToDevice, 0);

    for (int l = 0; l < 7; l++) {
        const size_t wdd = (size_t)ND*ND;
        const float* Wq_l  = wq  + l*wdd;  const float* Wk_l  = wk  + l*wdd;
        const float* Wv_l  = wv  + l*wdd;  const float* Wo_l  = wo  + l*wdd;
        const float* mWk_l = mwk + l*wdd;  const float* mWv_l = mwv + l*wdd;
        const float* bWq_l = bwq + l*wdd;  const float* bWk_l = bwk + l*wdd;
        const float* bWv_l = bwv + l*wdd;  const float* fWq_l = fwq + l*wdd;
        const float* fWk_l = fwk + l*wdd;  const float* fWv_l = fwv + l*wdd;
        const float* Wg_l  = wg + (size_t)l*ND*NF;
        const float* Wu_l  = wu + (size_t)l*ND*NF;
        const float* Wd_l  = wd + (size_t)l*NF*ND;
        const float* mem_l = memr + (size_t)l*NM*ND;
        const bool last = (l == 6);

        /* ln1 + layer-entry record of beacon/forget rows */
        rmsnorm_kernel<<<NCAT, 256>>>(cat, ln1 + (size_t)l*ND, x,
                                      inj + (size_t)l*NM*ND, fg + (size_t)l*NM*ND);

        /* ALL projections of the layer in one batched launch */
        {
            GemmBatch ba; int nb = 0;
            const float* bx = x + (size_t)NS*ND;
            const float* fx = x + (size_t)(NS+NM)*ND;
            if (!last) ba.d[nb++] = { x, Wq_l, q, 8 };
            ba.d[nb++] = { x, Wk_l, k + (size_t)NM*ND, 8 };
            ba.d[nb++] = { x, Wv_l, v + (size_t)NM*ND, 8 };
            ba.d[nb++] = { mem_l, mWk_l, k, 1 };
            ba.d[nb++] = { mem_l, mWv_l, v, 1 };
            ba.d[nb++] = { bx, bWq_l, qbf, 1 };
            ba.d[nb++] = { bx, bWk_l, kbf, 1 };
            ba.d[nb++] = { bx, bWv_l, vbf, 1 };
            ba.d[nb++] = { fx, fWq_l, qbf + (size_t)NM*ND, 1 };
            ba.d[nb++] = { fx, fWk_l, kbf + (size_t)NM*ND, 1 };
            ba.d[nb++] = { fx, fWv_l, vbf + (size_t)NM*ND, 1 };
            sgemm_batch_kernel<<<dim3(8, 8, nb), 128, GSMEM_BYTES>>>(ba, ND, ND, 0);
        }

        {
            int inc_q = last ? 0 : 1;
            int rows = (inc_q ? NS : 0) + NKV + 512;
            rope_all_kernel<<<(rows*512 + 255)/256, 256>>>(q, k, qbf, kbf, inc_q);
        }

        if (!last)
            attn_kernel<<<dim3(NS/64, NH, 1), 128, ATTN_SMEM>>>(q, 0, k, v, NKV,
                                                    k, v, 0, 0,
                                                    att, 0, NM);
        attn_kernel<<<dim3(NM/64, NH, 2), 128, ATTN_SMEM>>>(qbf, (size_t)NM*ND, k, v, NKV,
                                                kbf, vbf, (size_t)NM*ND, NM,
                                                att + (size_t)NS*ND, (size_t)NM*ND, NKV);

        if (!last)
            sgemm_kernel<<<dim3(8, 10), 128, GSMEM_BYTES>>>(att, Wo_l, cat, ND, ND, 1);
        else
            sgemm_kernel<<<dim3(8, 2), 128, GSMEM_BYTES>>>(att + (size_t)NS*ND, Wo_l,
                                              cat + (size_t)NS*ND, ND, ND, 1);

        int rows = last ? 2*NM : NCAT;
        size_t off = last ? (size_t)NS*ND : 0;
        rmsnorm_kernel<<<rows, 256>>>(cat + off, ln2 + (size_t)l*ND, x + off,
                                      (float*)0, (float*)0);
        {
            GemmBatch ga;
            ga.d[0] = { x + off, Wg_l, m1, rows/128 };
            ga.d[1] = { x + off, Wu_l, m2, rows/128 };
            sgemm_batch_kernel<<<dim3(NF/128, rows/128, 2), 128, GSMEM_BYTES>>>(ga, NF, ND, 0);
        }
        silumul_kernel<<<(rows*NF)/256, 256>>>(m1, m2, rows*NF);
        sgemm_kernel<<<dim3(8, rows/128), 128, GSMEM_BYTES>>>(m1, Wd_l, cat + off, ND, NF, 1);
    }

    cudaMemcpyAsync(inj + (size_t)7*NM*ND, cat + (size_t)NS*ND,      RECB, cudaMemcpyDeviceToDevice, 0);
    cudaMemcpyAsync(fg  + (size_t)7*NM*ND, cat + (size_t)(NS+NM)*ND, RECB, cudaMemcpyDeviceToDevice, 0);

    gate_out_kernel<<<(NL*NM*ND)/256, 256>>>(memory, inj, fg, (float*)d_out, NL*NM*ND);
}

// round 12
// speedup vs baseline: 2.2936x; 1.0822x over previous
#include <cuda_runtime.h>
#include <math.h>
#include <mma.h>
#include <stdint.h>

using namespace nvcuda;

#define NS   1024
#define NM   128
#define ND   1024
#define NH   16
#define NHD  64
#define NF   2048
#define NL   8
#define NCAT 1280   /* S + 2M */
#define NKV  1152   /* M + S  */
#define NPOS 1280

/* ------------------------------------------------------------------ */
/* scratch (static device arrays; no allocation allowed)              */
/* ------------------------------------------------------------------ */
__device__ float g_cat[NCAT*ND];
__device__ float g_x  [NCAT*ND];
__device__ float g_q  [NS*ND];
__device__ float g_k  [NKV*ND];
__device__ float g_v  [NKV*ND];
__device__ float g_qbf[2*NM*ND];
__device__ float g_kbf[2*NM*ND];
__device__ float g_vbf[2*NM*ND];
__device__ float g_att[NCAT*ND];
__device__ float g_m1 [NCAT*NF];
__device__ float g_m2 [NCAT*NF];
__device__ float g_inj[NL*NM*ND];
__device__ float g_fg [NL*NM*ND];
__device__ float g_memr[7*NM*ND];
__device__ float g_cs [NPOS*32];
__device__ float g_sn [NPOS*32];

/* pre-rounded (tf32-grid) weights, 7 layers each */
#define WDD (7*ND*ND)
#define WDF (7*ND*NF)
#define WFD (7*NF*ND)
__device__ float g_wq [WDD]; __device__ float g_wk [WDD];
__device__ float g_wv [WDD]; __device__ float g_wo [WDD];
__device__ float g_mwk[WDD]; __device__ float g_mwv[WDD];
__device__ float g_bwq[WDD]; __device__ float g_bwk[WDD];
__device__ float g_bwv[WDD]; __device__ float g_fwq[WDD];
__device__ float g_fwk[WDD]; __device__ float g_fwv[WDD];
__device__ float g_wg [WDF]; __device__ float g_wu [WDF];
__device__ float g_wd [WFD];

/* round-to-nearest onto the tf32 grid (so HW truncation is exact)    */
__device__ __forceinline__ float tf32r(float x) {
    unsigned u = __float_as_uint(x), r;
    asm("cvt.rna.tf32.f32 %0, %1;" : "=r"(r) : "r"(u));
    return __uint_as_float(r);
}

/* ------------------------------------------------------------------ */
__global__ void init_tables_kernel() {
    int idx = blockIdx.x*blockDim.x + threadIdx.x;
    if (idx >= NPOS*32) return;
    int pos = idx >> 5, j = idx & 31;
    double inv = exp(-((double)(2*j)/64.0) * log(10000.0));
    double a = (double)pos * inv;
    g_cs[idx] = (float)cos(a);
    g_sn[idx] = (float)sin(a);
}

__global__ void gather_kernel(const int* __restrict__ ids,
                              const float* __restrict__ embed,
                              float* __restrict__ out) {
    int row = blockIdx.x;
    int id  = ids[row];
    const float4* src = (const float4*)(embed + (size_t)id*ND);
    float4* dst = (float4*)(out + (size_t)row*ND);
    dst[threadIdx.x] = src[threadIdx.x];
}

/* batched tf32-grid rounding (one layer's weights per call)          */
struct RoundJob  { const float* s; float* d; int n4; };
struct RoundJobs { RoundJob j[16]; };

__global__ void round_w_kernel(RoundJobs js) {
    RoundJob jb = js.j[blockIdx.y];
    const float4* s = (const float4*)jb.s;
    float4* d = (float4*)jb.d;
    int stride = gridDim.x*blockDim.x;
    for (int i = blockIdx.x*blockDim.x + threadIdx.x; i < jb.n4; i += stride) {
        float4 v = s[i];
        v.x = tf32r(v.x); v.y = tf32r(v.y);
        v.z = tf32r(v.z); v.w = tf32r(v.w);
        d[i] = v;
    }
}

/* RMSNorm; output rounded to tf32 grid. Optionally records the raw   */
/* beacon/forget rows (layer-entry snapshot) into inj/fg.             */
__global__ void rmsnorm_kernel(const float* __restrict__ x,
                               const float* __restrict__ w,
                               float* __restrict__ y,
                               float* __restrict__ rec_inj,
                               float* __restrict__ rec_fg) {
    int row = blockIdx.x, t = threadIdx.x;
    const float* xr = x + (size_t)row*ND;
    float s = 0.f;
    #pragma unroll
    for (int i = t; i < ND; i += 256) { float v = xr[i]; s += v*v; }
    __shared__ float red[256];
    red[t] = s; __syncthreads();
    for (int st = 128; st > 0; st >>= 1) {
        if (t < st) red[t] += red[t+st];
        __syncthreads();
    }
    float r = rsqrtf(red[0]*(1.f/ND) + 1e-5f);
    float* yr = y + (size_t)row*ND;
    float* dst = 0;
    if (rec_inj && row >= NS)
        dst = (row < NS+NM) ? rec_inj + (size_t)(row-NS)*ND
                            : rec_fg  + (size_t)(row-NS-NM)*ND;
    #pragma unroll
    for (int i = t; i < ND; i += 256) {
        float v = xr[i];
        if (dst) dst[i] = v;
        yr[i] = tf32r(v*w[i]*r);
    }
}

/* ------------------------------------------------------------------ */
/* tf32 WMMA GEMM: 128x128 CTA tile, 4 warps (64x64), BK=32, 3-stage  */
/* cp.async. A and B both pre-rounded to the tf32 grid -> zero cvt.   */
/* ------------------------------------------------------------------ */
struct GemmDesc  { const float* A; const float* B; float* C; };
struct GemmBatch { GemmDesc d[12]; unsigned char yd[40]; unsigned char yr[40]; };

typedef wmma::fragment<wmma::matrix_a, 16,16,8, wmma::precision::tf32, wmma::row_major> FragA;
typedef wmma::fragment<wmma::matrix_b, 16,16,8, wmma::precision::tf32, wmma::row_major> FragB;
typedef wmma::fragment<wmma::matrix_b, 16,16,8, wmma::precision::tf32, wmma::col_major> FragBc;
typedef wmma::fragment<wmma::accumulator, 16,16,8, float> FragC;

#define GSTAGES 3
#define A_STRIDE 36
#define B_STRIDE 132
#define A_TILE_F (128*A_STRIDE)
#define B_TILE_F (32*B_STRIDE)
#define GSMEM_BYTES (GSTAGES*(A_TILE_F + B_TILE_F)*4)

__device__ __forceinline__ void cp16(uint32_t dst, const void* src) {
    asm volatile("cp.async.cg.shared.global [%0], [%1], 16;" :: "r"(dst), "l"(src));
}
__device__ __forceinline__ void cp_commit() {
    asm volatile("cp.async.commit_group;");
}
__device__ __forceinline__ void cp_wait1() {
    asm volatile("cp.async.wait_group 1;");
}

__device__ __forceinline__ void gemm_core(const float* __restrict__ A,
                                          const float* __restrict__ B,
                                          float* __restrict__ C,
                                          int N, int K, int beta, int rowblk) {
    extern __shared__ float sm[];
    float* Asm = sm;
    float* Bsm = sm + GSTAGES*A_TILE_F;

    int tid = threadIdx.x;
    int wid = tid >> 5;
    int wy  = wid >> 1;
    int wx  = wid & 1;
    size_t brow = (size_t)rowblk * 128;
    size_t bcol = (size_t)blockIdx.x * 128;

    int ar = tid >> 3, ac = (tid & 7) << 2;
    int br = tid >> 5, bc = (tid & 31) << 2;

    const float* Ag = A + (brow + ar)*K + ac;
    const float* Bg = B + (size_t)br*N + bcol + bc;

    uint32_t sA = (uint32_t)__cvta_generic_to_shared(Asm + ar*A_STRIDE + ac);
    uint32_t sB = (uint32_t)__cvta_generic_to_shared(Bsm + br*B_STRIDE + bc);
    const uint32_t aStageB = A_TILE_F*4;
    const uint32_t bStageB = B_TILE_F*4;

    int nt = K >> 5;

    #pragma unroll
    for (int s = 0; s < 2; s++) {
        int k0 = s << 5;
        #pragma unroll
        for (int i = 0; i < 8; i++)
            cp16(sA + s*aStageB + i*16*A_STRIDE*4, Ag + k0 + (size_t)(16*i)*K);
        #pragma unroll
        for (int i = 0; i < 8; i++)
            cp16(sB + s*bStageB + i*4*B_STRIDE*4, Bg + (size_t)(k0 + 4*i)*N);
        cp_commit();
    }

    FragC acc[4][4];
    #pragma unroll
    for (int mi = 0; mi < 4; mi++)
        #pragma unroll
        for (int ni = 0; ni < 4; ni++)
            wmma::fill_fragment(acc[mi][ni], 0.f);

    int st = 0, ld = 2;
    for (int kt = 0; kt < nt; kt++) {
        cp_wait1();
        __syncthreads();
        if (kt + 2 < nt) {
            int k0 = (kt + 2) << 5;
            #pragma unroll
            for (int i = 0; i < 8; i++)
                cp16(sA + ld*aStageB + i*16*A_STRIDE*4, Ag + k0 + (size_t)(16*i)*K);
            #pragma unroll
            for (int i = 0; i < 8; i++)
                cp16(sB + ld*bStageB + i*4*B_STRIDE*4, Bg + (size_t)(k0 + 4*i)*N);
        }
        cp_commit();

        const float* Ast = Asm + st*A_TILE_F;
        const float* Bst = Bsm + st*B_TILE_F;
        #pragma unroll
        for (int kk = 0; kk < 32; kk += 8) {
            FragA af[4];
            FragB bf[4];
            #pragma unroll
            for (int mi = 0; mi < 4; mi++)
                wmma::load_matrix_sync(af[mi], Ast + (wy*64 + mi*16)*A_STRIDE + kk, A_STRIDE);
            #pragma unroll
            for (int ni = 0; ni < 4; ni++)
                wmma::load_matrix_sync(bf[ni], Bst + kk*B_STRIDE + wx*64 + ni*16, B_STRIDE);
            #pragma unroll
            for (int mi = 0; mi < 4; mi++)
                #pragma unroll
                for (int ni = 0; ni < 4; ni++)
                    wmma::mma_sync(acc[mi][ni], af[mi], bf[ni], acc[mi][ni]);
        }
        st++; if (st == GSTAGES) st = 0;
        ld++; if (ld == GSTAGES) ld = 0;
    }

    #pragma unroll
    for (int mi = 0; mi < 4; mi++)
        #pragma unroll
        for (int ni = 0; ni < 4; ni++) {
            float* cp = C + (brow + wy*64 + mi*16)*N + bcol + wx*64 + ni*16;
            if (beta) {
                FragC cf;
                wmma::load_matrix_sync(cf, cp, N, wmma::mem_row_major);
                #pragma unroll
                for (int t = 0; t < cf.num_elements; t++)
                    acc[mi][ni].x[t] += cf.x[t];
            }
            wmma::store_matrix_sync(cp, acc[mi][ni], N, wmma::mem_row_major);
        }
}

__global__ __launch_bounds__(128, 2)
void sgemm_kernel(const float* A, const float* B, float* C, int N, int K, int beta) {
    gemm_core(A, B, C, N, K, beta, blockIdx.y);
}
__global__ __launch_bounds__(128, 2)
void sgemm_batch_kernel(GemmBatch bat, int N, int K, int beta) {
    int y = blockIdx.y;
    GemmDesc dsc = bat.d[bat.yd[y]];
    gemm_core(dsc.A, dsc.B, dsc.C, N, K, beta, bat.yr[y]);
}

/* ------------------------------------------------------------------ */
/* WMMA flash attention (3x tf32 hi/lo split) with RoPE fused into    */
/* the Q/K tile loads (pair (j, j+32) exchanged via neighbor-lane     */
/* shuffle; positions derived from row index: K1 row -> pos=row,      */
/* K2 row i -> pos=coff+i, Q row q -> pos=coff+q).                    */
/* ------------------------------------------------------------------ */
#define AT_STRIDE 68
#define AT_TILE   (64*AT_STRIDE)
#define ATTN_SMEM ((5*AT_TILE + 128)*4)

template<class F>
__device__ __forceinline__ void split_frag(const F& raw, F& hi, F& lo) {
    #pragma unroll
    for (int t = 0; t < raw.num_elements; t++) {
        float x = raw.x[t];
        float h = wmma::__float_to_tf32(x);
        hi.x[t] = h;
        lo.x[t] = wmma::__float_to_tf32(x - h);
    }
}

__global__ __launch_bounds__(128)
void attn_kernel(const float* Q, size_t qz,
                 const float* K1, const float* V1, int n1,
                 const float* K2, const float* V2, size_t kz, int n2,
                 float* O, size_t oz, int coff) {
    extern __shared__ float sm[];
    float* Qs = sm;
    float* Ks = sm +   AT_TILE;
    float* Vs = sm + 2*AT_TILE;
    float* Ss = sm + 3*AT_TILE;
    float* Os = sm + 4*AT_TILE;
    float* mrow = sm + 5*AT_TILE;
    float* lrow = mrow + 64;

    int z = blockIdx.z;
    Q  += (size_t)z*qz;  K2 += (size_t)z*kz;
    V2 += (size_t)z*kz;  O  += (size_t)z*oz;
    int h  = blockIdx.y;
    int q0 = blockIdx.x*64;
    int tid = threadIdx.x;
    int wid = tid >> 5;
    int r2  = tid >> 1;
    int hf  = tid & 1;
    float sgn = hf ? 1.f : -1.f;

    /* Q load + RoPE + zero O, init m/l */
    {
        float qv[32], cs[32], sn[32];
        const float4* qp = (const float4*)(Q + (size_t)(q0+r2)*ND + h*64 + hf*32);
        #pragma unroll
        for (int i = 0; i < 8; i++) {
            float4 t = qp[i];
            qv[4*i]=t.x; qv[4*i+1]=t.y; qv[4*i+2]=t.z; qv[4*i+3]=t.w;
        }
        int pos = coff + q0 + r2;
        const float4* c4 = (const float4*)(g_cs + pos*32);
        const float4* s4 = (const float4*)(g_sn + pos*32);
        #pragma unroll
        for (int i = 0; i < 8; i++) {
            float4 a = c4[i]; cs[4*i]=a.x; cs[4*i+1]=a.y; cs[4*i+2]=a.z; cs[4*i+3]=a.w;
            float4 b = s4[i]; sn[4*i]=b.x; sn[4*i+1]=b.y; sn[4*i+2]=b.z; sn[4*i+3]=b.w;
        }
        float* qd = Qs + r2*AT_STRIDE + hf*32;
        float* od = Os + r2*AT_STRIDE + hf*32;
        #pragma unroll
        for (int c = 0; c < 32; c++) {
            float o = __shfl_xor_sync(0xffffffffu, qv[c], 1);
            qd[c] = qv[c]*cs[c] + sgn*o*sn[c];
            od[c] = 0.f;
        }
        if (tid < 64) { mrow[tid] = -1e30f; lrow[tid] = 0.f; }
    }
    __syncthreads();

    int ntot = n1 + n2;
    int kmax = ntot;
    int vis  = q0 + 64 + coff;
    if (vis < kmax) kmax = vis;

    for (int t0 = 0; t0 < kmax; t0 += 64) {
        /* K/V tile load; K gets RoPE */
        {
            int kk = t0 + r2;
            const float *kp, *vp; int pos;
            if (kk < n1) { kp = K1 + (size_t)kk*ND; vp = V1 + (size_t)kk*ND; pos = kk; }
            else { int r = kk - n1; kp = K2 + (size_t)r*ND; vp = V2 + (size_t)r*ND; pos = coff + r; }
            kp += h*64 + hf*32; vp += h*64 + hf*32;
            float kv[32], cs[32], sn[32];
            float4* vd = (float4*)(Vs + r2*AT_STRIDE + hf*32);
            #pragma unroll
            for (int i = 0; i < 8; i++) {
                float4 t = ((const float4*)kp)[i];
                kv[4*i]=t.x; kv[4*i+1]=t.y; kv[4*i+2]=t.z; kv[4*i+3]=t.w;
                vd[i] = ((const float4*)vp)[i];
            }
            const float4* c4 = (const float4*)(g_cs + pos*32);
            const float4* s4 = (const float4*)(g_sn + pos*32);
            #pragma unroll
            for (int i = 0; i < 8; i++) {
                float4 a = c4[i]; cs[4*i]=a.x; cs[4*i+1]=a.y; cs[4*i+2]=a.z; cs[4*i+3]=a.w;
                float4 b = s4[i]; sn[4*i]=b.x; sn[4*i+1]=b.y; sn[4*i+2]=b.z; sn[4*i+3]=b.w;
            }
            float* kd = Ks + r2*AT_STRIDE + hf*32;
            #pragma unroll
            for (int c = 0; c < 32; c++) {
                float o = __shfl_xor_sync(0xffffffffu, kv[c], 1);
                kd[c] = kv[c]*cs[c] + sgn*o*sn[c];
            }
        }
        __syncthreads();

        {
            FragC sacc[4];
            #pragma unroll
            for (int ni = 0; ni < 4; ni++) wmma::fill_fragment(sacc[ni], 0.f);
            #pragma unroll
            for (int ks = 0; ks < 8; ks++) {
                FragA araw, ah, al;
                wmma::load_matrix_sync(araw, Qs + (wid*16)*AT_STRIDE + ks*8, AT_STRIDE);
                split_frag(araw, ah, al);
                #pragma unroll
                for (int ni = 0; ni < 4; ni++) {
                    FragBc braw, bh, bl;
                    wmma::load_matrix_sync(braw, Ks + (ni*16)*AT_STRIDE + ks*8, AT_STRIDE);
                    split_frag(braw, bh, bl);
                    wmma::mma_sync(sacc[ni], ah, bh, sacc[ni]);
                    wmma::mma_sync(sacc[ni], ah, bl, sacc[ni]);
                    wmma::mma_sync(sacc[ni], al, bh, sacc[ni]);
                }
            }
            #pragma unroll
            for (int ni = 0; ni < 4; ni++)
                wmma::store_matrix_sync(Ss + (wid*16)*AT_STRIDE + ni*16, sacc[ni],
                                        AT_STRIDE, wmma::mem_row_major);
        }
        __syncthreads();

        {
            int moff = q0 + coff - t0;
            int jmax = r2 + moff; if (jmax > 63) jmax = 63;
            float mold = mrow[r2];
            float* srow = Ss + r2*AT_STRIDE + hf*32;
            float sv[32];
            float tmax = -1e30f;
            #pragma unroll
            for (int c = 0; c < 32; c++) {
                int cc = hf*32 + c;
                float s = srow[c]*0.125f;
                sv[c] = s;
                if (cc <= jmax) tmax = fmaxf(tmax, s);
            }
            tmax = fmaxf(tmax, __shfl_xor_sync(0xffffffffu, tmax, 1));
            float mnew = fmaxf(mold, tmax);
            float corr = expf(mold - mnew);
            float psum = 0.f;
            #pragma unroll
            for (int c = 0; c < 32; c++) {
                int cc = hf*32 + c;
                float p = (cc <= jmax) ? expf(sv[c] - mnew) : 0.f;
                srow[c] = p;
                psum += p;
            }
            psum += __shfl_xor_sync(0xffffffffu, psum, 1);
            if (hf == 0) { mrow[r2] = mnew; lrow[r2] = lrow[r2]*corr + psum; }
            float* orow = Os + r2*AT_STRIDE + hf*32;
            #pragma unroll
            for (int c = 0; c < 32; c++) orow[c] *= corr;
        }
        __syncthreads();

        {
            FragC oacc[4];
            #pragma unroll
            for (int ni = 0; ni < 4; ni++)
                wmma::load_matrix_sync(oacc[ni], Os + (wid*16)*AT_STRIDE + ni*16,
                                       AT_STRIDE, wmma::mem_row_major);
            #pragma unroll
            for (int ks = 0; ks < 8; ks++) {
                FragA praw, ph, pl;
                wmma::load_matrix_sync(praw, Ss + (wid*16)*AT_STRIDE + ks*8, AT_STRIDE);
                split_frag(praw, ph, pl);
                #pragma unroll
                for (int ni = 0; ni < 4; ni++) {
                    FragB vraw, vh, vl;
                    wmma::load_matrix_sync(vraw, Vs + (ks*8)*AT_STRIDE + ni*16, AT_STRIDE);
                    split_frag(vraw, vh, vl);
                    wmma::mma_sync(oacc[ni], ph, vh, oacc[ni]);
                    wmma::mma_sync(oacc[ni], ph, vl, oacc[ni]);
                    wmma::mma_sync(oacc[ni], pl, vh, oacc[ni]);
                }
            }
            #pragma unroll
            for (int ni = 0; ni < 4; ni++)
                wmma::store_matrix_sync(Os + (wid*16)*AT_STRIDE + ni*16, oacc[ni],
                                        AT_STRIDE, wmma::mem_row_major);
        }
        __syncthreads();
    }

    {
        float invl = 1.f/lrow[r2];
        const float* orow = Os + r2*AT_STRIDE + hf*32;
        float* op = O + (size_t)(q0+r2)*ND + h*64 + hf*32;
        #pragma unroll
        for (int c = 0; c < 32; c++) op[c] = tf32r(orow[c]*invl);
    }
}

/* ------------------------------------------------------------------ */
__global__ void silumul_kernel(float* __restrict__ a, const float* __restrict__ b, int n) {
    int i = blockIdx.x*blockDim.x + threadIdx.x;
    if (i >= n) return;
    float g = a[i];
    a[i] = tf32r((g / (1.f + expf(-g))) * b[i]);
}

__global__ void gate_out_kernel(const float* __restrict__ mem,
                                const float* __restrict__ inj,
                                const float* __restrict__ fg,
                                float* __restrict__ out, int n) {
    int i = blockIdx.x*blockDim.x + threadIdx.x;
    if (i >= n) return;
    float g = 1.f / (1.f + expf(-fg[i]));
    out[i] = mem[i]*g + inj[i]*(1.f - g);
}

/* ================================================================== */
extern "C" void kernel_launch(void* const* d_in, const int* in_sizes, int n_in,
                              void* d_out, int out_size) {
    const int*   ids    = (const int*)d_in[0];
    const float* memory = (const float*)d_in[1];
    const float* beacon = (const float*)d_in[2];
    const float* forget = (const float*)d_in[3];
    const float* embed  = (const float*)d_in[4];
    const float* ln1    = (const float*)d_in[5];
    const float* ln2    = (const float*)d_in[6];
    const float* Wq  = (const float*)d_in[7];
    const float* Wk  = (const float*)d_in[8];
    const float* Wv  = (const float*)d_in[9];
    const float* Wo  = (const float*)d_in[10];
    const float* mWk = (const float*)d_in[11];
    const float* mWv = (const float*)d_in[12];
    const float* bWq = (const float*)d_in[13];
    const float* bWk = (const float*)d_in[14];
    const float* bWv = (const float*)d_in[15];
    const float* fWq = (const float*)d_in[16];
    const float* fWk = (const float*)d_in[17];
    const float* fWv = (const float*)d_in[18];
    const float* Wg  = (const float*)d_in[19];
    const float* Wu  = (const float*)d_in[20];
    const float* Wd  = (const float*)d_in[21];

    static int attr_set = 0;
    static cudaStream_t s2;
    static cudaEvent_t eA, eB, eC;
    if (!attr_set) {
        cudaFuncSetAttribute(sgemm_kernel, cudaFuncAttributeMaxDynamicSharedMemorySize, GSMEM_BYTES);
        cudaFuncSetAttribute(sgemm_batch_kernel, cudaFuncAttributeMaxDynamicSharedMemorySize, GSMEM_BYTES);
        cudaFuncSetAttribute(attn_kernel, cudaFuncAttributeMaxDynamicSharedMemorySize, ATTN_SMEM);
        cudaStreamCreateWithFlags(&s2, cudaStreamNonBlocking);
        cudaEventCreateWithFlags(&eA, cudaEventDisableTiming);
        cudaEventCreateWithFlags(&eB, cudaEventDisableTiming);
        cudaEventCreateWithFlags(&eC, cudaEventDisableTiming);
        attr_set = 1;
    }

    float *cat,*x,*q,*k,*v,*qbf,*kbf,*vbf,*att,*m1,*m2,*inj,*fg,*memr;
    float *wq,*wk,*wv,*wo,*mwk,*mwv,*bwq,*bwk,*bwv,*fwq,*fwk,*fwv,*wg,*wu,*wd;
    cudaGetSymbolAddress((void**)&cat, g_cat);
    cudaGetSymbolAddress((void**)&x,   g_x);
    cudaGetSymbolAddress((void**)&q,   g_q);
    cudaGetSymbolAddress((void**)&k,   g_k);
    cudaGetSymbolAddress((void**)&v,   g_v);
    cudaGetSymbolAddress((void**)&qbf, g_qbf);
    cudaGetSymbolAddress((void**)&kbf, g_kbf);
    cudaGetSymbolAddress((void**)&vbf, g_vbf);
    cudaGetSymbolAddress((void**)&att, g_att);
    cudaGetSymbolAddress((void**)&m1,  g_m1);
    cudaGetSymbolAddress((void**)&m2,  g_m2);
    cudaGetSymbolAddress((void**)&inj, g_inj);
    cudaGetSymbolAddress((void**)&fg,  g_fg);
    cudaGetSymbolAddress((void**)&memr,g_memr);
    cudaGetSymbolAddress((void**)&wq,  g_wq);
    cudaGetSymbolAddress((void**)&wk,  g_wk);
    cudaGetSymbolAddress((void**)&wv,  g_wv);
    cudaGetSymbolAddress((void**)&wo,  g_wo);
    cudaGetSymbolAddress((void**)&mwk, g_mwk);
    cudaGetSymbolAddress((void**)&mwv, g_mwv);
    cudaGetSymbolAddress((void**)&bwq, g_bwq);
    cudaGetSymbolAddress((void**)&bwk, g_bwk);
    cudaGetSymbolAddress((void**)&bwv, g_bwv);
    cudaGetSymbolAddress((void**)&fwq, g_fwq);
    cudaGetSymbolAddress((void**)&fwk, g_fwk);
    cudaGetSymbolAddress((void**)&fwv, g_fwv);
    cudaGetSymbolAddress((void**)&wg,  g_wg);
    cudaGetSymbolAddress((void**)&wu,  g_wu);
    cudaGetSymbolAddress((void**)&wd,  g_wd);

    const size_t RECB = (size_t)NM*ND*sizeof(float);
    const size_t wdd = (size_t)ND*ND;
    const int DD4 = ND*ND/4, DF4 = ND*NF/4, MEM4 = NM*ND/4;

    auto round_layer = [&](int l, cudaStream_t st) {
        RoundJobs js;
        js.j[0]  = { Wq  + l*wdd, wq  + l*wdd, DD4 };
        js.j[1]  = { Wk  + l*wdd, wk  + l*wdd, DD4 };
        js.j[2]  = { Wv  + l*wdd, wv  + l*wdd, DD4 };
        js.j[3]  = { Wo  + l*wdd, wo  + l*wdd, DD4 };
        js.j[4]  = { mWk + l*wdd, mwk + l*wdd, DD4 };
        js.j[5]  = { mWv + l*wdd, mwv + l*wdd, DD4 };
        js.j[6]  = { bWq + l*wdd, bwq + l*wdd, DD4 };
        js.j[7]  = { bWk + l*wdd, bwk + l*wdd, DD4 };
        js.j[8]  = { bWv + l*wdd, bwv + l*wdd, DD4 };
        js.j[9]  = { fWq + l*wdd, fwq + l*wdd, DD4 };
        js.j[10] = { fWk + l*wdd, fwk + l*wdd, DD4 };
        js.j[11] = { fWv + l*wdd, fwv + l*wdd, DD4 };
        js.j[12] = { Wg + (size_t)l*ND*NF, wg + (size_t)l*ND*NF, DF4 };
        js.j[13] = { Wu + (size_t)l*ND*NF, wu + (size_t)l*ND*NF, DF4 };
        js.j[14] = { Wd + (size_t)l*NF*ND, wd + (size_t)l*NF*ND, DF4 };
        js.j[15] = { memory + (size_t)l*NM*ND, memr + (size_t)l*NM*ND, MEM4 };
        round_w_kernel<<<dim3(256, 16), 256, 0, st>>>(js);
    };

    init_tables_kernel<<<(NPOS*32+255)/256, 256>>>();
    gather_kernel<<<NS, 256>>>(ids, embed, cat);
    round_layer(0, 0);
    cudaMemcpyAsync(cat + (size_t)NS*ND,      beacon, RECB, cudaMemcpyDeviceToDevice, 0);
    cudaMemcpyAsync(cat + (size_t)(NS+NM)*ND, forget, RECB, cudaMemcpyDeviceToDevice, 0);

    for (int l = 0; l < 7; l++) {
        const float* Wq_l  = wq  + l*wdd;  const float* Wk_l  = wk  + l*wdd;
        const float* Wv_l  = wv  + l*wdd;  const float* Wo_l  = wo  + l*wdd;
        const float* mWk_l = mwk + l*wdd;  const float* mWv_l = mwv + l*wdd;
        const float* bWq_l = bwq + l*wdd;  const float* bWk_l = bwk + l*wdd;
        const float* bWv_l = bwv + l*wdd;  const float* fWq_l = fwq + l*wdd;
        const float* fWk_l = fwk + l*wdd;  const float* fWv_l = fwv + l*wdd;
        const float* Wg_l  = wg + (size_t)l*ND*NF;
        const float* Wu_l  = wu + (size_t)l*ND*NF;
        const float* Wd_l  = wd + (size_t)l*NF*ND;
        const float* mem_l = memr + (size_t)l*NM*ND;
        const bool last = (l == 6);

        if (l > 0) cudaStreamWaitEvent(0, eC, 0);   /* layer-l weights ready */

        rmsnorm_kernel<<<NCAT, 256>>>(cat, ln1 + (size_t)l*ND, x,
                                      inj + (size_t)l*NM*ND, fg + (size_t)l*NM*ND);

        /* ALL projections of the layer in one packed batched launch */
        {
            GemmBatch ba; int nb = 0, ny = 0;
            const float* bx = x + (size_t)NS*ND;
            const float* fx = x + (size_t)(NS+NM)*ND;
            int nrbs[12];
            if (!last) { ba.d[nb] = { x, Wq_l, q }; nrbs[nb++] = 8; }
            ba.d[nb] = { x, Wk_l, k + (size_t)NM*ND }; nrbs[nb++] = 8;
            ba.d[nb] = { x, Wv_l, v + (size_t)NM*ND }; nrbs[nb++] = 8;
            ba.d[nb] = { mem_l, mWk_l, k };   nrbs[nb++] = 1;
            ba.d[nb] = { mem_l, mWv_l, v };   nrbs[nb++] = 1;
            ba.d[nb] = { bx, bWq_l, qbf };    nrbs[nb++] = 1;
            ba.d[nb] = { bx, bWk_l, kbf };    nrbs[nb++] = 1;
            ba.d[nb] = { bx, bWv_l, vbf };    nrbs[nb++] = 1;
            ba.d[nb] = { fx, fWq_l, qbf + (size_t)NM*ND }; nrbs[nb++] = 1;
            ba.d[nb] = { fx, fWk_l, kbf + (size_t)NM*ND }; nrbs[nb++] = 1;
            ba.d[nb] = { fx, fWv_l, vbf + (size_t)NM*ND }; nrbs[nb++] = 1;
            for (int di = 0; di < nb; di++)
                for (int rb = 0; rb < nrbs[di]; rb++) {
                    ba.yd[ny] = (unsigned char)di;
                    ba.yr[ny] = (unsigned char)rb; ny++;
                }
            sgemm_batch_kernel<<<dim3(8, ny, 1), 128, GSMEM_BYTES>>>(ba, ND, ND, 0);
        }

        /* fork: gates chain on s2, hidden chain on main */
        cudaEventRecord(eA, 0);
        cudaStreamWaitEvent(s2, eA, 0);

        if (!last)
            attn_kernel<<<dim3(NS/64, NH, 1), 128, ATTN_SMEM>>>(q, 0, k, v, NKV,
                                                    k, v, 0, 0, att, 0, NM);
        attn_kernel<<<dim3(NM/64, NH, 2), 128, ATTN_SMEM, s2>>>(
                                                qbf, (size_t)NM*ND, k, v, NKV,
                                                kbf, vbf, (size_t)NM*ND, NM,
                                                att + (size_t)NS*ND, (size_t)NM*ND, NKV);
        sgemm_kernel<<<dim3(8, 2), 128, GSMEM_BYTES, s2>>>(att + (size_t)NS*ND, Wo_l,
                                              cat + (size_t)NS*ND, ND, ND, 1);
        cudaEventRecord(eB, s2);
        if (l + 1 < 7) { round_layer(l + 1, s2); cudaEventRecord(eC, s2); }

        if (!last)
            sgemm_kernel<<<dim3(8, 8), 128, GSMEM_BYTES>>>(att, Wo_l, cat, ND, ND, 1);
        cudaStreamWaitEvent(0, eB, 0);

        int rows = last ? 2*NM : NCAT;
        size_t off = last ? (size_t)NS*ND : 0;
        rmsnorm_kernel<<<rows, 256>>>(cat + off, ln2 + (size_t)l*ND, x + off,
                                      (float*)0, (float*)0);
        {
            GemmBatch ga; int ny = 0;
            ga.d[0] = { x + off, Wg_l, m1 };
            ga.d[1] = { x + off, Wu_l, m2 };
            for (int di = 0; di < 2; di++)
                for (int rb = 0; rb < rows/128; rb++) {
                    ga.yd[ny] = (unsigned char)di;
                    ga.yr[ny] = (unsigned char)rb; ny++;
                }
            sgemm_batch_kernel<<<dim3(NF/128, ny, 1), 128, GSMEM_BYTES>>>(ga, NF, ND, 0);
        }
        silumul_kernel<<<(rows*NF)/256, 256>>>(m1, m2, rows*NF);
        sgemm_kernel<<<dim3(8, rows/128), 128, GSMEM_BYTES>>>(m1, Wd_l, cat + off, ND, NF, 1);
    }

    cudaMemcpyAsync(inj + (size_t)7*NM*ND, cat + (size_t)NS*ND,      RECB, cudaMemcpyDeviceToDevice, 0);
    cudaMemcpyAsync(fg  + (size_t)7*NM*ND, cat + (size_t)(NS+NM)*ND, RECB, cudaMemcpyDeviceToDevice, 0);

    gate_out_kernel<<<(NL*NM*ND)/256, 256>>>(memory, inj, fg, (float*)d_out, NL*NM*ND);
}

// round 13
// speedup vs baseline: 3.7935x; 1.6539x over previous
#include <cuda_runtime.h>
#include <cuda_fp16.h>
#include <math.h>
#include <mma.h>
#include <stdint.h>

using namespace nvcuda;

#define NS   1024
#define NM   128
#define ND   1024
#define NH   16
#define NHD  64
#define NF   2048
#define NL   8
#define NCAT 1280   /* S + 2M */
#define NKV  1152   /* M + S  */
#define NPOS 1280

/* ------------------------------------------------------------------ */
/* scratch (static device arrays; no allocation allowed)              */
/* ------------------------------------------------------------------ */
__device__ float g_cat[NCAT*ND];
__device__ __align__(256) __half g_xh [NCAT*ND];
__device__ float g_q  [NS*ND];
__device__ float g_k  [NKV*ND];
__device__ float g_v  [NKV*ND];
__device__ float g_qbf[2*NM*ND];
__device__ float g_kbf[2*NM*ND];
__device__ float g_vbf[2*NM*ND];
__device__ __align__(256) __half g_atth[NCAT*ND];
__device__ float g_m1 [NCAT*NF];
__device__ float g_m2 [NCAT*NF];
__device__ __align__(256) __half g_m1h[NCAT*NF];
__device__ float g_inj[NL*NM*ND];
__device__ float g_fg [NL*NM*ND];
__device__ __align__(256) __half g_memh[7*NM*ND];
__device__ float g_cs [NPOS*32];
__device__ float g_sn [NPOS*32];

/* pre-rounded fp16 weights, 7 layers each */
#define WDD (7*ND*ND)
#define WDF (7*ND*NF)
__device__ __align__(256) __half g_wq [WDD]; __device__ __align__(256) __half g_wk [WDD];
__device__ __align__(256) __half g_wv [WDD]; __device__ __align__(256) __half g_wo [WDD];
__device__ __align__(256) __half g_mwk[WDD]; __device__ __align__(256) __half g_mwv[WDD];
__device__ __align__(256) __half g_bwq[WDD]; __device__ __align__(256) __half g_bwk[WDD];
__device__ __align__(256) __half g_bwv[WDD]; __device__ __align__(256) __half g_fwq[WDD];
__device__ __align__(256) __half g_fwk[WDD]; __device__ __align__(256) __half g_fwv[WDD];
__device__ __align__(256) __half g_wg [WDF]; __device__ __align__(256) __half g_wu [WDF];
__device__ __align__(256) __half g_wd [WDF];

/* ------------------------------------------------------------------ */
__global__ void init_tables_kernel() {
    int idx = blockIdx.x*blockDim.x + threadIdx.x;
    if (idx >= NPOS*32) return;
    int pos = idx >> 5, j = idx & 31;
    double inv = exp(-((double)(2*j)/64.0) * log(10000.0));
    double a = (double)pos * inv;
    g_cs[idx] = (float)cos(a);
    g_sn[idx] = (float)sin(a);
}

__global__ void gather_kernel(const int* __restrict__ ids,
                              const float* __restrict__ embed,
                              float* __restrict__ out) {
    int row = blockIdx.x;
    int id  = ids[row];
    const float4* src = (const float4*)(embed + (size_t)id*ND);
    float4* dst = (float4*)(out + (size_t)row*ND);
    dst[threadIdx.x] = src[threadIdx.x];
}

/* batched fp32 -> fp16 rounding (one layer's weights per call)       */
struct RoundJob  { const float* s; __half* d; int n4; };
struct RoundJobs { RoundJob j[16]; };

__global__ void round_w_kernel(RoundJobs js) {
    RoundJob jb = js.j[blockIdx.y];
    const float4* s = (const float4*)jb.s;
    __half2* d = (__half2*)jb.d;
    int stride = gridDim.x*blockDim.x;
    for (int i = blockIdx.x*blockDim.x + threadIdx.x; i < jb.n4; i += stride) {
        float4 v = s[i];
        d[2*i]   = __floats2half2_rn(v.x, v.y);
        d[2*i+1] = __floats2half2_rn(v.z, v.w);
    }
}

/* RMSNorm -> fp16 output. Optionally records raw beacon/forget rows. */
__global__ void rmsnorm_kernel(const float* __restrict__ x,
                               const float* __restrict__ w,
                               __half* __restrict__ y,
                               float* __restrict__ rec_inj,
                               float* __restrict__ rec_fg) {
    int row = blockIdx.x, t = threadIdx.x;
    const float* xr = x + (size_t)row*ND;
    float s = 0.f;
    #pragma unroll
    for (int i = t; i < ND; i += 256) { float v = xr[i]; s += v*v; }
    __shared__ float red[256];
    red[t] = s; __syncthreads();
    for (int st = 128; st > 0; st >>= 1) {
        if (t < st) red[t] += red[t+st];
        __syncthreads();
    }
    float r = rsqrtf(red[0]*(1.f/ND) + 1e-5f);
    __half* yr = y + (size_t)row*ND;
    float* dst = 0;
    if (rec_inj && row >= NS)
        dst = (row < NS+NM) ? rec_inj + (size_t)(row-NS)*ND
                            : rec_fg  + (size_t)(row-NS-NM)*ND;
    #pragma unroll
    for (int i = t; i < ND; i += 256) {
        float v = xr[i];
        if (dst) dst[i] = v;
        yr[i] = __float2half_rn(v*w[i]*r);
    }
}

/* ------------------------------------------------------------------ */
/* fp16 WMMA GEMM: 128x128 CTA tile, 4 warps (64x64), BK=32, 3-stage  */
/* cp.async. fp16 inputs (11-bit significand, same as tf32), fp32 acc */
/* ------------------------------------------------------------------ */
struct GemmDesc  { const __half* A; const __half* B; float* C; };
struct GemmBatch { GemmDesc d[12]; unsigned char yd[40]; unsigned char yr[40]; };

typedef wmma::fragment<wmma::matrix_a, 16,16,16, __half, wmma::row_major> HFragA;
typedef wmma::fragment<wmma::matrix_b, 16,16,16, __half, wmma::row_major> HFragB;
typedef wmma::fragment<wmma::accumulator, 16,16,16, float> HFragC;

#define GSTAGES 3
#define HA_STRIDE 40           /* halves */
#define HB_STRIDE 136
#define HA_TILE (128*HA_STRIDE)
#define HB_TILE (32*HB_STRIDE)
#define GSMEM_BYTES (GSTAGES*(HA_TILE + HB_TILE)*2)    /* 56832 */

__device__ __forceinline__ void cp16(uint32_t dst, const void* src) {
    asm volatile("cp.async.cg.shared.global [%0], [%1], 16;" :: "r"(dst), "l"(src));
}
__device__ __forceinline__ void cp_commit() {
    asm volatile("cp.async.commit_group;");
}
__device__ __forceinline__ void cp_wait1() {
    asm volatile("cp.async.wait_group 1;");
}

__device__ __forceinline__ void gemm_core(const __half* __restrict__ A,
                                          const __half* __restrict__ B,
                                          float* __restrict__ C,
                                          int N, int K, int beta, int rowblk) {
    extern __shared__ __half smh[];
    __half* Asm = smh;
    __half* Bsm = smh + GSTAGES*HA_TILE;

    int tid = threadIdx.x;
    int wid = tid >> 5;
    int wy  = wid >> 1;
    int wx  = wid & 1;
    size_t brow = (size_t)rowblk * 128;
    size_t bcol = (size_t)blockIdx.x * 128;

    /* A: 128x32 halves; thread -> rows ar+32i (i<4), 8-half chunk ac */
    int ar = tid >> 2, ac = (tid & 3) << 3;
    /* B: 32x128 halves; thread -> rows br+8i (i<4), chunk bc         */
    int br = tid >> 4, bc = (tid & 15) << 3;

    const __half* Ag = A + (brow + ar)*K + ac;
    const __half* Bg = B + (size_t)br*N + bcol + bc;

    uint32_t sA = (uint32_t)__cvta_generic_to_shared(Asm + ar*HA_STRIDE + ac);
    uint32_t sB = (uint32_t)__cvta_generic_to_shared(Bsm + br*HB_STRIDE + bc);
    const uint32_t aStageB = HA_TILE*2;
    const uint32_t bStageB = HB_TILE*2;

    int nt = K >> 5;

    #pragma unroll
    for (int s = 0; s < 2; s++) {
        int k0 = s << 5;
        #pragma unroll
        for (int i = 0; i < 4; i++)
            cp16(sA + s*aStageB + i*32*HA_STRIDE*2, Ag + k0 + (size_t)(32*i)*K);
        #pragma unroll
        for (int i = 0; i < 4; i++)
            cp16(sB + s*bStageB + i*8*HB_STRIDE*2, Bg + (size_t)(k0 + 8*i)*N);
        cp_commit();
    }

    HFragC acc[4][4];
    #pragma unroll
    for (int mi = 0; mi < 4; mi++)
        #pragma unroll
        for (int ni = 0; ni < 4; ni++)
            wmma::fill_fragment(acc[mi][ni], 0.f);

    int st = 0, ld = 2;
    for (int kt = 0; kt < nt; kt++) {
        cp_wait1();
        __syncthreads();
        if (kt + 2 < nt) {
            int k0 = (kt + 2) << 5;
            #pragma unroll
            for (int i = 0; i < 4; i++)
                cp16(sA + ld*aStageB + i*32*HA_STRIDE*2, Ag + k0 + (size_t)(32*i)*K);
            #pragma unroll
            for (int i = 0; i < 4; i++)
                cp16(sB + ld*bStageB + i*8*HB_STRIDE*2, Bg + (size_t)(k0 + 8*i)*N);
        }
        cp_commit();

        const __half* Ast = Asm + st*HA_TILE;
        const __half* Bst = Bsm + st*HB_TILE;
        #pragma unroll
        for (int kk = 0; kk < 32; kk += 16) {
            HFragA af[4];
            HFragB bf[4];
            #pragma unroll
            for (int mi = 0; mi < 4; mi++)
                wmma::load_matrix_sync(af[mi], Ast + (wy*64 + mi*16)*HA_STRIDE + kk, HA_STRIDE);
            #pragma unroll
            for (int ni = 0; ni < 4; ni++)
                wmma::load_matrix_sync(bf[ni], Bst + kk*HB_STRIDE + wx*64 + ni*16, HB_STRIDE);
            #pragma unroll
            for (int mi = 0; mi < 4; mi++)
                #pragma unroll
                for (int ni = 0; ni < 4; ni++)
                    wmma::mma_sync(acc[mi][ni], af[mi], bf[ni], acc[mi][ni]);
        }
        st++; if (st == GSTAGES) st = 0;
        ld++; if (ld == GSTAGES) ld = 0;
    }

    #pragma unroll
    for (int mi = 0; mi < 4; mi++)
        #pragma unroll
        for (int ni = 0; ni < 4; ni++) {
            float* cp = C + (brow + wy*64 + mi*16)*N + bcol + wx*64 + ni*16;
            if (beta) {
                HFragC cf;
                wmma::load_matrix_sync(cf, cp, N, wmma::mem_row_major);
                #pragma unroll
                for (int t = 0; t < cf.num_elements; t++)
                    acc[mi][ni].x[t] += cf.x[t];
            }
            wmma::store_matrix_sync(cp, acc[mi][ni], N, wmma::mem_row_major);
        }
}

__global__ __launch_bounds__(128, 2)
void sgemm_kernel(const __half* A, const __half* B, float* C, int N, int K, int beta) {
    gemm_core(A, B, C, N, K, beta, blockIdx.y);
}
__global__ __launch_bounds__(128, 2)
void sgemm_batch_kernel(GemmBatch bat, int N, int K, int beta) {
    int y = blockIdx.y;
    GemmDesc dsc = bat.d[bat.yd[y]];
    gemm_core(dsc.A, dsc.B, dsc.C, N, K, beta, bat.yr[y]);
}

/* ------------------------------------------------------------------ */
/* WMMA flash attention (3x tf32 hi/lo split) with fused RoPE.        */
/* Output written as fp16 (feeds Wo GEMM).                            */
/* ------------------------------------------------------------------ */
#define AT_STRIDE 68
#define AT_TILE   (64*AT_STRIDE)
#define ATTN_SMEM ((5*AT_TILE + 128)*4)

typedef wmma::fragment<wmma::matrix_a, 16,16,8, wmma::precision::tf32, wmma::row_major> FragA;
typedef wmma::fragment<wmma::matrix_b, 16,16,8, wmma::precision::tf32, wmma::row_major> FragB;
typedef wmma::fragment<wmma::matrix_b, 16,16,8, wmma::precision::tf32, wmma::col_major> FragBc;
typedef wmma::fragment<wmma::accumulator, 16,16,8, float> FragC;

template<class F>
__device__ __forceinline__ void split_frag(const F& raw, F& hi, F& lo) {
    #pragma unroll
    for (int t = 0; t < raw.num_elements; t++) {
        float x = raw.x[t];
        float h = wmma::__float_to_tf32(x);
        hi.x[t] = h;
        lo.x[t] = wmma::__float_to_tf32(x - h);
    }
}

__global__ __launch_bounds__(128)
void attn_kernel(const float* Q, size_t qz,
                 const float* K1, const float* V1, int n1,
                 const float* K2, const float* V2, size_t kz, int n2,
                 __half* O, size_t oz, int coff) {
    extern __shared__ float sm[];
    float* Qs = sm;
    float* Ks = sm +   AT_TILE;
    float* Vs = sm + 2*AT_TILE;
    float* Ss = sm + 3*AT_TILE;
    float* Os = sm + 4*AT_TILE;
    float* mrow = sm + 5*AT_TILE;
    float* lrow = mrow + 64;

    int z = blockIdx.z;
    Q  += (size_t)z*qz;  K2 += (size_t)z*kz;
    V2 += (size_t)z*kz;  O  += (size_t)z*oz;
    int h  = blockIdx.y;
    int q0 = blockIdx.x*64;
    int tid = threadIdx.x;
    int wid = tid >> 5;
    int r2  = tid >> 1;
    int hf  = tid & 1;
    float sgn = hf ? 1.f : -1.f;

    /* Q load + RoPE + zero O, init m/l */
    {
        float qv[32], cs[32], sn[32];
        const float4* qp = (const float4*)(Q + (size_t)(q0+r2)*ND + h*64 + hf*32);
        #pragma unroll
        for (int i = 0; i < 8; i++) {
            float4 t = qp[i];
            qv[4*i]=t.x; qv[4*i+1]=t.y; qv[4*i+2]=t.z; qv[4*i+3]=t.w;
        }
        int pos = coff + q0 + r2;
        const float4* c4 = (const float4*)(g_cs + pos*32);
        const float4* s4 = (const float4*)(g_sn + pos*32);
        #pragma unroll
        for (int i = 0; i < 8; i++) {
            float4 a = c4[i]; cs[4*i]=a.x; cs[4*i+1]=a.y; cs[4*i+2]=a.z; cs[4*i+3]=a.w;
            float4 b = s4[i]; sn[4*i]=b.x; sn[4*i+1]=b.y; sn[4*i+2]=b.z; sn[4*i+3]=b.w;
        }
        float* qd = Qs + r2*AT_STRIDE + hf*32;
        float* od = Os + r2*AT_STRIDE + hf*32;
        #pragma unroll
        for (int c = 0; c < 32; c++) {
            float o = __shfl_xor_sync(0xffffffffu, qv[c], 1);
            qd[c] = qv[c]*cs[c] + sgn*o*sn[c];
            od[c] = 0.f;
        }
        if (tid < 64) { mrow[tid] = -1e30f; lrow[tid] = 0.f; }
    }
    __syncthreads();

    int ntot = n1 + n2;
    int kmax = ntot;
    int vis  = q0 + 64 + coff;
    if (vis < kmax) kmax = vis;

    for (int t0 = 0; t0 < kmax; t0 += 64) {
        {
            int kk = t0 + r2;
            const float *kp, *vp; int pos;
            if (kk < n1) { kp = K1 + (size_t)kk*ND; vp = V1 + (size_t)kk*ND; pos = kk; }
            else { int r = kk - n1; kp = K2 + (size_t)r*ND; vp = V2 + (size_t)r*ND; pos = coff + r; }
            kp += h*64 + hf*32; vp += h*64 + hf*32;
            float kv[32], cs[32], sn[32];
            float4* vd = (float4*)(Vs + r2*AT_STRIDE + hf*32);
            #pragma unroll
            for (int i = 0; i < 8; i++) {
                float4 t = ((const float4*)kp)[i];
                kv[4*i]=t.x; kv[4*i+1]=t.y; kv[4*i+2]=t.z; kv[4*i+3]=t.w;
                vd[i] = ((const float4*)vp)[i];
            }
            const float4* c4 = (const float4*)(g_cs + pos*32);
            const float4* s4 = (const float4*)(g_sn + pos*32);
            #pragma unroll
            for (int i = 0; i < 8; i++) {
                float4 a = c4[i]; cs[4*i]=a.x; cs[4*i+1]=a.y; cs[4*i+2]=a.z; cs[4*i+3]=a.w;
                float4 b = s4[i]; sn[4*i]=b.x; sn[4*i+1]=b.y; sn[4*i+2]=b.z; sn[4*i+3]=b.w;
            }
            float* kd = Ks + r2*AT_STRIDE + hf*32;
            #pragma unroll
            for (int c = 0; c < 32; c++) {
                float o = __shfl_xor_sync(0xffffffffu, kv[c], 1);
                kd[c] = kv[c]*cs[c] + sgn*o*sn[c];
            }
        }
        __syncthreads();

        {
            FragC sacc[4];
            #pragma unroll
            for (int ni = 0; ni < 4; ni++) wmma::fill_fragment(sacc[ni], 0.f);
            #pragma unroll
            for (int ks = 0; ks < 8; ks++) {
                FragA araw, ah, al;
                wmma::load_matrix_sync(araw, Qs + (wid*16)*AT_STRIDE + ks*8, AT_STRIDE);
                split_frag(araw, ah, al);
                #pragma unroll
                for (int ni = 0; ni < 4; ni++) {
                    FragBc braw, bh, bl;
                    wmma::load_matrix_sync(braw, Ks + (ni*16)*AT_STRIDE + ks*8, AT_STRIDE);
                    split_frag(braw, bh, bl);
                    wmma::mma_sync(sacc[ni], ah, bh, sacc[ni]);
                    wmma::mma_sync(sacc[ni], ah, bl, sacc[ni]);
                    wmma::mma_sync(sacc[ni], al, bh, sacc[ni]);
                }
            }
            #pragma unroll
            for (int ni = 0; ni < 4; ni++)
                wmma::store_matrix_sync(Ss + (wid*16)*AT_STRIDE + ni*16, sacc[ni],
                                        AT_STRIDE, wmma::mem_row_major);
        }
        __syncthreads();

        {
            int moff = q0 + coff - t0;
            int jmax = r2 + moff; if (jmax > 63) jmax = 63;
            float mold = mrow[r2];
            float* srow = Ss + r2*AT_STRIDE + hf*32;
            float sv[32];
            float tmax = -1e30f;
            #pragma unroll
            for (int c = 0; c < 32; c++) {
                int cc = hf*32 + c;
                float s = srow[c]*0.125f;
                sv[c] = s;
                if (cc <= jmax) tmax = fmaxf(tmax, s);
            }
            tmax = fmaxf(tmax, __shfl_xor_sync(0xffffffffu, tmax, 1));
            float mnew = fmaxf(mold, tmax);
            float corr = expf(mold - mnew);
            float psum = 0.f;
            #pragma unroll
            for (int c = 0; c < 32; c++) {
                int cc = hf*32 + c;
                float p = (cc <= jmax) ? expf(sv[c] - mnew) : 0.f;
                srow[c] = p;
                psum += p;
            }
            psum += __shfl_xor_sync(0xffffffffu, psum, 1);
            if (hf == 0) { mrow[r2] = mnew; lrow[r2] = lrow[r2]*corr + psum; }
            float* orow = Os + r2*AT_STRIDE + hf*32;
            #pragma unroll
            for (int c = 0; c < 32; c++) orow[c] *= corr;
        }
        __syncthreads();

        {
            FragC oacc[4];
            #pragma unroll
            for (int ni = 0; ni < 4; ni++)
                wmma::load_matrix_sync(oacc[ni], Os + (wid*16)*AT_STRIDE + ni*16,
                                       AT_STRIDE, wmma::mem_row_major);
            #pragma unroll
            for (int ks = 0; ks < 8; ks++) {
                FragA praw, ph, pl;
                wmma::load_matrix_sync(praw, Ss + (wid*16)*AT_STRIDE + ks*8, AT_STRIDE);
                split_frag(praw, ph, pl);
                #pragma unroll
                for (int ni = 0; ni < 4; ni++) {
                    FragB vraw, vh, vl;
                    wmma::load_matrix_sync(vraw, Vs + (ks*8)*AT_STRIDE + ni*16, AT_STRIDE);
                    split_frag(vraw, vh, vl);
                    wmma::mma_sync(oacc[ni], ph, vh, oacc[ni]);
                    wmma::mma_sync(oacc[ni], ph, vl, oacc[ni]);
                    wmma::mma_sync(oacc[ni], pl, vh, oacc[ni]);
                }
            }
            #pragma unroll
            for (int ni = 0; ni < 4; ni++)
                wmma::store_matrix_sync(Os + (wid*16)*AT_STRIDE + ni*16, oacc[ni],
                                        AT_STRIDE, wmma::mem_row_major);
        }
        __syncthreads();
    }

    {
        float invl = 1.f/lrow[r2];
        const float* orow = Os + r2*AT_STRIDE + hf*32;
        __half* op = O + (size_t)(q0+r2)*ND + h*64 + hf*32;
        #pragma unroll
        for (int c = 0; c < 32; c++) op[c] = __float2half_rn(orow[c]*invl);
    }
}

/* ------------------------------------------------------------------ */
__global__ void silumul_kernel(const float* __restrict__ a, const float* __restrict__ b,
                               __half* __restrict__ o, int n) {
    int i = blockIdx.x*blockDim.x + threadIdx.x;
    if (i >= n) return;
    float g = a[i];
    o[i] = __float2half_rn((g / (1.f + expf(-g))) * b[i]);
}

__global__ void gate_out_kernel(const float* __restrict__ mem,
                                const float* __restrict__ inj,
                                const float* __restrict__ fg,
                                float* __restrict__ out, int n) {
    int i = blockIdx.x*blockDim.x + threadIdx.x;
    if (i >= n) return;
    float g = 1.f / (1.f + expf(-fg[i]));
    out[i] = mem[i]*g + inj[i]*(1.f - g);
}

/* ================================================================== */
extern "C" void kernel_launch(void* const* d_in, const int* in_sizes, int n_in,
                              void* d_out, int out_size) {
    const int*   ids    = (const int*)d_in[0];
    const float* memory = (const float*)d_in[1];
    const float* beacon = (const float*)d_in[2];
    const float* forget = (const float*)d_in[3];
    const float* embed  = (const float*)d_in[4];
    const float* ln1    = (const float*)d_in[5];
    const float* ln2    = (const float*)d_in[6];
    const float* Wq  = (const float*)d_in[7];
    const float* Wk  = (const float*)d_in[8];
    const float* Wv  = (const float*)d_in[9];
    const float* Wo  = (const float*)d_in[10];
    const float* mWk = (const float*)d_in[11];
    const float* mWv = (const float*)d_in[12];
    const float* bWq = (const float*)d_in[13];
    const float* bWk = (const float*)d_in[14];
    const float* bWv = (const float*)d_in[15];
    const float* fWq = (const float*)d_in[16];
    const float* fWk = (const float*)d_in[17];
    const float* fWv = (const float*)d_in[18];
    const float* Wg  = (const float*)d_in[19];
    const float* Wu  = (const float*)d_in[20];
    const float* Wd  = (const float*)d_in[21];

    static int attr_set = 0;
    static cudaStream_t s2;
    static cudaEvent_t eA, eB, eC;
    if (!attr_set) {
        cudaFuncSetAttribute(sgemm_kernel, cudaFuncAttributeMaxDynamicSharedMemorySize, GSMEM_BYTES);
        cudaFuncSetAttribute(sgemm_batch_kernel, cudaFuncAttributeMaxDynamicSharedMemorySize, GSMEM_BYTES);
        cudaFuncSetAttribute(attn_kernel, cudaFuncAttributeMaxDynamicSharedMemorySize, ATTN_SMEM);
        cudaStreamCreateWithFlags(&s2, cudaStreamNonBlocking);
        cudaEventCreateWithFlags(&eA, cudaEventDisableTiming);
        cudaEventCreateWithFlags(&eB, cudaEventDisableTiming);
        cudaEventCreateWithFlags(&eC, cudaEventDisableTiming);
        attr_set = 1;
    }

    float *cat,*q,*k,*v,*qbf,*kbf,*vbf,*m1,*m2,*inj,*fg;
    __half *xh,*atth,*m1h,*memh;
    __half *wq,*wk,*wv,*wo,*mwk,*mwv,*bwq,*bwk,*bwv,*fwq,*fwk,*fwv,*wg,*wu,*wd;
    cudaGetSymbolAddress((void**)&cat, g_cat);
    cudaGetSymbolAddress((void**)&xh,  g_xh);
    cudaGetSymbolAddress((void**)&q,   g_q);
    cudaGetSymbolAddress((void**)&k,   g_k);
    cudaGetSymbolAddress((void**)&v,   g_v);
    cudaGetSymbolAddress((void**)&qbf, g_qbf);
    cudaGetSymbolAddress((void**)&kbf, g_kbf);
    cudaGetSymbolAddress((void**)&vbf, g_vbf);
    cudaGetSymbolAddress((void**)&atth,g_atth);
    cudaGetSymbolAddress((void**)&m1,  g_m1);
    cudaGetSymbolAddress((void**)&m2,  g_m2);
    cudaGetSymbolAddress((void**)&m1h, g_m1h);
    cudaGetSymbolAddress((void**)&inj, g_inj);
    cudaGetSymbolAddress((void**)&fg,  g_fg);
    cudaGetSymbolAddress((void**)&memh,g_memh);
    cudaGetSymbolAddress((void**)&wq,  g_wq);
    cudaGetSymbolAddress((void**)&wk,  g_wk);
    cudaGetSymbolAddress((void**)&wv,  g_wv);
    cudaGetSymbolAddress((void**)&wo,  g_wo);
    cudaGetSymbolAddress((void**)&mwk, g_mwk);
    cudaGetSymbolAddress((void**)&mwv, g_mwv);
    cudaGetSymbolAddress((void**)&bwq, g_bwq);
    cudaGetSymbolAddress((void**)&bwk, g_bwk);
    cudaGetSymbolAddress((void**)&bwv, g_bwv);
    cudaGetSymbolAddress((void**)&fwq, g_fwq);
    cudaGetSymbolAddress((void**)&fwk, g_fwk);
    cudaGetSymbolAddress((void**)&fwv, g_fwv);
    cudaGetSymbolAddress((void**)&wg,  g_wg);
    cudaGetSymbolAddress((void**)&wu,  g_wu);
    cudaGetSymbolAddress((void**)&wd,  g_wd);

    const size_t RECB = (size_t)NM*ND*sizeof(float);
    const size_t wdd = (size_t)ND*ND;
    const int DD4 = ND*ND/4, DF4 = ND*NF/4, MEM4 = NM*ND/4;

    auto round_layer = [&](int l, cudaStream_t st) {
        RoundJobs js;
        js.j[0]  = { Wq  + l*wdd, wq  + l*wdd, DD4 };
        js.j[1]  = { Wk  + l*wdd, wk  + l*wdd, DD4 };
        js.j[2]  = { Wv  + l*wdd, wv  + l*wdd, DD4 };
        js.j[3]  = { Wo  + l*wdd, wo  + l*wdd, DD4 };
        js.j[4]  = { mWk + l*wdd, mwk + l*wdd, DD4 };
        js.j[5]  = { mWv + l*wdd, mwv + l*wdd, DD4 };
        js.j[6]  = { bWq + l*wdd, bwq + l*wdd, DD4 };
        js.j[7]  = { bWk + l*wdd, bwk + l*wdd, DD4 };
        js.j[8]  = { bWv + l*wdd, bwv + l*wdd, DD4 };
        js.j[9]  = { fWq + l*wdd, fwq + l*wdd, DD4 };
        js.j[10] = { fWk + l*wdd, fwk + l*wdd, DD4 };
        js.j[11] = { fWv + l*wdd, fwv + l*wdd, DD4 };
        js.j[12] = { Wg + (size_t)l*ND*NF, wg + (size_t)l*ND*NF, DF4 };
        js.j[13] = { Wu + (size_t)l*ND*NF, wu + (size_t)l*ND*NF, DF4 };
        js.j[14] = { Wd + (size_t)l*NF*ND, wd + (size_t)l*NF*ND, DF4 };
        js.j[15] = { memory + (size_t)l*NM*ND, memh + (size_t)l*NM*ND, MEM4 };
        round_w_kernel<<<dim3(256, 16), 256, 0, st>>>(js);
    };

    init_tables_kernel<<<(NPOS*32+255)/256, 256>>>();
    gather_kernel<<<NS, 256>>>(ids, embed, cat);
    round_layer(0, 0);
    cudaMemcpyAsync(cat + (size_t)NS*ND,      beacon, RECB, cudaMemcpyDeviceToDevice, 0);
    cudaMemcpyAsync(cat + (size_t)(NS+NM)*ND, forget, RECB, cudaMemcpyDeviceToDevice, 0);

    for (int l = 0; l < 7; l++) {
        const __half* Wq_l  = wq  + l*wdd;  const __half* Wk_l  = wk  + l*wdd;
        const __half* Wv_l  = wv  + l*wdd;  const __half* Wo_l  = wo  + l*wdd;
        const __half* mWk_l = mwk + l*wdd;  const __half* mWv_l = mwv + l*wdd;
        const __half* bWq_l = bwq + l*wdd;  const __half* bWk_l = bwk + l*wdd;
        const __half* bWv_l = bwv + l*wdd;  const __half* fWq_l = fwq + l*wdd;
        const __half* fWk_l = fwk + l*wdd;  const __half* fWv_l = fwv + l*wdd;
        const __half* Wg_l  = wg + (size_t)l*ND*NF;
        const __half* Wu_l  = wu + (size_t)l*ND*NF;
        const __half* Wd_l  = wd + (size_t)l*NF*ND;
        const __half* mem_l = memh + (size_t)l*NM*ND;
        const bool last = (l == 6);

        if (l > 0) cudaStreamWaitEvent(0, eC, 0);

        rmsnorm_kernel<<<NCAT, 256>>>(cat, ln1 + (size_t)l*ND, xh,
                                      inj + (size_t)l*NM*ND, fg + (size_t)l*NM*ND);

        {
            GemmBatch ba; int nb = 0, ny = 0;
            const __half* bx = xh + (size_t)NS*ND;
            const __half* fx = xh + (size_t)(NS+NM)*ND;
            int nrbs[12];
            if (!last) { ba.d[nb] = { xh, Wq_l, q }; nrbs[nb++] = 8; }
            ba.d[nb] = { xh, Wk_l, k + (size_t)NM*ND }; nrbs[nb++] = 8;
            ba.d[nb] = { xh, Wv_l, v + (size_t)NM*ND }; nrbs[nb++] = 8;
            ba.d[nb] = { mem_l, mWk_l, k };   nrbs[nb++] = 1;
            ba.d[nb] = { mem_l, mWv_l, v };   nrbs[nb++] = 1;
            ba.d[nb] = { bx, bWq_l, qbf };    nrbs[nb++] = 1;
            ba.d[nb] = { bx, bWk_l, kbf };    nrbs[nb++] = 1;
            ba.d[nb] = { bx, bWv_l, vbf };    nrbs[nb++] = 1;
            ba.d[nb] = { fx, fWq_l, qbf + (size_t)NM*ND }; nrbs[nb++] = 1;
            ba.d[nb] = { fx, fWk_l, kbf + (size_t)NM*ND }; nrbs[nb++] = 1;
            ba.d[nb] = { fx, fWv_l, vbf + (size_t)NM*ND }; nrbs[nb++] = 1;
            for (int di = 0; di < nb; di++)
                for (int rb = 0; rb < nrbs[di]; rb++) {
                    ba.yd[ny] = (unsigned char)di;
                    ba.yr[ny] = (unsigned char)rb; ny++;
                }
            sgemm_batch_kernel<<<dim3(8, ny, 1), 128, GSMEM_BYTES>>>(ba, ND, ND, 0);
        }

        /* fork: gates chain on s2, hidden chain on main */
        cudaEventRecord(eA, 0);
        cudaStreamWaitEvent(s2, eA, 0);

        if (!last)
            attn_kernel<<<dim3(NS/64, NH, 1), 128, ATTN_SMEM>>>(q, 0, k, v, NKV,
                                                    k, v, 0, 0, atth, 0, NM);
        attn_kernel<<<dim3(NM/64, NH, 2), 128, ATTN_SMEM, s2>>>(
                                                qbf, (size_t)NM*ND, k, v, NKV,
                                                kbf, vbf, (size_t)NM*ND, NM,
                                                atth + (size_t)NS*ND, (size_t)NM*ND, NKV);
        sgemm_kernel<<<dim3(8, 2), 128, GSMEM_BYTES, s2>>>(atth + (size_t)NS*ND, Wo_l,
                                              cat + (size_t)NS*ND, ND, ND, 1);
        cudaEventRecord(eB, s2);
        if (l + 1 < 7) { round_layer(l + 1, s2); cudaEventRecord(eC, s2); }

        if (!last)
            sgemm_kernel<<<dim3(8, 8), 128, GSMEM_BYTES>>>(atth, Wo_l, cat, ND, ND, 1);
        cudaStreamWaitEvent(0, eB, 0);

        int rows = last ? 2*NM : NCAT;
        size_t off = last ? (size_t)NS*ND : 0;
        rmsnorm_kernel<<<rows, 256>>>(cat + off, ln2 + (size_t)l*ND, xh + off,
                                      (float*)0, (float*)0);
        {
            GemmBatch ga; int ny = 0;
            ga.d[0] = { xh + off, Wg_l, m1 };
            ga.d[1] = { xh + off, Wu_l, m2 };
            for (int di = 0; di < 2; di++)
                for (int rb = 0; rb < rows/128; rb++) {
                    ga.yd[ny] = (unsigned char)di;
                    ga.yr[ny] = (unsigned char)rb; ny++;
                }
            sgemm_batch_kernel<<<dim3(NF/128, ny, 1), 128, GSMEM_BYTES>>>(ga, NF, ND, 0);
        }
        silumul_kernel<<<(rows*NF)/256, 256>>>(m1, m2, m1h, rows*NF);
        sgemm_kernel<<<dim3(8, rows/128), 128, GSMEM_BYTES>>>(m1h, Wd_l, cat + off, ND, NF, 1);
    }

    cudaMemcpyAsync(inj + (size_t)7*NM*ND, cat + (size_t)NS*ND,      RECB, cudaMemcpyDeviceToDevice, 0);
    cudaMemcpyAsync(fg  + (size_t)7*NM*ND, cat + (size_t)(NS+NM)*ND, RECB, cudaMemcpyDeviceToDevice, 0);

    gate_out_kernel<<<(NL*NM*ND)/256, 256>>>(memory, inj, fg, (float*)d_out, NL*NM*ND);
}

// round 14
// speedup vs baseline: 5.3170x; 1.4016x over previous
#include <cuda_runtime.h>
#include <cuda_fp16.h>
#include <math.h>
#include <mma.h>
#include <stdint.h>

using namespace nvcuda;

#define NS   1024
#define NM   128
#define ND   1024
#define NH   16
#define NHD  64
#define NF   2048
#define NL   8
#define NCAT 1280   /* S + 2M */
#define NKV  1152   /* M + S  */
#define NPOS 1280

/* ------------------------------------------------------------------ */
/* scratch (static device arrays; no allocation allowed)              */
/* ------------------------------------------------------------------ */
__device__ float g_cat[NCAT*ND];
__device__ __align__(256) __half g_xh [NCAT*ND];
__device__ float g_q  [NS*ND];
__device__ float g_k  [NKV*ND];
__device__ float g_v  [NKV*ND];
__device__ float g_qbf[2*NM*ND];
__device__ float g_kbf[2*NM*ND];
__device__ float g_vbf[2*NM*ND];
__device__ __align__(256) __half g_atth[NCAT*ND];
__device__ float g_m1 [NCAT*NF];
__device__ float g_m2 [NCAT*NF];
__device__ __align__(256) __half g_m1h[NCAT*NF];
__device__ float g_inj[NL*NM*ND];
__device__ float g_fg [NL*NM*ND];
__device__ __align__(256) __half g_memh[7*NM*ND];
__device__ float g_cs [NPOS*32];
__device__ float g_sn [NPOS*32];

/* pre-rounded fp16 weights, 7 layers each */
#define WDD (7*ND*ND)
#define WDF (7*ND*NF)
__device__ __align__(256) __half g_wq [WDD]; __device__ __align__(256) __half g_wk [WDD];
__device__ __align__(256) __half g_wv [WDD]; __device__ __align__(256) __half g_wo [WDD];
__device__ __align__(256) __half g_mwk[WDD]; __device__ __align__(256) __half g_mwv[WDD];
__device__ __align__(256) __half g_bwq[WDD]; __device__ __align__(256) __half g_bwk[WDD];
__device__ __align__(256) __half g_bwv[WDD]; __device__ __align__(256) __half g_fwq[WDD];
__device__ __align__(256) __half g_fwk[WDD]; __device__ __align__(256) __half g_fwv[WDD];
__device__ __align__(256) __half g_wg [WDF]; __device__ __align__(256) __half g_wu [WDF];
__device__ __align__(256) __half g_wd [WDF];

/* ------------------------------------------------------------------ */
__global__ void init_tables_kernel() {
    int idx = blockIdx.x*blockDim.x + threadIdx.x;
    if (idx >= NPOS*32) return;
    int pos = idx >> 5, j = idx & 31;
    double inv = exp(-((double)(2*j)/64.0) * log(10000.0));
    double a = (double)pos * inv;
    g_cs[idx] = (float)cos(a);
    g_sn[idx] = (float)sin(a);
}

__global__ void gather_kernel(const int* __restrict__ ids,
                              const float* __restrict__ embed,
                              float* __restrict__ out) {
    int row = blockIdx.x;
    int id  = ids[row];
    const float4* src = (const float4*)(embed + (size_t)id*ND);
    float4* dst = (float4*)(out + (size_t)row*ND);
    dst[threadIdx.x] = src[threadIdx.x];
}

/* batched fp32 -> fp16 rounding (one layer's weights per call)       */
struct RoundJob  { const float* s; __half* d; int n4; };
struct RoundJobs { RoundJob j[16]; };

__global__ void round_w_kernel(RoundJobs js) {
    RoundJob jb = js.j[blockIdx.y];
    const float4* s = (const float4*)jb.s;
    __half2* d = (__half2*)jb.d;
    int stride = gridDim.x*blockDim.x;
    for (int i = blockIdx.x*blockDim.x + threadIdx.x; i < jb.n4; i += stride) {
        float4 v = s[i];
        d[2*i]   = __floats2half2_rn(v.x, v.y);
        d[2*i+1] = __floats2half2_rn(v.z, v.w);
    }
}

/* RMSNorm -> fp16 output. Optionally records raw beacon/forget rows. */
__global__ void rmsnorm_kernel(const float* __restrict__ x,
                               const float* __restrict__ w,
                               __half* __restrict__ y,
                               float* __restrict__ rec_inj,
                               float* __restrict__ rec_fg) {
    int row = blockIdx.x, t = threadIdx.x;
    const float* xr = x + (size_t)row*ND;
    float s = 0.f;
    #pragma unroll
    for (int i = t; i < ND; i += 256) { float v = xr[i]; s += v*v; }
    __shared__ float red[256];
    red[t] = s; __syncthreads();
    for (int st = 128; st > 0; st >>= 1) {
        if (t < st) red[t] += red[t+st];
        __syncthreads();
    }
    float r = rsqrtf(red[0]*(1.f/ND) + 1e-5f);
    __half* yr = y + (size_t)row*ND;
    float* dst = 0;
    if (rec_inj && row >= NS)
        dst = (row < NS+NM) ? rec_inj + (size_t)(row-NS)*ND
                            : rec_fg  + (size_t)(row-NS-NM)*ND;
    #pragma unroll
    for (int i = t; i < ND; i += 256) {
        float v = xr[i];
        if (dst) dst[i] = v;
        yr[i] = __float2half_rn(v*w[i]*r);
    }
}

/* ------------------------------------------------------------------ */
/* fp16 WMMA GEMM: 128x128 CTA tile, 4 warps (64x64), BK=32, 3-stage  */
/* cp.async. fp16 inputs (11-bit significand, same as tf32), fp32 acc */
/* ------------------------------------------------------------------ */
struct GemmDesc  { const __half* A; const __half* B; float* C; };
struct GemmBatch { GemmDesc d[12]; unsigned char yd[40]; unsigned char yr[40]; };

typedef wmma::fragment<wmma::matrix_a, 16,16,16, __half, wmma::row_major> HFragA;
typedef wmma::fragment<wmma::matrix_b, 16,16,16, __half, wmma::row_major> HFragB;
typedef wmma::fragment<wmma::matrix_b, 16,16,16, __half, wmma::col_major> HFragBc;
typedef wmma::fragment<wmma::accumulator, 16,16,16, float> HFragC;

#define GSTAGES 3
#define HA_STRIDE 40           /* halves */
#define HB_STRIDE 136
#define HA_TILE (128*HA_STRIDE)
#define HB_TILE (32*HB_STRIDE)
#define GSMEM_BYTES (GSTAGES*(HA_TILE + HB_TILE)*2)    /* 56832 */

__device__ __forceinline__ void cp16(uint32_t dst, const void* src) {
    asm volatile("cp.async.cg.shared.global [%0], [%1], 16;" :: "r"(dst), "l"(src));
}
__device__ __forceinline__ void cp_commit() {
    asm volatile("cp.async.commit_group;");
}
__device__ __forceinline__ void cp_wait1() {
    asm volatile("cp.async.wait_group 1;");
}

__device__ __forceinline__ void gemm_core(const __half* __restrict__ A,
                                          const __half* __restrict__ B,
                                          float* __restrict__ C,
                                          int N, int K, int beta, int rowblk) {
    extern __shared__ __half smh[];
    __half* Asm = smh;
    __half* Bsm = smh + GSTAGES*HA_TILE;

    int tid = threadIdx.x;
    int wid = tid >> 5;
    int wy  = wid >> 1;
    int wx  = wid & 1;
    size_t brow = (size_t)rowblk * 128;
    size_t bcol = (size_t)blockIdx.x * 128;

    int ar = tid >> 2, ac = (tid & 3) << 3;
    int br = tid >> 4, bc = (tid & 15) << 3;

    const __half* Ag = A + (brow + ar)*K + ac;
    const __half* Bg = B + (size_t)br*N + bcol + bc;

    uint32_t sA = (uint32_t)__cvta_generic_to_shared(Asm + ar*HA_STRIDE + ac);
    uint32_t sB = (uint32_t)__cvta_generic_to_shared(Bsm + br*HB_STRIDE + bc);
    const uint32_t aStageB = HA_TILE*2;
    const uint32_t bStageB = HB_TILE*2;

    int nt = K >> 5;

    #pragma unroll
    for (int s = 0; s < 2; s++) {
        int k0 = s << 5;
        #pragma unroll
        for (int i = 0; i < 4; i++)
            cp16(sA + s*aStageB + i*32*HA_STRIDE*2, Ag + k0 + (size_t)(32*i)*K);
        #pragma unroll
        for (int i = 0; i < 4; i++)
            cp16(sB + s*bStageB + i*8*HB_STRIDE*2, Bg + (size_t)(k0 + 8*i)*N);
        cp_commit();
    }

    HFragC acc[4][4];
    #pragma unroll
    for (int mi = 0; mi < 4; mi++)
        #pragma unroll
        for (int ni = 0; ni < 4; ni++)
            wmma::fill_fragment(acc[mi][ni], 0.f);

    int st = 0, ld = 2;
    for (int kt = 0; kt < nt; kt++) {
        cp_wait1();
        __syncthreads();
        if (kt + 2 < nt) {
            int k0 = (kt + 2) << 5;
            #pragma unroll
            for (int i = 0; i < 4; i++)
                cp16(sA + ld*aStageB + i*32*HA_STRIDE*2, Ag + k0 + (size_t)(32*i)*K);
            #pragma unroll
            for (int i = 0; i < 4; i++)
                cp16(sB + ld*bStageB + i*8*HB_STRIDE*2, Bg + (size_t)(k0 + 8*i)*N);
        }
        cp_commit();

        const __half* Ast = Asm + st*HA_TILE;
        const __half* Bst = Bsm + st*HB_TILE;
        #pragma unroll
        for (int kk = 0; kk < 32; kk += 16) {
            HFragA af[4];
            HFragB bf[4];
            #pragma unroll
            for (int mi = 0; mi < 4; mi++)
                wmma::load_matrix_sync(af[mi], Ast + (wy*64 + mi*16)*HA_STRIDE + kk, HA_STRIDE);
            #pragma unroll
            for (int ni = 0; ni < 4; ni++)
                wmma::load_matrix_sync(bf[ni], Bst + kk*HB_STRIDE + wx*64 + ni*16, HB_STRIDE);
            #pragma unroll
            for (int mi = 0; mi < 4; mi++)
                #pragma unroll
                for (int ni = 0; ni < 4; ni++)
                    wmma::mma_sync(acc[mi][ni], af[mi], bf[ni], acc[mi][ni]);
        }
        st++; if (st == GSTAGES) st = 0;
        ld++; if (ld == GSTAGES) ld = 0;
    }

    #pragma unroll
    for (int mi = 0; mi < 4; mi++)
        #pragma unroll
        for (int ni = 0; ni < 4; ni++) {
            float* cp = C + (brow + wy*64 + mi*16)*N + bcol + wx*64 + ni*16;
            if (beta) {
                HFragC cf;
                wmma::load_matrix_sync(cf, cp, N, wmma::mem_row_major);
                #pragma unroll
                for (int t = 0; t < cf.num_elements; t++)
                    acc[mi][ni].x[t] += cf.x[t];
            }
            wmma::store_matrix_sync(cp, acc[mi][ni], N, wmma::mem_row_major);
        }
}

__global__ __launch_bounds__(128, 2)
void sgemm_kernel(const __half* A, const __half* B, float* C, int N, int K, int beta) {
    gemm_core(A, B, C, N, K, beta, blockIdx.y);
}
__global__ __launch_bounds__(128, 2)
void sgemm_batch_kernel(GemmBatch bat, int N, int K, int beta) {
    int y = blockIdx.y;
    GemmDesc dsc = bat.d[bat.yd[y]];
    gemm_core(dsc.A, dsc.B, dsc.C, N, K, beta, bat.yr[y]);
}

/* ------------------------------------------------------------------ */
/* fp16 WMMA flash attention with fused RoPE.                         */
/* QK^T: fp16 hi/lo split (22-bit effective) -> fp32-grade scores.    */
/* PV:   plain fp16 (P in [0,1], V already carries 2.4e-4 rounding).  */
/* Softmax and O-rescale in fp32.                                     */
/* ------------------------------------------------------------------ */
#define HSTR 72                    /* halves per row (64 + 8 pad)     */
#define HT   (64*HSTR)             /* one half tile                   */
#define FSTR 68
#define FT   (64*FSTR)
#define ATTN_SMEM (6*HT*2 + 2*FT*4 + 512)   /* 90624 B */

typedef wmma::fragment<wmma::matrix_a, 16,16,16, __half, wmma::row_major> AFragA;
typedef wmma::fragment<wmma::matrix_b, 16,16,16, __half, wmma::col_major> AFragBc;
typedef wmma::fragment<wmma::matrix_b, 16,16,16, __half, wmma::row_major> AFragB;
typedef wmma::fragment<wmma::accumulator, 16,16,16, float> AFragC;

__global__ __launch_bounds__(128)
void attn_kernel(const float* Q, size_t qz,
                 const float* K1, const float* V1, int n1,
                 const float* K2, const float* V2, size_t kz, int n2,
                 __half* O, size_t oz, int coff) {
    extern __shared__ char smc[];
    __half* Qhi = (__half*)smc;
    __half* Qlo = Qhi + HT;
    __half* Khi = Qlo + HT;
    __half* Klo = Khi + HT;
    __half* Vh  = Klo + HT;
    __half* Ph  = Vh  + HT;
    float*  Ss  = (float*)(Ph + HT);
    float*  Os  = Ss + FT;
    float*  mrow = Os + FT;
    float*  lrow = mrow + 64;

    int z = blockIdx.z;
    Q  += (size_t)z*qz;  K2 += (size_t)z*kz;
    V2 += (size_t)z*kz;  O  += (size_t)z*oz;
    int h  = blockIdx.y;
    int q0 = blockIdx.x*64;
    int tid = threadIdx.x;
    int wid = tid >> 5;
    int r2  = tid >> 1;
    int hf  = tid & 1;
    float sgn = hf ? 1.f : -1.f;

    /* Q load + RoPE + hi/lo split; zero O; init m/l */
    {
        float qv[32], cs[32], sn[32];
        const float4* qp = (const float4*)(Q + (size_t)(q0+r2)*ND + h*64 + hf*32);
        #pragma unroll
        for (int i = 0; i < 8; i++) {
            float4 t = qp[i];
            qv[4*i]=t.x; qv[4*i+1]=t.y; qv[4*i+2]=t.z; qv[4*i+3]=t.w;
        }
        int pos = coff + q0 + r2;
        const float4* c4 = (const float4*)(g_cs + pos*32);
        const float4* s4 = (const float4*)(g_sn + pos*32);
        #pragma unroll
        for (int i = 0; i < 8; i++) {
            float4 a = c4[i]; cs[4*i]=a.x; cs[4*i+1]=a.y; cs[4*i+2]=a.z; cs[4*i+3]=a.w;
            float4 b = s4[i]; sn[4*i]=b.x; sn[4*i+1]=b.y; sn[4*i+2]=b.z; sn[4*i+3]=b.w;
        }
        __half* qhd = Qhi + r2*HSTR + hf*32;
        __half* qld = Qlo + r2*HSTR + hf*32;
        float* od = Os + r2*FSTR + hf*32;
        #pragma unroll
        for (int c = 0; c < 32; c++) {
            float o = __shfl_xor_sync(0xffffffffu, qv[c], 1);
            float x = qv[c]*cs[c] + sgn*o*sn[c];
            __half hx = __float2half_rn(x);
            qhd[c] = hx;
            qld[c] = __float2half_rn(x - __half2float(hx));
            od[c] = 0.f;
        }
        if (tid < 64) { mrow[tid] = -1e30f; lrow[tid] = 0.f; }
    }
    __syncthreads();

    int ntot = n1 + n2;
    int kmax = ntot;
    int vis  = q0 + 64 + coff;
    if (vis < kmax) kmax = vis;

    for (int t0 = 0; t0 < kmax; t0 += 64) {
        /* K/V tile load; K gets RoPE + hi/lo split, V plain fp16 */
        {
            int kk = t0 + r2;
            const float *kp, *vp; int pos;
            if (kk < n1) { kp = K1 + (size_t)kk*ND; vp = V1 + (size_t)kk*ND; pos = kk; }
            else { int r = kk - n1; kp = K2 + (size_t)r*ND; vp = V2 + (size_t)r*ND; pos = coff + r; }
            kp += h*64 + hf*32; vp += h*64 + hf*32;
            float kv[32], cs[32], sn[32];
            __half* vd = Vh + r2*HSTR + hf*32;
            #pragma unroll
            for (int i = 0; i < 8; i++) {
                float4 t = ((const float4*)kp)[i];
                kv[4*i]=t.x; kv[4*i+1]=t.y; kv[4*i+2]=t.z; kv[4*i+3]=t.w;
                float4 vv = ((const float4*)vp)[i];
                vd[4*i]   = __float2half_rn(vv.x);
                vd[4*i+1] = __float2half_rn(vv.y);
                vd[4*i+2] = __float2half_rn(vv.z);
                vd[4*i+3] = __float2half_rn(vv.w);
            }
            const float4* c4 = (const float4*)(g_cs + pos*32);
            const float4* s4 = (const float4*)(g_sn + pos*32);
            #pragma unroll
            for (int i = 0; i < 8; i++) {
                float4 a = c4[i]; cs[4*i]=a.x; cs[4*i+1]=a.y; cs[4*i+2]=a.z; cs[4*i+3]=a.w;
                float4 b = s4[i]; sn[4*i]=b.x; sn[4*i+1]=b.y; sn[4*i+2]=b.z; sn[4*i+3]=b.w;
            }
            __half* khd = Khi + r2*HSTR + hf*32;
            __half* kld = Klo + r2*HSTR + hf*32;
            #pragma unroll
            for (int c = 0; c < 32; c++) {
                float o = __shfl_xor_sync(0xffffffffu, kv[c], 1);
                float x = kv[c]*cs[c] + sgn*o*sn[c];
                __half hx = __float2half_rn(x);
                khd[c] = hx;
                kld[c] = __float2half_rn(x - __half2float(hx));
            }
        }
        __syncthreads();

        /* S = Q @ K^T  (3-term fp16 hi/lo) */
        {
            AFragC sacc[4];
            #pragma unroll
            for (int ni = 0; ni < 4; ni++) wmma::fill_fragment(sacc[ni], 0.f);
            #pragma unroll
            for (int ks = 0; ks < 4; ks++) {
                AFragA ah, al;
                wmma::load_matrix_sync(ah, Qhi + (wid*16)*HSTR + ks*16, HSTR);
                wmma::load_matrix_sync(al, Qlo + (wid*16)*HSTR + ks*16, HSTR);
                #pragma unroll
                for (int ni = 0; ni < 4; ni++) {
                    AFragBc bh, bl;
                    wmma::load_matrix_sync(bh, Khi + (ni*16)*HSTR + ks*16, HSTR);
                    wmma::load_matrix_sync(bl, Klo + (ni*16)*HSTR + ks*16, HSTR);
                    wmma::mma_sync(sacc[ni], ah, bh, sacc[ni]);
                    wmma::mma_sync(sacc[ni], ah, bl, sacc[ni]);
                    wmma::mma_sync(sacc[ni], al, bh, sacc[ni]);
                }
            }
            #pragma unroll
            for (int ni = 0; ni < 4; ni++)
                wmma::store_matrix_sync(Ss + (wid*16)*FSTR + ni*16, sacc[ni],
                                        FSTR, wmma::mem_row_major);
        }
        __syncthreads();

        /* online softmax (fp32) -> P fp16 */
        {
            int moff = q0 + coff - t0;
            int jmax = r2 + moff; if (jmax > 63) jmax = 63;
            float mold = mrow[r2];
            float* srow = Ss + r2*FSTR + hf*32;
            __half* prow = Ph + r2*HSTR + hf*32;
            float sv[32];
            float tmax = -1e30f;
            #pragma unroll
            for (int c = 0; c < 32; c++) {
                int cc = hf*32 + c;
                float s = srow[c]*0.125f;
                sv[c] = s;
                if (cc <= jmax) tmax = fmaxf(tmax, s);
            }
            tmax = fmaxf(tmax, __shfl_xor_sync(0xffffffffu, tmax, 1));
            float mnew = fmaxf(mold, tmax);
            float corr = expf(mold - mnew);
            float psum = 0.f;
            #pragma unroll
            for (int c = 0; c < 32; c++) {
                int cc = hf*32 + c;
                float p = (cc <= jmax) ? expf(sv[c] - mnew) : 0.f;
                prow[c] = __float2half_rn(p);
                psum += p;
            }
            psum += __shfl_xor_sync(0xffffffffu, psum, 1);
            if (hf == 0) { mrow[r2] = mnew; lrow[r2] = lrow[r2]*corr + psum; }
            float* orow = Os + r2*FSTR + hf*32;
            #pragma unroll
            for (int c = 0; c < 32; c++) orow[c] *= corr;
        }
        __syncthreads();

        /* O += P @ V  (plain fp16) */
        {
            AFragC oacc[4];
            #pragma unroll
            for (int ni = 0; ni < 4; ni++)
                wmma::load_matrix_sync(oacc[ni], Os + (wid*16)*FSTR + ni*16,
                                       FSTR, wmma::mem_row_major);
            #pragma unroll
            for (int ks = 0; ks < 4; ks++) {
                AFragA pf;
                wmma::load_matrix_sync(pf, Ph + (wid*16)*HSTR + ks*16, HSTR);
                #pragma unroll
                for (int ni = 0; ni < 4; ni++) {
                    AFragB vf;
                    wmma::load_matrix_sync(vf, Vh + (ks*16)*HSTR + ni*16, HSTR);
                    wmma::mma_sync(oacc[ni], pf, vf, oacc[ni]);
                }
            }
            #pragma unroll
            for (int ni = 0; ni < 4; ni++)
                wmma::store_matrix_sync(Os + (wid*16)*FSTR + ni*16, oacc[ni],
                                        FSTR, wmma::mem_row_major);
        }
        __syncthreads();
    }

    {
        float invl = 1.f/lrow[r2];
        const float* orow = Os + r2*FSTR + hf*32;
        __half* op = O + (size_t)(q0+r2)*ND + h*64 + hf*32;
        #pragma unroll
        for (int c = 0; c < 32; c++) op[c] = __float2half_rn(orow[c]*invl);
    }
}

/* ------------------------------------------------------------------ */
__global__ void silumul_kernel(const float* __restrict__ a, const float* __restrict__ b,
                               __half* __restrict__ o, int n) {
    int i = blockIdx.x*blockDim.x + threadIdx.x;
    if (i >= n) return;
    float g = a[i];
    o[i] = __float2half_rn((g / (1.f + expf(-g))) * b[i]);
}

__global__ void gate_out_kernel(const float* __restrict__ mem,
                                const float* __restrict__ inj,
                                const float* __restrict__ fg,
                                float* __restrict__ out, int n) {
    int i = blockIdx.x*blockDim.x + threadIdx.x;
    if (i >= n) return;
    float g = 1.f / (1.f + expf(-fg[i]));
    out[i] = mem[i]*g + inj[i]*(1.f - g);
}

/* ================================================================== */
extern "C" void kernel_launch(void* const* d_in, const int* in_sizes, int n_in,
                              void* d_out, int out_size) {
    const int*   ids    = (const int*)d_in[0];
    const float* memory = (const float*)d_in[1];
    const float* beacon = (const float*)d_in[2];
    const float* forget = (const float*)d_in[3];
    const float* embed  = (const float*)d_in[4];
    const float* ln1    = (const float*)d_in[5];
    const float* ln2    = (const float*)d_in[6];
    const float* Wq  = (const float*)d_in[7];
    const float* Wk  = (const float*)d_in[8];
    const float* Wv  = (const float*)d_in[9];
    const float* Wo  = (const float*)d_in[10];
    const float* mWk = (const float*)d_in[11];
    const float* mWv = (const float*)d_in[12];
    const float* bWq = (const float*)d_in[13];
    const float* bWk = (const float*)d_in[14];
    const float* bWv = (const float*)d_in[15];
    const float* fWq = (const float*)d_in[16];
    const float* fWk = (const float*)d_in[17];
    const float* fWv = (const float*)d_in[18];
    const float* Wg  = (const float*)d_in[19];
    const float* Wu  = (const float*)d_in[20];
    const float* Wd  = (const float*)d_in[21];

    static int attr_set = 0;
    static cudaStream_t s2;
    static cudaEvent_t eA, eB, eC;
    if (!attr_set) {
        cudaFuncSetAttribute(sgemm_kernel, cudaFuncAttributeMaxDynamicSharedMemorySize, GSMEM_BYTES);
        cudaFuncSetAttribute(sgemm_batch_kernel, cudaFuncAttributeMaxDynamicSharedMemorySize, GSMEM_BYTES);
        cudaFuncSetAttribute(attn_kernel, cudaFuncAttributeMaxDynamicSharedMemorySize, ATTN_SMEM);
        cudaStreamCreateWithFlags(&s2, cudaStreamNonBlocking);
        cudaEventCreateWithFlags(&eA, cudaEventDisableTiming);
        cudaEventCreateWithFlags(&eB, cudaEventDisableTiming);
        cudaEventCreateWithFlags(&eC, cudaEventDisableTiming);
        attr_set = 1;
    }

    float *cat,*q,*k,*v,*qbf,*kbf,*vbf,*m1,*m2,*inj,*fg;
    __half *xh,*atth,*m1h,*memh;
    __half *wq,*wk,*wv,*wo,*mwk,*mwv,*bwq,*bwk,*bwv,*fwq,*fwk,*fwv,*wg,*wu,*wd;
    cudaGetSymbolAddress((void**)&cat, g_cat);
    cudaGetSymbolAddress((void**)&xh,  g_xh);
    cudaGetSymbolAddress((void**)&q,   g_q);
    cudaGetSymbolAddress((void**)&k,   g_k);
    cudaGetSymbolAddress((void**)&v,   g_v);
    cudaGetSymbolAddress((void**)&qbf, g_qbf);
    cudaGetSymbolAddress((void**)&kbf, g_kbf);
    cudaGetSymbolAddress((void**)&vbf, g_vbf);
    cudaGetSymbolAddress((void**)&atth,g_atth);
    cudaGetSymbolAddress((void**)&m1,  g_m1);
    cudaGetSymbolAddress((void**)&m2,  g_m2);
    cudaGetSymbolAddress((void**)&m1h, g_m1h);
    cudaGetSymbolAddress((void**)&inj, g_inj);
    cudaGetSymbolAddress((void**)&fg,  g_fg);
    cudaGetSymbolAddress((void**)&memh,g_memh);
    cudaGetSymbolAddress((void**)&wq,  g_wq);
    cudaGetSymbolAddress((void**)&wk,  g_wk);
    cudaGetSymbolAddress((void**)&wv,  g_wv);
    cudaGetSymbolAddress((void**)&wo,  g_wo);
    cudaGetSymbolAddress((void**)&mwk, g_mwk);
    cudaGetSymbolAddress((void**)&mwv, g_mwv);
    cudaGetSymbolAddress((void**)&bwq, g_bwq);
    cudaGetSymbolAddress((void**)&bwk, g_bwk);
    cudaGetSymbolAddress((void**)&bwv, g_bwv);
    cudaGetSymbolAddress((void**)&fwq, g_fwq);
    cudaGetSymbolAddress((void**)&fwk, g_fwk);
    cudaGetSymbolAddress((void**)&fwv, g_fwv);
    cudaGetSymbolAddress((void**)&wg,  g_wg);
    cudaGetSymbolAddress((void**)&wu,  g_wu);
    cudaGetSymbolAddress((void**)&wd,  g_wd);

    const size_t RECB = (size_t)NM*ND*sizeof(float);
    const size_t wdd = (size_t)ND*ND;
    const int DD4 = ND*ND/4, DF4 = ND*NF/4, MEM4 = NM*ND/4;

    auto round_layer = [&](int l, cudaStream_t st) {
        RoundJobs js;
        js.j[0]  = { Wq  + l*wdd, wq  + l*wdd, DD4 };
        js.j[1]  = { Wk  + l*wdd, wk  + l*wdd, DD4 };
        js.j[2]  = { Wv  + l*wdd, wv  + l*wdd, DD4 };
        js.j[3]  = { Wo  + l*wdd, wo  + l*wdd, DD4 };
        js.j[4]  = { mWk + l*wdd, mwk + l*wdd, DD4 };
        js.j[5]  = { mWv + l*wdd, mwv + l*wdd, DD4 };
        js.j[6]  = { bWq + l*wdd, bwq + l*wdd, DD4 };
        js.j[7]  = { bWk + l*wdd, bwk + l*wdd, DD4 };
        js.j[8]  = { bWv + l*wdd, bwv + l*wdd, DD4 };
        js.j[9]  = { fWq + l*wdd, fwq + l*wdd, DD4 };
        js.j[10] = { fWk + l*wdd, fwk + l*wdd, DD4 };
        js.j[11] = { fWv + l*wdd, fwv + l*wdd, DD4 };
        js.j[12] = { Wg + (size_t)l*ND*NF, wg + (size_t)l*ND*NF, DF4 };
        js.j[13] = { Wu + (size_t)l*ND*NF, wu + (size_t)l*ND*NF, DF4 };
        js.j[14] = { Wd + (size_t)l*NF*ND, wd + (size_t)l*NF*ND, DF4 };
        js.j[15] = { memory + (size_t)l*NM*ND, memh + (size_t)l*NM*ND, MEM4 };
        round_w_kernel<<<dim3(256, 16), 256, 0, st>>>(js);
    };

    init_tables_kernel<<<(NPOS*32+255)/256, 256>>>();
    gather_kernel<<<NS, 256>>>(ids, embed, cat);
    round_layer(0, 0);
    cudaMemcpyAsync(cat + (size_t)NS*ND,      beacon, RECB, cudaMemcpyDeviceToDevice, 0);
    cudaMemcpyAsync(cat + (size_t)(NS+NM)*ND, forget, RECB, cudaMemcpyDeviceToDevice, 0);

    for (int l = 0; l < 7; l++) {
        const __half* Wq_l  = wq  + l*wdd;  const __half* Wk_l  = wk  + l*wdd;
        const __half* Wv_l  = wv  + l*wdd;  const __half* Wo_l  = wo  + l*wdd;
        const __half* mWk_l = mwk + l*wdd;  const __half* mWv_l = mwv + l*wdd;
        const __half* bWq_l = bwq + l*wdd;  const __half* bWk_l = bwk + l*wdd;
        const __half* bWv_l = bwv + l*wdd;  const __half* fWq_l = fwq + l*wdd;
        const __half* fWk_l = fwk + l*wdd;  const __half* fWv_l = fwv + l*wdd;
        const __half* Wg_l  = wg + (size_t)l*ND*NF;
        const __half* Wu_l  = wu + (size_t)l*ND*NF;
        const __half* Wd_l  = wd + (size_t)l*NF*ND;
        const __half* mem_l = memh + (size_t)l*NM*ND;
        const bool last = (l == 6);

        if (l > 0) cudaStreamWaitEvent(0, eC, 0);

        rmsnorm_kernel<<<NCAT, 256>>>(cat, ln1 + (size_t)l*ND, xh,
                                      inj + (size_t)l*NM*ND, fg + (size_t)l*NM*ND);

        {
            GemmBatch ba; int nb = 0, ny = 0;
            const __half* bx = xh + (size_t)NS*ND;
            const __half* fx = xh + (size_t)(NS+NM)*ND;
            int nrbs[12];
            if (!last) { ba.d[nb] = { xh, Wq_l, q }; nrbs[nb++] = 8; }
            ba.d[nb] = { xh, Wk_l, k + (size_t)NM*ND }; nrbs[nb++] = 8;
            ba.d[nb] = { xh, Wv_l, v + (size_t)NM*ND }; nrbs[nb++] = 8;
            ba.d[nb] = { mem_l, mWk_l, k };   nrbs[nb++] = 1;
            ba.d[nb] = { mem_l, mWv_l, v };   nrbs[nb++] = 1;
            ba.d[nb] = { bx, bWq_l, qbf };    nrbs[nb++] = 1;
            ba.d[nb] = { bx, bWk_l, kbf };    nrbs[nb++] = 1;
            ba.d[nb] = { bx, bWv_l, vbf };    nrbs[nb++] = 1;
            ba.d[nb] = { fx, fWq_l, qbf + (size_t)NM*ND }; nrbs[nb++] = 1;
            ba.d[nb] = { fx, fWk_l, kbf + (size_t)NM*ND }; nrbs[nb++] = 1;
            ba.d[nb] = { fx, fWv_l, vbf + (size_t)NM*ND }; nrbs[nb++] = 1;
            for (int di = 0; di < nb; di++)
                for (int rb = 0; rb < nrbs[di]; rb++) {
                    ba.yd[ny] = (unsigned char)di;
                    ba.yr[ny] = (unsigned char)rb; ny++;
                }
            sgemm_batch_kernel<<<dim3(8, ny, 1), 128, GSMEM_BYTES>>>(ba, ND, ND, 0);
        }

        /* fork: gates chain on s2, hidden chain on main */
        cudaEventRecord(eA, 0);
        cudaStreamWaitEvent(s2, eA, 0);

        if (!last)
            attn_kernel<<<dim3(NS/64, NH, 1), 128, ATTN_SMEM>>>(q, 0, k, v, NKV,
                                                    k, v, 0, 0, atth, 0, NM);
        attn_kernel<<<dim3(NM/64, NH, 2), 128, ATTN_SMEM, s2>>>(
                                                qbf, (size_t)NM*ND, k, v, NKV,
                                                kbf, vbf, (size_t)NM*ND, NM,
                                                atth + (size_t)NS*ND, (size_t)NM*ND, NKV);
        sgemm_kernel<<<dim3(8, 2), 128, GSMEM_BYTES, s2>>>(atth + (size_t)NS*ND, Wo_l,
                                              cat + (size_t)NS*ND, ND, ND, 1);
        cudaEventRecord(eB, s2);
        if (l + 1 < 7) { round_layer(l + 1, s2); cudaEventRecord(eC, s2); }

        if (!last)
            sgemm_kernel<<<dim3(8, 8), 128, GSMEM_BYTES>>>(atth, Wo_l, cat, ND, ND, 1);
        cudaStreamWaitEvent(0, eB, 0);

        int rows = last ? 2*NM : NCAT;
        size_t off = last ? (size_t)NS*ND : 0;
        rmsnorm_kernel<<<rows, 256>>>(cat + off, ln2 + (size_t)l*ND, xh + off,
                                      (float*)0, (float*)0);
        {
            GemmBatch ga; int ny = 0;
            ga.d[0] = { xh + off, Wg_l, m1 };
            ga.d[1] = { xh + off, Wu_l, m2 };
            for (int di = 0; di < 2; di++)
                for (int rb = 0; rb < rows/128; rb++) {
                    ga.yd[ny] = (unsigned char)di;
                    ga.yr[ny] = (unsigned char)rb; ny++;
                }
            sgemm_batch_kernel<<<dim3(NF/128, ny, 1), 128, GSMEM_BYTES>>>(ga, NF, ND, 0);
        }
        silumul_kernel<<<(rows*NF)/256, 256>>>(m1, m2, m1h, rows*NF);
        sgemm_kernel<<<dim3(8, rows/128), 128, GSMEM_BYTES>>>(m1h, Wd_l, cat + off, ND, NF, 1);
    }

    cudaMemcpyAsync(inj + (size_t)7*NM*ND, cat + (size_t)NS*ND,      RECB, cudaMemcpyDeviceToDevice, 0);
    cudaMemcpyAsync(fg  + (size_t)7*NM*ND, cat + (size_t)(NS+NM)*ND, RECB, cudaMemcpyDeviceToDevice, 0);

    gate_out_kernel<<<(NL*NM*ND)/256, 256>>>(memory, inj, fg, (float*)d_out, NL*NM*ND);
}